// round 8
// baseline (speedup 1.0000x reference)
#include <cuda_runtime.h>
#include <cuda_bf16.h>
#include <math.h>
#include <stdint.h>

// ---------------- problem constants ----------------
#define CB   2
#define CS   2048
#define CHID 2048
#define CNH  16
#define CHD  128
#define CQLR 1536
#define CKVLR 512
#define CBS  (CB*CS)          // 4096
#define CCAT (CKVLR+CHD)      // 640
#define CQHD (2*CHD)          // 256

typedef __nv_bfloat16 bf16;

// ---------------- device scratch ----------------
static __device__ __align__(256) float g_qa[(size_t)CBS*CQLR];
static __device__ __align__(256) float g_ckv[(size_t)CBS*CCAT];

static __device__ __align__(256) bf16 g_hid_h[(size_t)CBS*CHID],  g_hid_l[(size_t)CBS*CHID];
static __device__ __align__(256) bf16 g_qaw_h[(size_t)CQLR*CHID], g_qaw_l[(size_t)CQLR*CHID];
static __device__ __align__(256) bf16 g_qbw_h[(size_t)CNH*CQHD*CQLR], g_qbw_l[(size_t)CNH*CQHD*CQLR];
static __device__ __align__(256) bf16 g_kvaw_h[(size_t)CCAT*CHID], g_kvaw_l[(size_t)CCAT*CHID];
static __device__ __align__(256) bf16 g_ow_h[(size_t)CHID*CNH*CHD], g_ow_l[(size_t)CHID*CNH*CHD];
static __device__ __align__(256) bf16 g_qan_h[(size_t)CBS*CQLR], g_qan_l[(size_t)CBS*CQLR];
static __device__ __align__(256) bf16 g_qs_h[(size_t)CBS*CNH*CQHD], g_qs_l[(size_t)CBS*CNH*CQHD];
static __device__ __align__(256) bf16 g_qab_h[(size_t)CNH*CKVLR*CHD], g_qab_l[(size_t)CNH*CKVLR*CHD];     // [h][c][d]
static __device__ __align__(256) bf16 g_oabt_h[(size_t)CNH*CHD*CKVLR], g_oabt_l[(size_t)CNH*CHD*CKVLR];   // [h][d][c]
static __device__ __align__(256) bf16 g_qc_h[(size_t)CB*CNH*CS*CCAT], g_qc_l[(size_t)CB*CNH*CS*CCAT];
static __device__ __align__(256) bf16 g_ckv_h[(size_t)CBS*CCAT], g_ckv_l[(size_t)CBS*CCAT];
static __device__ __align__(256) bf16 g_ol_h[(size_t)CB*CNH*CS*CKVLR], g_ol_l[(size_t)CB*CNH*CS*CKVLR];
static __device__ __align__(256) bf16 g_oh_h[(size_t)CBS*CNH*CHD], g_oh_l[(size_t)CBS*CNH*CHD];

// ---------------- asm helpers (sm_80-portable) ----------------
__device__ __forceinline__ uint32_t smem_u32(const void* p) {
    uint32_t a;
    asm("{ .reg .u64 t; cvta.to.shared.u64 t, %1; cvt.u32.u64 %0, t; }" : "=r"(a) : "l"(p));
    return a;
}
#define CP_ASYNC16(dst, src) \
    asm volatile("cp.async.cg.shared.global [%0], [%1], 16;" :: "r"(dst), "l"(src) : "memory")
#define CP_COMMIT() asm volatile("cp.async.commit_group;" ::: "memory")
#define CP_WAIT(n)  asm volatile("cp.async.wait_group %0;" :: "n"(n) : "memory")

#define LDSM4(r, addr) \
    asm volatile("ldmatrix.sync.aligned.m8n8.x4.shared.b16 {%0,%1,%2,%3}, [%4];" \
        : "=r"((r)[0]),"=r"((r)[1]),"=r"((r)[2]),"=r"((r)[3]) : "r"(addr))
#define LDSM4T(r, addr) \
    asm volatile("ldmatrix.sync.aligned.m8n8.x4.trans.shared.b16 {%0,%1,%2,%3}, [%4];" \
        : "=r"((r)[0]),"=r"((r)[1]),"=r"((r)[2]),"=r"((r)[3]) : "r"(addr))

#define MMA16816(d, a, b0, b1) \
    asm volatile("mma.sync.aligned.m16n8k16.row.col.f32.bf16.bf16.f32 " \
        "{%0,%1,%2,%3},{%4,%5,%6,%7},{%8,%9},{%0,%1,%2,%3};" \
        : "+f"((d)[0]),"+f"((d)[1]),"+f"((d)[2]),"+f"((d)[3]) \
        : "r"((a)[0]),"r"((a)[1]),"r"((a)[2]),"r"((a)[3]), "r"(b0),"r"(b1))

__device__ __forceinline__ void split2(float v, bf16* hp, bf16* lp) {
    bf16 h = __float2bfloat16(v);
    *hp = h;
    *lp = __float2bfloat16(v - __bfloat162float(h));
}
__device__ __forceinline__ void split2x2(float v0, float v1, bf16* hp, bf16* lp) {
    bf16 h0 = __float2bfloat16(v0), h1 = __float2bfloat16(v1);
    bf16 l0 = __float2bfloat16(v0 - __bfloat162float(h0));
    bf16 l1 = __float2bfloat16(v1 - __bfloat162float(h1));
    __nv_bfloat162 hh; hh.x = h0; hh.y = h1;
    __nv_bfloat162 ll; ll.x = l0; ll.y = l1;
    *reinterpret_cast<__nv_bfloat162*>(hp) = hh;
    *reinterpret_cast<__nv_bfloat162*>(lp) = ll;
}

// ---------------- bf16 hi/lo split MMA GEMM (512 threads, 16 warps) ----------------
static constexpr int GBK = 32, STAGES = 4;
static constexpr int ASZ = 128 * GBK * 2;   // 8192 B

__device__ __forceinline__ uint32_t swz(int row, int ch) {
    return (uint32_t)(row * 64 + ((ch ^ ((row >> 1) & 3)) * 16));
}

template<int BN>
__global__ __launch_bounds__(512, 1) void mma_gemm(
    const bf16* __restrict__ Ah, const bf16* __restrict__ Al, int lda, long long aO, long long aI,
    const bf16* __restrict__ Bh, const bf16* __restrict__ Bl, int ldb, long long bO, long long bI,
    float* __restrict__ C, bf16* __restrict__ Chi, bf16* __restrict__ Clo,
    int ldc, long long cO, long long cI,
    const float* __restrict__ bias, float alpha, int K, int zInner)
{
    constexpr int JG = BN / 64;               // B ldsm-groups per warp (warp n-tile = BN/4)
    constexpr int BSZ = BN * GBK * 2;
    constexpr int STAGE_B = 2 * ASZ + 2 * BSZ;

    extern __shared__ char smem_raw[];
    uint32_t sbase = smem_u32(smem_raw);

    int tid = threadIdx.x, wid = tid >> 5, lane = tid & 31;
    int z = blockIdx.z, zo = z / zInner, zi = z - zo * zInner;
    Ah += zo * aO + zi * aI;  Al += zo * aO + zi * aI;
    Bh += zo * bO + zi * bI;  Bl += zo * bO + zi * bI;
    if (C)   C   += zo * cO + zi * cI;
    if (Chi) { Chi += zo * cO + zi * cI; Clo += zo * cO + zi * cI; }

    int bm = blockIdx.y * 128, bn = blockIdx.x * BN;
    int wm = (wid & 3) * 32;
    int wn = (wid >> 2) * (BN / 4);

    const bf16* pAh = Ah + (long long)bm * lda;
    const bf16* pAl = Al + (long long)bm * lda;
    const bf16* pBh = Bh + (long long)bn * ldb;
    const bf16* pBl = Bl + (long long)bn * ldb;

    float acc[2][2 * JG][4];
#pragma unroll
    for (int t = 0; t < 2; t++)
#pragma unroll
        for (int j = 0; j < 2 * JG; j++)
#pragma unroll
            for (int q = 0; q < 4; q++) acc[t][j][q] = 0.f;

    int nk = K / GBK;

#define ISSUE(stage_) do { \
    int st_ = (stage_) % STAGES; \
    uint32_t sb_ = sbase + st_ * STAGE_B; \
    long long k0_ = (long long)(stage_) * GBK; \
    { int r = tid >> 2, ch = tid & 3; \
      uint32_t so = swz(r, ch); \
      CP_ASYNC16(sb_ + so,       pAh + (long long)r * lda + k0_ + ch * 8); \
      CP_ASYNC16(sb_ + ASZ + so, pAl + (long long)r * lda + k0_ + ch * 8); } \
    _Pragma("unroll") \
    for (int u = 0; u < BN / 128; u++) { \
        int idx = u * 512 + tid; int r = idx >> 2, ch = idx & 3; \
        uint32_t so = swz(r, ch); \
        CP_ASYNC16(sb_ + 2 * ASZ + so,       pBh + (long long)r * ldb + k0_ + ch * 8); \
        CP_ASYNC16(sb_ + 2 * ASZ + BSZ + so, pBl + (long long)r * ldb + k0_ + ch * 8); \
    } \
} while (0)

    for (int s = 0; s < STAGES - 1; s++) {
        if (s < nk) ISSUE(s);
        CP_COMMIT();
    }

    int a_row = (lane & 15);
    int a_sel = lane >> 4;
    int b_row = (lane & 7) + ((lane >> 4) * 8);
    int b_sel = (lane >> 3) & 1;

    for (int i = 0; i < nk; i++) {
        CP_WAIT(STAGES - 2);
        __syncthreads();
        if (i + STAGES - 1 < nk) ISSUE(i + STAGES - 1);
        CP_COMMIT();

        uint32_t sb = sbase + (i % STAGES) * STAGE_B;

#pragma unroll
        for (int kh = 0; kh < 2; kh++) {
            uint32_t Afh[2][4], Afl[2][4];
#pragma unroll
            for (int t = 0; t < 2; t++) {
                int row = wm + t * 16 + a_row;
                uint32_t off = swz(row, 2 * kh + a_sel);
                LDSM4(Afh[t], sb + off);
                LDSM4(Afl[t], sb + ASZ + off);
            }
#pragma unroll
            for (int jg = 0; jg < JG; jg++) {
                int row = wn + jg * 16 + b_row;
                uint32_t off = swz(row, 2 * kh + b_sel);
                uint32_t Bh4[4], Bl4[4];
                LDSM4(Bh4, sb + 2 * ASZ + off);
                LDSM4(Bl4, sb + 2 * ASZ + BSZ + off);
#pragma unroll
                for (int t = 0; t < 2; t++) {
                    MMA16816(acc[t][2*jg],   Afh[t], Bh4[0], Bh4[1]);
                    MMA16816(acc[t][2*jg],   Afh[t], Bl4[0], Bl4[1]);
                    MMA16816(acc[t][2*jg],   Afl[t], Bh4[0], Bh4[1]);
                    MMA16816(acc[t][2*jg+1], Afh[t], Bh4[2], Bh4[3]);
                    MMA16816(acc[t][2*jg+1], Afh[t], Bl4[2], Bl4[3]);
                    MMA16816(acc[t][2*jg+1], Afl[t], Bh4[2], Bh4[3]);
                }
            }
        }
    }
#undef ISSUE

#pragma unroll
    for (int t = 0; t < 2; t++) {
        int r0 = bm + wm + t * 16 + (lane >> 2);
#pragma unroll
        for (int j = 0; j < 2 * JG; j++) {
            int col = bn + wn + j * 8 + (lane & 3) * 2;
            float v0 = acc[t][j][0] * alpha;
            float v1 = acc[t][j][1] * alpha;
            float v2 = acc[t][j][2] * alpha;
            float v3 = acc[t][j][3] * alpha;
            if (bias) { v0 += bias[col]; v1 += bias[col + 1]; v2 += bias[col]; v3 += bias[col + 1]; }
            if (Chi) {
                long long o0 = (long long)r0 * ldc + col;
                long long o1 = (long long)(r0 + 8) * ldc + col;
                split2x2(v0, v1, Chi + o0, Clo + o0);
                split2x2(v2, v3, Chi + o1, Clo + o1);
            } else {
                C[(long long)r0 * ldc + col]           = v0;
                C[(long long)r0 * ldc + col + 1]       = v1;
                C[(long long)(r0 + 8) * ldc + col]     = v2;
                C[(long long)(r0 + 8) * ldc + col + 1] = v3;
            }
        }
    }
}

// ---------------- fused flash attention (512 threads, 16 warps) ----------------
// CTA: 64 q rows, one (b,h). K' tile (64 keys x 640, hi/lo) resident in smem;
// V = K'[:, :512] read in-place via ldmatrix.trans. Max-free softmax.
// smem: K chunks 10 x 16KB = 160KB @0; Q ring 4 x 16KB @163840 (P overlays stage 0).
static constexpr int FQOFF = 163840;
static constexpr int FSMEM = 163840 + 4 * 16384;   // 224 KB

__device__ __forceinline__ uint32_t psw(int row, int ch) {
    return (uint32_t)(row * 128 + ((ch ^ (row & 7)) << 4));
}

__device__ __forceinline__ void fissue(uint32_t sbase, int kc,
    const bf16* pQh, const bf16* pQl, const bf16* pKhj, const bf16* pKlj,
    uint32_t soff, long long goff)
{
    uint32_t kb = sbase + kc * 16384;
    uint32_t qb = sbase + FQOFF + (kc & 3) * 16384;
    long long co = (long long)kc * 64;
    CP_ASYNC16(kb + soff,        pKhj + goff + co);
    CP_ASYNC16(kb + 8192 + soff, pKlj + goff + co);
    CP_ASYNC16(qb + soff,        pQh + goff + co);
    CP_ASYNC16(qb + 8192 + soff, pQl + goff + co);
}

__global__ __launch_bounds__(512, 1) void flash_kernel(
    const bf16* __restrict__ Qh, const bf16* __restrict__ Ql,
    const bf16* __restrict__ Kh, const bf16* __restrict__ Kl,
    const float* __restrict__ mask,
    bf16* __restrict__ Oh, bf16* __restrict__ Ol,
    float scale)
{
    extern __shared__ char smem[];
    uint32_t sbase = smem_u32(smem);
    int tid = threadIdx.x, wid = tid >> 5, lane = tid & 31;
    int mg = wid & 3, cg = wid >> 2;          // cg in [0,4)
    int bh = blockIdx.y, b = bh >> 4;
    int q0 = blockIdx.x * 64;

    const bf16* pQh = Qh + (long long)bh * CS * CCAT + (long long)q0 * CCAT;
    const bf16* pQl = Ql + (long long)bh * CS * CCAT + (long long)q0 * CCAT;
    const bf16* pKh = Kh + (long long)b * CS * CCAT;
    const bf16* pKl = Kl + (long long)b * CS * CCAT;

    // cp.async: 64 rows x 8 chunks, one granule per thread per buffer
    int lrow = tid >> 3, lch = tid & 7;
    uint32_t soff = psw(lrow, lch);
    long long goff = (long long)lrow * CCAT + lch * 8;

    int arow = mg * 16 + (lane & 15);
    int asel = lane >> 4;
    int brow = cg * 16 + (lane & 7) + ((lane >> 4) * 8);
    int bsel = (lane >> 3) & 1;
    int trow_b = (lane & 7) + (((lane >> 3) & 1) * 8);
    int tsel = lane >> 4;

    float oacc[16][4];
#pragma unroll
    for (int i = 0; i < 16; i++)
#pragma unroll
        for (int q = 0; q < 4; q++) oacc[i][q] = 0.f;
    float lsum0 = 0.f, lsum1 = 0.f;

    int prow0 = mg * 16 + (lane >> 2), prow1 = prow0 + 8;

    for (int j = 0; j < 32; j++) {
        const bf16* pKhj = pKh + (long long)j * 64 * CCAT;
        const bf16* pKlj = pKl + (long long)j * 64 * CCAT;

        fissue(sbase, 0, pQh, pQl, pKhj, pKlj, soff, goff); CP_COMMIT();
        fissue(sbase, 1, pQh, pQl, pKhj, pKlj, soff, goff); CP_COMMIT();
        fissue(sbase, 2, pQh, pQl, pKhj, pKlj, soff, goff); CP_COMMIT();

        float sacc[2][4];
#pragma unroll
        for (int n = 0; n < 2; n++)
#pragma unroll
            for (int q = 0; q < 4; q++) sacc[n][q] = 0.f;

        for (int kc = 0; kc < 10; kc++) {
            CP_WAIT(2);
            __syncthreads();
            if (kc + 3 < 10) fissue(sbase, kc + 3, pQh, pQl, pKhj, pKlj, soff, goff);
            CP_COMMIT();
            uint32_t kb = sbase + kc * 16384;
            uint32_t qb = sbase + FQOFF + (kc & 3) * 16384;
#pragma unroll
            for (int kk = 0; kk < 4; kk++) {
                uint32_t ao = psw(arow, kk * 2 + asel);
                uint32_t Ah4[4], Al4[4];
                LDSM4(Ah4, qb + ao);
                LDSM4(Al4, qb + 8192 + ao);
                uint32_t bo = psw(brow, kk * 2 + bsel);
                uint32_t Bh4[4], Bl4[4];
                LDSM4(Bh4, kb + bo);
                LDSM4(Bl4, kb + 8192 + bo);
                MMA16816(sacc[0], Ah4, Bh4[0], Bh4[1]);
                MMA16816(sacc[0], Ah4, Bl4[0], Bl4[1]);
                MMA16816(sacc[0], Al4, Bh4[0], Bh4[1]);
                MMA16816(sacc[1], Ah4, Bh4[2], Bh4[3]);
                MMA16816(sacc[1], Ah4, Bl4[2], Bl4[3]);
                MMA16816(sacc[1], Al4, Bh4[2], Bh4[3]);
            }
        }
        // no sync needed: P overlays Q slot 0; its last reader (kc=8) is fenced
        // by kc=9's top-of-loop __syncthreads, which every warp has passed.

        // softmax (max-free) + P split write (warp owns 16 keys: cols cg*16..+16)
        {
            const float* mrow = mask + (long long)b * CS * CS
                              + (long long)(q0 + prow0) * CS + j * 64 + cg * 16 + (lane & 3) * 2;
            float ladd0 = 0.f, ladd1 = 0.f;
#pragma unroll
            for (int nn = 0; nn < 2; nn++) {
                float2 m0 = *reinterpret_cast<const float2*>(mrow + nn * 8);
                float2 m1 = *reinterpret_cast<const float2*>(mrow + nn * 8 + 8 * CS);
                float p0 = __expf(sacc[nn][0] * scale + m0.x);
                float p1 = __expf(sacc[nn][1] * scale + m0.y);
                float p2 = __expf(sacc[nn][2] * scale + m1.x);
                float p3 = __expf(sacc[nn][3] * scale + m1.y);
                ladd0 += p0 + p1; ladd1 += p2 + p3;
                int col = cg * 16 + nn * 8 + (lane & 3) * 2;
                uint32_t o0 = (uint32_t)(prow0 * 128 + ((((col >> 3)) ^ (prow0 & 7)) << 4) + (col & 7) * 2);
                uint32_t o1 = (uint32_t)(prow1 * 128 + ((((col >> 3)) ^ (prow1 & 7)) << 4) + (col & 7) * 2);
                split2x2(p0, p1, (bf16*)(smem + FQOFF + o0), (bf16*)(smem + FQOFF + 8192 + o0));
                split2x2(p2, p3, (bf16*)(smem + FQOFF + o1), (bf16*)(smem + FQOFF + 8192 + o1));
            }
            ladd0 += __shfl_xor_sync(~0u, ladd0, 1); ladd0 += __shfl_xor_sync(~0u, ladd0, 2);
            ladd1 += __shfl_xor_sync(~0u, ladd1, 1); ladd1 += __shfl_xor_sync(~0u, ladd1, 2);
            lsum0 += ladd0; lsum1 += ladd1;
        }
        __syncthreads();   // P visible to all warps

        // AV: O += P*V; warp covers 16 rows x 128 cols (cg quarter of 512)
#pragma unroll
        for (int kt = 0; kt < 4; kt++) {
            uint32_t ao = psw(arow, kt * 2 + asel);
            uint32_t Ph4[4], Pl4[4];
            LDSM4(Ph4, sbase + FQOFF + ao);
            LDSM4(Pl4, sbase + FQOFF + 8192 + ao);
            int trow = kt * 16 + trow_b;
#pragma unroll
            for (int ng = 0; ng < 8; ng++) {
                int c0 = cg * 128 + ng * 16;
                uint32_t kcb = sbase + (c0 >> 6) * 16384;
                uint32_t bo = psw(trow, ((c0 & 63) >> 3) + tsel);
                uint32_t Vh4[4], Vl4[4];
                LDSM4T(Vh4, kcb + bo);
                LDSM4T(Vl4, kcb + 8192 + bo);
                MMA16816(oacc[ng*2],   Ph4, Vh4[0], Vh4[1]);
                MMA16816(oacc[ng*2],   Ph4, Vl4[0], Vl4[1]);
                MMA16816(oacc[ng*2],   Pl4, Vh4[0], Vh4[1]);
                MMA16816(oacc[ng*2+1], Ph4, Vh4[2], Vh4[3]);
                MMA16816(oacc[ng*2+1], Ph4, Vl4[2], Vl4[3]);
                MMA16816(oacc[ng*2+1], Pl4, Vh4[2], Vh4[3]);
            }
        }
        __syncthreads();   // AV reads done before next j overwrites K/Q/P
    }

    // finalize: combine row sums across 4 cg groups, normalize, split-write O
    float* Larr = reinterpret_cast<float*>(smem);
    if ((lane & 3) == 0) {
        Larr[cg * 64 + prow0] = lsum0;
        Larr[cg * 64 + prow1] = lsum1;
    }
    __syncthreads();
    float inv0 = 1.f / (Larr[prow0] + Larr[64 + prow0] + Larr[128 + prow0] + Larr[192 + prow0]);
    float inv1 = 1.f / (Larr[prow1] + Larr[64 + prow1] + Larr[128 + prow1] + Larr[192 + prow1]);

    bf16* poh = Oh + (long long)bh * CS * CKVLR + (long long)q0 * CKVLR;
    bf16* pol = Ol + (long long)bh * CS * CKVLR + (long long)q0 * CKVLR;
#pragma unroll
    for (int ng = 0; ng < 8; ng++) {
#pragma unroll
        for (int h8 = 0; h8 < 2; h8++) {
            int c = cg * 128 + ng * 16 + h8 * 8 + (lane & 3) * 2;
            float* a = oacc[ng * 2 + h8];
            long long o0 = (long long)prow0 * CKVLR + c;
            long long o1 = (long long)prow1 * CKVLR + c;
            split2x2(a[0] * inv0, a[1] * inv0, poh + o0, pol + o0);
            split2x2(a[2] * inv1, a[3] * inv1, poh + o1, pol + o1);
        }
    }
}

// ---------------- conversions (vectorized) ----------------
__global__ void cvt_split_kernel(const float* __restrict__ s, bf16* __restrict__ hi, bf16* __restrict__ lo, long long n)
{
    long long n4 = n >> 2;
    long long i = (long long)blockIdx.x * blockDim.x + threadIdx.x;
    long long st = (long long)gridDim.x * blockDim.x;
    for (; i < n4; i += st) {
        float4 v = reinterpret_cast<const float4*>(s)[i];
        bf16 h[4], l[4];
        h[0] = __float2bfloat16(v.x); l[0] = __float2bfloat16(v.x - __bfloat162float(h[0]));
        h[1] = __float2bfloat16(v.y); l[1] = __float2bfloat16(v.y - __bfloat162float(h[1]));
        h[2] = __float2bfloat16(v.z); l[2] = __float2bfloat16(v.z - __bfloat162float(h[2]));
        h[3] = __float2bfloat16(v.w); l[3] = __float2bfloat16(v.w - __bfloat162float(h[3]));
        *reinterpret_cast<uint2*>(hi + i * 4) = *reinterpret_cast<uint2*>(h);
        *reinterpret_cast<uint2*>(lo + i * 4) = *reinterpret_cast<uint2*>(l);
    }
}

__global__ void extract_kernel(const float* __restrict__ kvb,
                               bf16* __restrict__ qh, bf16* __restrict__ ql,
                               bf16* __restrict__ oh, bf16* __restrict__ ol)
{
    long long n = (long long)CNH * CKVLR * CHD;
    long long i = (long long)blockIdx.x * blockDim.x + threadIdx.x;
    long long st = (long long)gridDim.x * blockDim.x;
    for (; i < n; i += st) {
        {
            int c = (int)(i & 511);
            int d = (int)((i >> 9) & 127);
            int h = (int)(i >> 16);
            float v = kvb[(((long long)c * CNH + h) * 2 + 1) * CHD + d];
            split2(v, oh + i, ol + i);
        }
        {
            int d = (int)(i & 127);
            int c = (int)((i >> 7) & 511);
            int h = (int)(i >> 16);
            float v = kvb[(((long long)c * CNH + h) * 2) * CHD + d];
            split2(v, qh + i, ql + i);
        }
    }
}

// ---------------- RMSNorm ----------------
__global__ __launch_bounds__(256) void rms_kernel(const float* __restrict__ x, const float* __restrict__ w,
                                                  bf16* __restrict__ hi, bf16* __restrict__ lo)
{
    __shared__ float red[8];
    size_t row = blockIdx.x;
    const float* p = x + row * CQLR;
    int tid = threadIdx.x;
    float s = 0.f;
    for (int i = tid; i < CQLR; i += 256) { float v = p[i]; s += v * v; }
#pragma unroll
    for (int o = 16; o; o >>= 1) s += __shfl_xor_sync(~0u, s, o);
    if ((tid & 31) == 0) red[tid >> 5] = s;
    __syncthreads();
    float tot = 0.f;
#pragma unroll
    for (int i = 0; i < 8; i++) tot += red[i];
    float r = rsqrtf(tot + 1e-6f);
    bf16* ph = hi + row * CQLR;
    bf16* pl = lo + row * CQLR;
    for (int i = tid; i < CQLR; i += 256) split2(p[i] * r * w[i], ph + i, pl + i);
}

// ---------------- RoPE ----------------
__device__ __forceinline__ void rope_cs(int s, int i, float& c, float& sn)
{
    double invf = pow(10000.0, -(double)(2 * i) / 128.0);
    double ang = (double)s * invf;
    c = (float)cos(ang);
    sn = (float)sin(ang);
}

__global__ void rope_k_kernel(float* __restrict__ ckv)
{
    int idx = blockIdx.x * blockDim.x + threadIdx.x;
    if (idx >= CB * CS * 64) return;
    int i = idx & 63;
    int row = idx >> 6;
    int s = row & (CS - 1);
    float c, sn; rope_cs(s, i, c, sn);
    float* p = ckv + (size_t)row * CCAT + CKVLR;
    float x1 = p[i], x2 = p[i + 64];
    p[i]      = x1 * c - x2 * sn;
    p[i + 64] = x2 * c + x1 * sn;
}

__global__ void rope_q_kernel(const bf16* __restrict__ qh, const bf16* __restrict__ ql,
                              bf16* __restrict__ qch, bf16* __restrict__ qcl)
{
    int idx = blockIdx.x * blockDim.x + threadIdx.x;
    if (idx >= CB * CS * CNH * 64) return;
    int i = idx & 63;
    int h = (idx >> 6) & 15;
    int row = idx >> 10;
    int s = row & (CS - 1);
    int b = row >> 11;
    float c, sn; rope_cs(s, i, c, sn);
    long long so = (long long)row * (CNH * CQHD) + h * CQHD + CHD;
    float x1 = __bfloat162float(qh[so + i])      + __bfloat162float(ql[so + i]);
    float x2 = __bfloat162float(qh[so + i + 64]) + __bfloat162float(ql[so + i + 64]);
    long long dofs = ((long long)(b * CNH + h) * CS + s) * CCAT + CKVLR;
    split2(x1 * c - x2 * sn, qch + dofs + i,      qcl + dofs + i);
    split2(x2 * c + x1 * sn, qch + dofs + i + 64, qcl + dofs + i + 64);
}

// ---------------- launch ----------------
extern "C" void kernel_launch(void* const* d_in, const int* in_sizes, int n_in,
                              void* d_out, int out_size)
{
    const float* hidden = (const float*)d_in[0];
    const float* mask   = (const float*)d_in[1];
    const float* q_a_W  = (const float*)d_in[2];
    const float* q_a_b  = (const float*)d_in[3];
    const float* q_a_nw = (const float*)d_in[4];
    const float* q_b_W  = (const float*)d_in[5];
    const float* kv_a_W = (const float*)d_in[6];
    const float* kv_b_W = (const float*)d_in[7];
    const float* o_W    = (const float*)d_in[8];
    float* out = (float*)d_out;

    void* p;
#define SYM(v, g) cudaGetSymbolAddress(&p, g); auto* v = (decltype(&g[0]))p
    SYM(qa, g_qa);     SYM(ckv, g_ckv);
    SYM(hidh, g_hid_h); SYM(hidl, g_hid_l);
    SYM(qawh, g_qaw_h); SYM(qawl, g_qaw_l);
    SYM(qbwh, g_qbw_h); SYM(qbwl, g_qbw_l);
    SYM(kvawh, g_kvaw_h); SYM(kvawl, g_kvaw_l);
    SYM(owh, g_ow_h);   SYM(owl, g_ow_l);
    SYM(qanh, g_qan_h); SYM(qanl, g_qan_l);
    SYM(qsh, g_qs_h);   SYM(qsl, g_qs_l);
    SYM(qabh, g_qab_h); SYM(qabl, g_qab_l);
    SYM(oabth, g_oabt_h); SYM(oabtl, g_oabt_l);
    SYM(qch, g_qc_h);   SYM(qcl, g_qc_l);
    SYM(ckvh, g_ckv_h); SYM(ckvl, g_ckv_l);
    SYM(olh, g_ol_h);   SYM(oll, g_ol_l);
    SYM(ohh, g_oh_h);   SYM(ohl, g_oh_l);
#undef SYM

    constexpr int SMEM128 = STAGES * (2 * ASZ + 2 * 128 * GBK * 2);  // 128 KB
    constexpr int SMEM256 = STAGES * (2 * ASZ + 2 * 256 * GBK * 2);  // 192 KB
    cudaFuncSetAttribute(mma_gemm<128>, cudaFuncAttributeMaxDynamicSharedMemorySize, SMEM128);
    cudaFuncSetAttribute(mma_gemm<256>, cudaFuncAttributeMaxDynamicSharedMemorySize, SMEM256);
    cudaFuncSetAttribute(flash_kernel, cudaFuncAttributeMaxDynamicSharedMemorySize, FSMEM);

    const long long LS = CS;
    const int CVG = 2048;

    cvt_split_kernel<<<CVG, 256>>>(hidden, hidh, hidl, (long long)CBS * CHID);
    cvt_split_kernel<<<CVG, 256>>>(q_a_W, qawh, qawl, (long long)CQLR * CHID);
    cvt_split_kernel<<<CVG, 256>>>(kv_a_W, kvawh, kvawl, (long long)CCAT * CHID);

    // q_a = hidden @ q_a_W^T + bias   [4096,1536] K=2048, fp32 out
    mma_gemm<256><<<dim3(CQLR / 256, CBS / 128, 1), 512, SMEM256>>>(
        hidh, hidl, CHID, 0, 0, qawh, qawl, CHID, 0, 0,
        qa, nullptr, nullptr, CQLR, 0, 0, q_a_b, 1.f, CHID, 1);

    // ckv = hidden @ kv_a_W^T  [4096,640] K=2048, fp32 out
    mma_gemm<128><<<dim3(CCAT / 128, CBS / 128, 1), 512, SMEM128>>>(
        hidh, hidl, CHID, 0, 0, kvawh, kvawl, CHID, 0, 0,
        ckv, nullptr, nullptr, CCAT, 0, 0, nullptr, 1.f, CHID, 1);

    rms_kernel<<<CBS, 256>>>(qa, q_a_nw, qanh, qanl);
    cvt_split_kernel<<<CVG, 256>>>(q_b_W, qbwh, qbwl, (long long)CNH * CQHD * CQLR);

    // q = qa_norm @ q_b_W^T  [4096,4096] K=1536, split out
    mma_gemm<256><<<dim3((CNH * CQHD) / 256, CBS / 128, 1), 512, SMEM256>>>(
        qanh, qanl, CQLR, 0, 0, qbwh, qbwl, CQLR, 0, 0,
        nullptr, qsh, qsl, CNH * CQHD, 0, 0, nullptr, 1.f, CQLR, 1);

    extract_kernel<<<CVG, 256>>>(kv_b_W, qabh, qabl, oabth, oabtl);
    rope_k_kernel<<<(CB * CS * 64) / 256, 256>>>(ckv);
    rope_q_kernel<<<(CB * CS * CNH * 64) / 256, 256>>>(qsh, qsl, qch, qcl);

    // q_lat -> qcat cols [0,512)  K=128, Z=32, split out
    mma_gemm<256><<<dim3(CKVLR / 256, CS / 128, CB * CNH), 512, SMEM256>>>(
        qsh, qsl, CNH * CQHD, LS * CNH * CQHD, CQHD,
        qabh, qabl, CHD, 0, (long long)CKVLR * CHD,
        nullptr, qch, qcl, CCAT, LS * CNH * CCAT, LS * CCAT,
        nullptr, 1.f, CHD, CNH);

    // split ckv (K-major)
    cvt_split_kernel<<<CVG, 256>>>(ckv, ckvh, ckvl, (long long)CBS * CCAT);

    // fused attention: scores + softmax + AV -> olat split
    float scale = 1.f / sqrtf((float)CCAT);
    flash_kernel<<<dim3(CS / 64, CB * CNH), 512, FSMEM>>>(
        qch, qcl, ckvh, ckvl, mask, olh, oll, scale);

    cvt_split_kernel<<<CVG, 256>>>(o_W, owh, owl, (long long)CHID * CNH * CHD);

    // out_head = olat . o_absorb^T -> [b,s,h*128+d]  K=512, N=128, Z=32, split out
    mma_gemm<128><<<dim3(1, CS / 128, CB * CNH), 512, SMEM128>>>(
        olh, oll, CKVLR, LS * CNH * CKVLR, LS * CKVLR,
        oabth, oabtl, CKVLR, 0, (long long)CHD * CKVLR,
        nullptr, ohh, ohl, CNH * CHD, LS * (long long)CNH * CHD, CHD,
        nullptr, 1.f, CKVLR, CNH);

    // final = ohead @ o_W^T  [4096,2048] K=2048, fp32 out
    mma_gemm<256><<<dim3(CHID / 256, CBS / 128, 1), 512, SMEM256>>>(
        ohh, ohl, CNH * CHD, 0, 0, owh, owl, CNH * CHD, 0, 0,
        out, nullptr, nullptr, CHID, 0, 0, nullptr, 1.f, CNH * CHD, 1);
}

// round 9
// speedup vs baseline: 1.2685x; 1.2685x over previous
#include <cuda_runtime.h>
#include <cuda_fp16.h>
#include <math.h>
#include <stdint.h>

// ---------------- problem constants ----------------
#define CB   2
#define CS   2048
#define CHID 2048
#define CNH  16
#define CHD  128
#define CQLR 1536
#define CKVLR 512
#define CBS  (CB*CS)          // 4096
#define CCAT (CKVLR+CHD)      // 640
#define CQHD (2*CHD)          // 256

typedef __half hlf;

// ---------------- device scratch ----------------
static __device__ __align__(256) float g_qa[(size_t)CBS*CQLR];
static __device__ __align__(256) float g_ckv[(size_t)CBS*CCAT];

// A-side (split hi/lo fp16)
static __device__ __align__(256) hlf g_hid_h[(size_t)CBS*CHID],  g_hid_l[(size_t)CBS*CHID];
static __device__ __align__(256) hlf g_qan_h[(size_t)CBS*CQLR], g_qan_l[(size_t)CBS*CQLR];
static __device__ __align__(256) hlf g_qs_h[(size_t)CBS*CNH*CQHD], g_qs_l[(size_t)CBS*CNH*CQHD];
static __device__ __align__(256) hlf g_qc_h[(size_t)CB*CNH*CS*CCAT], g_qc_l[(size_t)CB*CNH*CS*CCAT];
static __device__ __align__(256) hlf g_ol_h[(size_t)CB*CNH*CS*CKVLR], g_ol_l[(size_t)CB*CNH*CS*CKVLR];
static __device__ __align__(256) hlf g_oh_h[(size_t)CBS*CNH*CHD], g_oh_l[(size_t)CBS*CNH*CHD];
// B-side (single fp16)
static __device__ __align__(256) hlf g_qaw[(size_t)CQLR*CHID];
static __device__ __align__(256) hlf g_qbw[(size_t)CNH*CQHD*CQLR];
static __device__ __align__(256) hlf g_kvaw[(size_t)CCAT*CHID];
static __device__ __align__(256) hlf g_ow[(size_t)CHID*CNH*CHD];
static __device__ __align__(256) hlf g_qab[(size_t)CNH*CKVLR*CHD];     // [h][c][d]
static __device__ __align__(256) hlf g_oabt[(size_t)CNH*CHD*CKVLR];    // [h][d][c]
static __device__ __align__(256) hlf g_ckvf[(size_t)CBS*CCAT];         // keys/V, K-major

// ---------------- asm helpers (sm_80-portable) ----------------
__device__ __forceinline__ uint32_t smem_u32(const void* p) {
    uint32_t a;
    asm("{ .reg .u64 t; cvta.to.shared.u64 t, %1; cvt.u32.u64 %0, t; }" : "=r"(a) : "l"(p));
    return a;
}
#define CP_ASYNC16(dst, src) \
    asm volatile("cp.async.cg.shared.global [%0], [%1], 16;" :: "r"(dst), "l"(src) : "memory")
#define CP_COMMIT() asm volatile("cp.async.commit_group;" ::: "memory")
#define CP_WAIT(n)  asm volatile("cp.async.wait_group %0;" :: "n"(n) : "memory")

#define LDSM4(r, addr) \
    asm volatile("ldmatrix.sync.aligned.m8n8.x4.shared.b16 {%0,%1,%2,%3}, [%4];" \
        : "=r"((r)[0]),"=r"((r)[1]),"=r"((r)[2]),"=r"((r)[3]) : "r"(addr))
#define LDSM4T(r, addr) \
    asm volatile("ldmatrix.sync.aligned.m8n8.x4.trans.shared.b16 {%0,%1,%2,%3}, [%4];" \
        : "=r"((r)[0]),"=r"((r)[1]),"=r"((r)[2]),"=r"((r)[3]) : "r"(addr))

#define MMA16816(d, a, b0, b1) \
    asm volatile("mma.sync.aligned.m16n8k16.row.col.f32.f16.f16.f32 " \
        "{%0,%1,%2,%3},{%4,%5,%6,%7},{%8,%9},{%0,%1,%2,%3};" \
        : "+f"((d)[0]),"+f"((d)[1]),"+f"((d)[2]),"+f"((d)[3]) \
        : "r"((a)[0]),"r"((a)[1]),"r"((a)[2]),"r"((a)[3]), "r"(b0),"r"(b1))

__device__ __forceinline__ void split2(float v, hlf* hp, hlf* lp) {
    hlf h = __float2half_rn(v);
    *hp = h;
    *lp = __float2half_rn(v - __half2float(h));
}
__device__ __forceinline__ void split2x2(float v0, float v1, hlf* hp, hlf* lp) {
    hlf h0 = __float2half_rn(v0), h1 = __float2half_rn(v1);
    hlf l0 = __float2half_rn(v0 - __half2float(h0));
    hlf l1 = __float2half_rn(v1 - __half2float(h1));
    __half2 hh; hh.x = h0; hh.y = h1;
    __half2 ll; ll.x = l0; ll.y = l1;
    *reinterpret_cast<__half2*>(hp) = hh;
    *reinterpret_cast<__half2*>(lp) = ll;
}

// ---------------- fp16 A-split MMA GEMM (512 threads, 16 warps) ----------------
// C = alpha*(Ah+Al)@B^T (+bias)(+split-out). 2 MMAs per k-step per acc tile.
static constexpr int GBK = 32, STAGES = 4;
static constexpr int ASZ = 128 * GBK * 2;   // 8192 B per A sub-tile

__device__ __forceinline__ uint32_t swz(int row, int ch) {
    return (uint32_t)(row * 64 + ((ch ^ ((row >> 1) & 3)) * 16));
}

template<int BN>
__global__ __launch_bounds__(512, 1) void mma_gemm(
    const hlf* __restrict__ Ah, const hlf* __restrict__ Al, int lda, long long aO, long long aI,
    const hlf* __restrict__ B, int ldb, long long bO, long long bI,
    float* __restrict__ C, hlf* __restrict__ Chi, hlf* __restrict__ Clo,
    int ldc, long long cO, long long cI,
    const float* __restrict__ bias, float alpha, int K, int zInner)
{
    constexpr int JG = BN / 64;
    constexpr int BSZ = BN * GBK * 2;
    constexpr int STAGE_B = 2 * ASZ + BSZ;

    extern __shared__ char smem_raw[];
    uint32_t sbase = smem_u32(smem_raw);

    int tid = threadIdx.x, wid = tid >> 5, lane = tid & 31;
    int z = blockIdx.z, zo = z / zInner, zi = z - zo * zInner;
    Ah += zo * aO + zi * aI;  Al += zo * aO + zi * aI;
    B  += zo * bO + zi * bI;
    if (C)   C   += zo * cO + zi * cI;
    if (Chi) { Chi += zo * cO + zi * cI; Clo += zo * cO + zi * cI; }

    int bm = blockIdx.y * 128, bn = blockIdx.x * BN;
    int wm = (wid & 3) * 32;
    int wn = (wid >> 2) * (BN / 4);

    const hlf* pAh = Ah + (long long)bm * lda;
    const hlf* pAl = Al + (long long)bm * lda;
    const hlf* pB  = B  + (long long)bn * ldb;

    float acc[2][2 * JG][4];
#pragma unroll
    for (int t = 0; t < 2; t++)
#pragma unroll
        for (int j = 0; j < 2 * JG; j++)
#pragma unroll
            for (int q = 0; q < 4; q++) acc[t][j][q] = 0.f;

    int nk = K / GBK;

#define ISSUE(stage_) do { \
    int st_ = (stage_) % STAGES; \
    uint32_t sb_ = sbase + st_ * STAGE_B; \
    long long k0_ = (long long)(stage_) * GBK; \
    { int r = tid >> 2, ch = tid & 3; \
      uint32_t so = swz(r, ch); \
      CP_ASYNC16(sb_ + so,       pAh + (long long)r * lda + k0_ + ch * 8); \
      CP_ASYNC16(sb_ + ASZ + so, pAl + (long long)r * lda + k0_ + ch * 8); } \
    _Pragma("unroll") \
    for (int u = 0; u < BN / 128; u++) { \
        int idx = u * 512 + tid; int r = idx >> 2, ch = idx & 3; \
        uint32_t so = swz(r, ch); \
        CP_ASYNC16(sb_ + 2 * ASZ + so, pB + (long long)r * ldb + k0_ + ch * 8); \
    } \
} while (0)

    for (int s = 0; s < STAGES - 1; s++) {
        if (s < nk) ISSUE(s);
        CP_COMMIT();
    }

    int a_row = (lane & 15);
    int a_sel = lane >> 4;
    int b_row = (lane & 7) + ((lane >> 4) * 8);
    int b_sel = (lane >> 3) & 1;

    for (int i = 0; i < nk; i++) {
        CP_WAIT(STAGES - 2);
        __syncthreads();
        if (i + STAGES - 1 < nk) ISSUE(i + STAGES - 1);
        CP_COMMIT();

        uint32_t sb = sbase + (i % STAGES) * STAGE_B;

#pragma unroll
        for (int kh = 0; kh < 2; kh++) {
            uint32_t Afh[2][4], Afl[2][4];
#pragma unroll
            for (int t = 0; t < 2; t++) {
                int row = wm + t * 16 + a_row;
                uint32_t off = swz(row, 2 * kh + a_sel);
                LDSM4(Afh[t], sb + off);
                LDSM4(Afl[t], sb + ASZ + off);
            }
#pragma unroll
            for (int jg = 0; jg < JG; jg++) {
                int row = wn + jg * 16 + b_row;
                uint32_t off = swz(row, 2 * kh + b_sel);
                uint32_t B4[4];
                LDSM4(B4, sb + 2 * ASZ + off);
#pragma unroll
                for (int t = 0; t < 2; t++) {
                    MMA16816(acc[t][2*jg],   Afh[t], B4[0], B4[1]);
                    MMA16816(acc[t][2*jg],   Afl[t], B4[0], B4[1]);
                    MMA16816(acc[t][2*jg+1], Afh[t], B4[2], B4[3]);
                    MMA16816(acc[t][2*jg+1], Afl[t], B4[2], B4[3]);
                }
            }
        }
    }
#undef ISSUE

#pragma unroll
    for (int t = 0; t < 2; t++) {
        int r0 = bm + wm + t * 16 + (lane >> 2);
#pragma unroll
        for (int j = 0; j < 2 * JG; j++) {
            int col = bn + wn + j * 8 + (lane & 3) * 2;
            float v0 = acc[t][j][0] * alpha;
            float v1 = acc[t][j][1] * alpha;
            float v2 = acc[t][j][2] * alpha;
            float v3 = acc[t][j][3] * alpha;
            if (bias) { v0 += bias[col]; v1 += bias[col + 1]; v2 += bias[col]; v3 += bias[col + 1]; }
            if (Chi) {
                long long o0 = (long long)r0 * ldc + col;
                long long o1 = (long long)(r0 + 8) * ldc + col;
                split2x2(v0, v1, Chi + o0, Clo + o0);
                split2x2(v2, v3, Chi + o1, Clo + o1);
            } else {
                C[(long long)r0 * ldc + col]           = v0;
                C[(long long)r0 * ldc + col + 1]       = v1;
                C[(long long)(r0 + 8) * ldc + col]     = v2;
                C[(long long)(r0 + 8) * ldc + col + 1] = v3;
            }
        }
    }
}

// ---------------- fused flash attention (512 threads) ----------------
// CTA: 64 q rows, one (b,h). K' tile (64 keys x 640, single fp16) resident;
// V = K'[:, :512] via ldmatrix.trans. Q/P split fp16. Max-free softmax.
// smem: K chunks 10 x 8KB = 80KB @0; Q ring 4 x 16KB @81920 (P overlays slot 0).
static constexpr int FQOFF = 81920;
static constexpr int FSMEM = 81920 + 4 * 16384;   // 144 KB

__device__ __forceinline__ uint32_t psw(int row, int ch) {
    return (uint32_t)(row * 128 + ((ch ^ (row & 7)) << 4));
}

__device__ __forceinline__ void fissue(uint32_t sbase, int kc,
    const hlf* pQh, const hlf* pQl, const hlf* pKj,
    uint32_t soff, long long goff)
{
    uint32_t kb = sbase + kc * 8192;
    uint32_t qb = sbase + FQOFF + (kc & 3) * 16384;
    long long co = (long long)kc * 64;
    CP_ASYNC16(kb + soff,        pKj + goff + co);
    CP_ASYNC16(qb + soff,        pQh + goff + co);
    CP_ASYNC16(qb + 8192 + soff, pQl + goff + co);
}

__global__ __launch_bounds__(512, 1) void flash_kernel(
    const hlf* __restrict__ Qh, const hlf* __restrict__ Ql,
    const hlf* __restrict__ Kf,
    const float* __restrict__ mask,
    hlf* __restrict__ Oh, hlf* __restrict__ Ol,
    float scale)
{
    extern __shared__ char smem[];
    uint32_t sbase = smem_u32(smem);
    int tid = threadIdx.x, wid = tid >> 5, lane = tid & 31;
    int mg = wid & 3, cg = wid >> 2;
    int bh = blockIdx.y, b = bh >> 4;
    int q0 = blockIdx.x * 64;

    const hlf* pQh = Qh + (long long)bh * CS * CCAT + (long long)q0 * CCAT;
    const hlf* pQl = Ql + (long long)bh * CS * CCAT + (long long)q0 * CCAT;
    const hlf* pK  = Kf + (long long)b * CS * CCAT;

    int lrow = tid >> 3, lch = tid & 7;
    uint32_t soff = psw(lrow, lch);
    long long goff = (long long)lrow * CCAT + lch * 8;

    int arow = mg * 16 + (lane & 15);
    int asel = lane >> 4;
    int brow = cg * 16 + (lane & 7) + ((lane >> 4) * 8);
    int bsel = (lane >> 3) & 1;
    int trow_b = (lane & 7) + (((lane >> 3) & 1) * 8);
    int tsel = lane >> 4;

    float oacc[16][4];
#pragma unroll
    for (int i = 0; i < 16; i++)
#pragma unroll
        for (int q = 0; q < 4; q++) oacc[i][q] = 0.f;
    float lsum0 = 0.f, lsum1 = 0.f;

    int prow0 = mg * 16 + (lane >> 2), prow1 = prow0 + 8;

    for (int j = 0; j < 32; j++) {
        const hlf* pKj = pK + (long long)j * 64 * CCAT;

        fissue(sbase, 0, pQh, pQl, pKj, soff, goff); CP_COMMIT();
        fissue(sbase, 1, pQh, pQl, pKj, soff, goff); CP_COMMIT();
        fissue(sbase, 2, pQh, pQl, pKj, soff, goff); CP_COMMIT();

        float sacc[2][4];
#pragma unroll
        for (int n = 0; n < 2; n++)
#pragma unroll
            for (int q = 0; q < 4; q++) sacc[n][q] = 0.f;

        for (int kc = 0; kc < 10; kc++) {
            CP_WAIT(2);
            __syncthreads();
            if (kc + 3 < 10) fissue(sbase, kc + 3, pQh, pQl, pKj, soff, goff);
            CP_COMMIT();
            uint32_t kb = sbase + kc * 8192;
            uint32_t qb = sbase + FQOFF + (kc & 3) * 16384;
#pragma unroll
            for (int kk = 0; kk < 4; kk++) {
                uint32_t ao = psw(arow, kk * 2 + asel);
                uint32_t Ah4[4], Al4[4];
                LDSM4(Ah4, qb + ao);
                LDSM4(Al4, qb + 8192 + ao);
                uint32_t bo = psw(brow, kk * 2 + bsel);
                uint32_t B4[4];
                LDSM4(B4, kb + bo);
                MMA16816(sacc[0], Ah4, B4[0], B4[1]);
                MMA16816(sacc[0], Al4, B4[0], B4[1]);
                MMA16816(sacc[1], Ah4, B4[2], B4[3]);
                MMA16816(sacc[1], Al4, B4[2], B4[3]);
            }
        }
        // no sync needed: P overlays Q slot 0; last slot-0 reader (kc=8) is
        // fenced by kc=9's top-of-loop __syncthreads.

        // softmax (max-free) + P split write
        {
            const float* mrow = mask + (long long)b * CS * CS
                              + (long long)(q0 + prow0) * CS + j * 64 + cg * 16 + (lane & 3) * 2;
            float ladd0 = 0.f, ladd1 = 0.f;
#pragma unroll
            for (int nn = 0; nn < 2; nn++) {
                float2 m0 = *reinterpret_cast<const float2*>(mrow + nn * 8);
                float2 m1 = *reinterpret_cast<const float2*>(mrow + nn * 8 + 8 * CS);
                float p0 = __expf(sacc[nn][0] * scale + m0.x);
                float p1 = __expf(sacc[nn][1] * scale + m0.y);
                float p2 = __expf(sacc[nn][2] * scale + m1.x);
                float p3 = __expf(sacc[nn][3] * scale + m1.y);
                ladd0 += p0 + p1; ladd1 += p2 + p3;
                int col = cg * 16 + nn * 8 + (lane & 3) * 2;
                uint32_t o0 = (uint32_t)(prow0 * 128 + ((((col >> 3)) ^ (prow0 & 7)) << 4) + (col & 7) * 2);
                uint32_t o1 = (uint32_t)(prow1 * 128 + ((((col >> 3)) ^ (prow1 & 7)) << 4) + (col & 7) * 2);
                split2x2(p0, p1, (hlf*)(smem + FQOFF + o0), (hlf*)(smem + FQOFF + 8192 + o0));
                split2x2(p2, p3, (hlf*)(smem + FQOFF + o1), (hlf*)(smem + FQOFF + 8192 + o1));
            }
            ladd0 += __shfl_xor_sync(~0u, ladd0, 1); ladd0 += __shfl_xor_sync(~0u, ladd0, 2);
            ladd1 += __shfl_xor_sync(~0u, ladd1, 1); ladd1 += __shfl_xor_sync(~0u, ladd1, 2);
            lsum0 += ladd0; lsum1 += ladd1;
        }
        __syncthreads();   // P visible to all warps

        // AV: O += P*V; warp covers 16 rows x 128 cols
#pragma unroll
        for (int kt = 0; kt < 4; kt++) {
            uint32_t ao = psw(arow, kt * 2 + asel);
            uint32_t Ph4[4], Pl4[4];
            LDSM4(Ph4, sbase + FQOFF + ao);
            LDSM4(Pl4, sbase + FQOFF + 8192 + ao);
            int trow = kt * 16 + trow_b;
#pragma unroll
            for (int ng = 0; ng < 8; ng++) {
                int c0 = cg * 128 + ng * 16;
                uint32_t kcb = sbase + (c0 >> 6) * 8192;
                uint32_t bo = psw(trow, ((c0 & 63) >> 3) + tsel);
                uint32_t V4[4];
                LDSM4T(V4, kcb + bo);
                MMA16816(oacc[ng*2],   Ph4, V4[0], V4[1]);
                MMA16816(oacc[ng*2],   Pl4, V4[0], V4[1]);
                MMA16816(oacc[ng*2+1], Ph4, V4[2], V4[3]);
                MMA16816(oacc[ng*2+1], Pl4, V4[2], V4[3]);
            }
        }
        __syncthreads();   // AV reads done before next j overwrites K/Q/P
    }

    // finalize
    float* Larr = reinterpret_cast<float*>(smem);
    if ((lane & 3) == 0) {
        Larr[cg * 64 + prow0] = lsum0;
        Larr[cg * 64 + prow1] = lsum1;
    }
    __syncthreads();
    float inv0 = 1.f / (Larr[prow0] + Larr[64 + prow0] + Larr[128 + prow0] + Larr[192 + prow0]);
    float inv1 = 1.f / (Larr[prow1] + Larr[64 + prow1] + Larr[128 + prow1] + Larr[192 + prow1]);

    hlf* poh = Oh + (long long)bh * CS * CKVLR + (long long)q0 * CKVLR;
    hlf* pol = Ol + (long long)bh * CS * CKVLR + (long long)q0 * CKVLR;
#pragma unroll
    for (int ng = 0; ng < 8; ng++) {
#pragma unroll
        for (int h8 = 0; h8 < 2; h8++) {
            int c = cg * 128 + ng * 16 + h8 * 8 + (lane & 3) * 2;
            float* a = oacc[ng * 2 + h8];
            long long o0 = (long long)prow0 * CKVLR + c;
            long long o1 = (long long)prow1 * CKVLR + c;
            split2x2(a[0] * inv0, a[1] * inv0, poh + o0, pol + o0);
            split2x2(a[2] * inv1, a[3] * inv1, poh + o1, pol + o1);
        }
    }
}

// ---------------- conversions ----------------
__global__ void cvt_split_kernel(const float* __restrict__ s, hlf* __restrict__ hi, hlf* __restrict__ lo, long long n)
{
    long long n4 = n >> 2;
    long long i = (long long)blockIdx.x * blockDim.x + threadIdx.x;
    long long st = (long long)gridDim.x * blockDim.x;
    for (; i < n4; i += st) {
        float4 v = reinterpret_cast<const float4*>(s)[i];
        hlf h[4], l[4];
        h[0] = __float2half_rn(v.x); l[0] = __float2half_rn(v.x - __half2float(h[0]));
        h[1] = __float2half_rn(v.y); l[1] = __float2half_rn(v.y - __half2float(h[1]));
        h[2] = __float2half_rn(v.z); l[2] = __float2half_rn(v.z - __half2float(h[2]));
        h[3] = __float2half_rn(v.w); l[3] = __float2half_rn(v.w - __half2float(h[3]));
        *reinterpret_cast<uint2*>(hi + i * 4) = *reinterpret_cast<uint2*>(h);
        *reinterpret_cast<uint2*>(lo + i * 4) = *reinterpret_cast<uint2*>(l);
    }
}

__global__ void cvt_half_kernel(const float* __restrict__ s, hlf* __restrict__ d, long long n)
{
    long long n4 = n >> 2;
    long long i = (long long)blockIdx.x * blockDim.x + threadIdx.x;
    long long st = (long long)gridDim.x * blockDim.x;
    for (; i < n4; i += st) {
        float4 v = reinterpret_cast<const float4*>(s)[i];
        hlf h[4];
        h[0] = __float2half_rn(v.x); h[1] = __float2half_rn(v.y);
        h[2] = __float2half_rn(v.z); h[3] = __float2half_rn(v.w);
        *reinterpret_cast<uint2*>(d + i * 4) = *reinterpret_cast<uint2*>(h);
    }
}

// qab [h][c][d], oabT [h][d][c] from kv_b_W [c, h, 2, d] (single fp16)
__global__ void extract_kernel(const float* __restrict__ kvb,
                               hlf* __restrict__ qab, hlf* __restrict__ oabt)
{
    long long n = (long long)CNH * CKVLR * CHD;
    long long i = (long long)blockIdx.x * blockDim.x + threadIdx.x;
    long long st = (long long)gridDim.x * blockDim.x;
    for (; i < n; i += st) {
        {
            int c = (int)(i & 511);
            int d = (int)((i >> 9) & 127);
            int h = (int)(i >> 16);
            oabt[i] = __float2half_rn(kvb[(((long long)c * CNH + h) * 2 + 1) * CHD + d]);
        }
        {
            int d = (int)(i & 127);
            int c = (int)((i >> 7) & 511);
            int h = (int)(i >> 16);
            qab[i] = __float2half_rn(kvb[(((long long)c * CNH + h) * 2) * CHD + d]);
        }
    }
}

// ---------------- RMSNorm ----------------
__global__ __launch_bounds__(256) void rms_kernel(const float* __restrict__ x, const float* __restrict__ w,
                                                  hlf* __restrict__ hi, hlf* __restrict__ lo)
{
    __shared__ float red[8];
    size_t row = blockIdx.x;
    const float* p = x + row * CQLR;
    int tid = threadIdx.x;
    float s = 0.f;
    for (int i = tid; i < CQLR; i += 256) { float v = p[i]; s += v * v; }
#pragma unroll
    for (int o = 16; o; o >>= 1) s += __shfl_xor_sync(~0u, s, o);
    if ((tid & 31) == 0) red[tid >> 5] = s;
    __syncthreads();
    float tot = 0.f;
#pragma unroll
    for (int i = 0; i < 8; i++) tot += red[i];
    float r = rsqrtf(tot + 1e-6f);
    hlf* ph = hi + row * CQLR;
    hlf* pl = lo + row * CQLR;
    for (int i = tid; i < CQLR; i += 256) split2(p[i] * r * w[i], ph + i, pl + i);
}

// ---------------- RoPE ----------------
__device__ __forceinline__ void rope_cs(int s, int i, float& c, float& sn)
{
    double invf = pow(10000.0, -(double)(2 * i) / 128.0);
    double ang = (double)s * invf;
    c = (float)cos(ang);
    sn = (float)sin(ang);
}

__global__ void rope_k_kernel(float* __restrict__ ckv)
{
    int idx = blockIdx.x * blockDim.x + threadIdx.x;
    if (idx >= CB * CS * 64) return;
    int i = idx & 63;
    int row = idx >> 6;
    int s = row & (CS - 1);
    float c, sn; rope_cs(s, i, c, sn);
    float* p = ckv + (size_t)row * CCAT + CKVLR;
    float x1 = p[i], x2 = p[i + 64];
    p[i]      = x1 * c - x2 * sn;
    p[i + 64] = x2 * c + x1 * sn;
}

__global__ void rope_q_kernel(const hlf* __restrict__ qh, const hlf* __restrict__ ql,
                              hlf* __restrict__ qch, hlf* __restrict__ qcl)
{
    int idx = blockIdx.x * blockDim.x + threadIdx.x;
    if (idx >= CB * CS * CNH * 64) return;
    int i = idx & 63;
    int h = (idx >> 6) & 15;
    int row = idx >> 10;
    int s = row & (CS - 1);
    int b = row >> 11;
    float c, sn; rope_cs(s, i, c, sn);
    long long so = (long long)row * (CNH * CQHD) + h * CQHD + CHD;
    float x1 = __half2float(qh[so + i])      + __half2float(ql[so + i]);
    float x2 = __half2float(qh[so + i + 64]) + __half2float(ql[so + i + 64]);
    long long dofs = ((long long)(b * CNH + h) * CS + s) * CCAT + CKVLR;
    split2(x1 * c - x2 * sn, qch + dofs + i,      qcl + dofs + i);
    split2(x2 * c + x1 * sn, qch + dofs + i + 64, qcl + dofs + i + 64);
}

// ---------------- launch ----------------
extern "C" void kernel_launch(void* const* d_in, const int* in_sizes, int n_in,
                              void* d_out, int out_size)
{
    const float* hidden = (const float*)d_in[0];
    const float* mask   = (const float*)d_in[1];
    const float* q_a_W  = (const float*)d_in[2];
    const float* q_a_b  = (const float*)d_in[3];
    const float* q_a_nw = (const float*)d_in[4];
    const float* q_b_W  = (const float*)d_in[5];
    const float* kv_a_W = (const float*)d_in[6];
    const float* kv_b_W = (const float*)d_in[7];
    const float* o_W    = (const float*)d_in[8];
    float* out = (float*)d_out;

    void* p;
#define SYM(v, g) cudaGetSymbolAddress(&p, g); auto* v = (decltype(&g[0]))p
    SYM(qa, g_qa);     SYM(ckv, g_ckv);
    SYM(hidh, g_hid_h); SYM(hidl, g_hid_l);
    SYM(qaw, g_qaw);   SYM(qbw, g_qbw);
    SYM(kvaw, g_kvaw); SYM(ow, g_ow);
    SYM(qanh, g_qan_h); SYM(qanl, g_qan_l);
    SYM(qsh, g_qs_h);   SYM(qsl, g_qs_l);
    SYM(qab, g_qab);   SYM(oabt, g_oabt);
    SYM(qch, g_qc_h);   SYM(qcl, g_qc_l);
    SYM(ckvf, g_ckvf);
    SYM(olh, g_ol_h);   SYM(oll, g_ol_l);
    SYM(ohh, g_oh_h);   SYM(ohl, g_oh_l);
#undef SYM

    constexpr int SMEM128 = STAGES * (2 * ASZ + 128 * GBK * 2);  //  96 KB
    constexpr int SMEM256 = STAGES * (2 * ASZ + 256 * GBK * 2);  // 128 KB
    cudaFuncSetAttribute(mma_gemm<128>, cudaFuncAttributeMaxDynamicSharedMemorySize, SMEM128);
    cudaFuncSetAttribute(mma_gemm<256>, cudaFuncAttributeMaxDynamicSharedMemorySize, SMEM256);
    cudaFuncSetAttribute(flash_kernel, cudaFuncAttributeMaxDynamicSharedMemorySize, FSMEM);

    const long long LS = CS;
    const int CVG = 2048;

    cvt_split_kernel<<<CVG, 256>>>(hidden, hidh, hidl, (long long)CBS * CHID);
    cvt_half_kernel<<<CVG, 256>>>(q_a_W, qaw, (long long)CQLR * CHID);
    cvt_half_kernel<<<CVG, 256>>>(kv_a_W, kvaw, (long long)CCAT * CHID);

    // q_a = hidden @ q_a_W^T + bias   [4096,1536] K=2048, fp32 out
    mma_gemm<256><<<dim3(CQLR / 256, CBS / 128, 1), 512, SMEM256>>>(
        hidh, hidl, CHID, 0, 0, qaw, CHID, 0, 0,
        qa, nullptr, nullptr, CQLR, 0, 0, q_a_b, 1.f, CHID, 1);

    // ckv = hidden @ kv_a_W^T  [4096,640] K=2048, fp32 out
    mma_gemm<128><<<dim3(CCAT / 128, CBS / 128, 1), 512, SMEM128>>>(
        hidh, hidl, CHID, 0, 0, kvaw, CHID, 0, 0,
        ckv, nullptr, nullptr, CCAT, 0, 0, nullptr, 1.f, CHID, 1);

    rms_kernel<<<CBS, 256>>>(qa, q_a_nw, qanh, qanl);
    cvt_half_kernel<<<CVG, 256>>>(q_b_W, qbw, (long long)CNH * CQHD * CQLR);

    // q = qa_norm @ q_b_W^T  [4096,4096] K=1536, split out
    mma_gemm<256><<<dim3((CNH * CQHD) / 256, CBS / 128, 1), 512, SMEM256>>>(
        qanh, qanl, CQLR, 0, 0, qbw, CQLR, 0, 0,
        nullptr, qsh, qsl, CNH * CQHD, 0, 0, nullptr, 1.f, CQLR, 1);

    extract_kernel<<<CVG, 256>>>(kv_b_W, qab, oabt);
    rope_k_kernel<<<(CB * CS * 64) / 256, 256>>>(ckv);
    rope_q_kernel<<<(CB * CS * CNH * 64) / 256, 256>>>(qsh, qsl, qch, qcl);

    // q_lat -> qcat cols [0,512)  K=128, Z=32, split out
    mma_gemm<256><<<dim3(CKVLR / 256, CS / 128, CB * CNH), 512, SMEM256>>>(
        qsh, qsl, CNH * CQHD, LS * CNH * CQHD, CQHD,
        qab, CHD, 0, (long long)CKVLR * CHD,
        nullptr, qch, qcl, CCAT, LS * CNH * CCAT, LS * CCAT,
        nullptr, 1.f, CHD, CNH);

    // keys/V single fp16 (K-major)
    cvt_half_kernel<<<CVG, 256>>>(ckv, ckvf, (long long)CBS * CCAT);

    // fused attention: scores + softmax + AV -> olat split
    float scale = 1.f / sqrtf((float)CCAT);
    flash_kernel<<<dim3(CS / 64, CB * CNH), 512, FSMEM>>>(
        qch, qcl, ckvf, mask, olh, oll, scale);

    cvt_half_kernel<<<CVG, 256>>>(o_W, ow, (long long)CHID * CNH * CHD);

    // out_head = olat . o_absorb^T -> [b,s,h*128+d]  K=512, N=128, Z=32, split out
    mma_gemm<128><<<dim3(1, CS / 128, CB * CNH), 512, SMEM128>>>(
        olh, oll, CKVLR, LS * CNH * CKVLR, LS * CKVLR,
        oabt, CKVLR, 0, (long long)CHD * CKVLR,
        nullptr, ohh, ohl, CNH * CHD, LS * (long long)CNH * CHD, CHD,
        nullptr, 1.f, CKVLR, CNH);

    // final = ohead @ o_W^T  [4096,2048] K=2048, fp32 out
    mma_gemm<256><<<dim3(CHID / 256, CBS / 128, 1), 512, SMEM256>>>(
        ohh, ohl, CNH * CHD, 0, 0, ow, CNH * CHD, 0, 0,
        out, nullptr, nullptr, CHID, 0, 0, nullptr, 1.f, CNH * CHD, 1);
}

// round 10
// speedup vs baseline: 1.5249x; 1.2021x over previous
#include <cuda_runtime.h>
#include <cuda_fp16.h>
#include <math.h>
#include <stdint.h>

// ---------------- problem constants ----------------
#define CB   2
#define CS   2048
#define CHID 2048
#define CNH  16
#define CHD  128
#define CQLR 1536
#define CKVLR 512
#define CBS  (CB*CS)          // 4096
#define CCAT (CKVLR+CHD)      // 640
#define CQHD (2*CHD)          // 256

typedef __half hlf;

// ---------------- device scratch ----------------
static __device__ __align__(256) float g_qa[(size_t)CBS*CQLR];
static __device__ __align__(256) float g_ckv[(size_t)CBS*CCAT];

// A-side (split hi/lo fp16)
static __device__ __align__(256) hlf g_hid_h[(size_t)CBS*CHID],  g_hid_l[(size_t)CBS*CHID];
static __device__ __align__(256) hlf g_qan_h[(size_t)CBS*CQLR], g_qan_l[(size_t)CBS*CQLR];
static __device__ __align__(256) hlf g_qs_h[(size_t)CBS*CNH*CQHD], g_qs_l[(size_t)CBS*CNH*CQHD];
static __device__ __align__(256) hlf g_ol_h[(size_t)CB*CNH*CS*CKVLR], g_ol_l[(size_t)CB*CNH*CS*CKVLR];
static __device__ __align__(256) hlf g_oh_h[(size_t)CBS*CNH*CHD], g_oh_l[(size_t)CBS*CNH*CHD];
// single fp16
static __device__ __align__(256) hlf g_qc[(size_t)CB*CNH*CS*CCAT];     // Q-cat (single)
static __device__ __align__(256) hlf g_qaw[(size_t)CQLR*CHID];
static __device__ __align__(256) hlf g_qbw[(size_t)CNH*CQHD*CQLR];
static __device__ __align__(256) hlf g_kvaw[(size_t)CCAT*CHID];
static __device__ __align__(256) hlf g_ow[(size_t)CHID*CNH*CHD];
static __device__ __align__(256) hlf g_qab[(size_t)CNH*CKVLR*CHD];     // [h][c][d]
static __device__ __align__(256) hlf g_oabt[(size_t)CNH*CHD*CKVLR];    // [h][d][c]
static __device__ __align__(256) hlf g_ckvf[(size_t)CBS*CCAT];         // keys/V, K-major

// ---------------- asm helpers (sm_80-portable) ----------------
__device__ __forceinline__ uint32_t smem_u32(const void* p) {
    uint32_t a;
    asm("{ .reg .u64 t; cvta.to.shared.u64 t, %1; cvt.u32.u64 %0, t; }" : "=r"(a) : "l"(p));
    return a;
}
#define CP_ASYNC16(dst, src) \
    asm volatile("cp.async.cg.shared.global [%0], [%1], 16;" :: "r"(dst), "l"(src) : "memory")
#define CP_COMMIT() asm volatile("cp.async.commit_group;" ::: "memory")
#define CP_WAIT(n)  asm volatile("cp.async.wait_group %0;" :: "n"(n) : "memory")

#define LDSM4(r, addr) \
    asm volatile("ldmatrix.sync.aligned.m8n8.x4.shared.b16 {%0,%1,%2,%3}, [%4];" \
        : "=r"((r)[0]),"=r"((r)[1]),"=r"((r)[2]),"=r"((r)[3]) : "r"(addr))
#define LDSM4T(r, addr) \
    asm volatile("ldmatrix.sync.aligned.m8n8.x4.trans.shared.b16 {%0,%1,%2,%3}, [%4];" \
        : "=r"((r)[0]),"=r"((r)[1]),"=r"((r)[2]),"=r"((r)[3]) : "r"(addr))

#define MMA16816(d, a, b0, b1) \
    asm volatile("mma.sync.aligned.m16n8k16.row.col.f32.f16.f16.f32 " \
        "{%0,%1,%2,%3},{%4,%5,%6,%7},{%8,%9},{%0,%1,%2,%3};" \
        : "+f"((d)[0]),"+f"((d)[1]),"+f"((d)[2]),"+f"((d)[3]) \
        : "r"((a)[0]),"r"((a)[1]),"r"((a)[2]),"r"((a)[3]), "r"(b0),"r"(b1))

__device__ __forceinline__ void split2(float v, hlf* hp, hlf* lp) {
    hlf h = __float2half_rn(v);
    *hp = h;
    *lp = __float2half_rn(v - __half2float(h));
}
__device__ __forceinline__ void split2x2(float v0, float v1, hlf* hp, hlf* lp) {
    hlf h0 = __float2half_rn(v0), h1 = __float2half_rn(v1);
    hlf l0 = __float2half_rn(v0 - __half2float(h0));
    hlf l1 = __float2half_rn(v1 - __half2float(h1));
    __half2 hh; hh.x = h0; hh.y = h1;
    __half2 ll; ll.x = l0; ll.y = l1;
    *reinterpret_cast<__half2*>(hp) = hh;
    *reinterpret_cast<__half2*>(lp) = ll;
}
__device__ __forceinline__ void store_h2(float v0, float v1, hlf* hp) {
    __half2 hh; hh.x = __float2half_rn(v0); hh.y = __float2half_rn(v1);
    *reinterpret_cast<__half2*>(hp) = hh;
}

// ---------------- fp16 A-split MMA GEMM (512 threads, 16 warps) ----------------
// C = alpha*(Ah+Al)@B^T (+bias). Out: fp32 (C), split (Chi+Clo), or single (Chi).
static constexpr int GBK = 32, STAGES = 4;
static constexpr int ASZ = 128 * GBK * 2;   // 8192 B per A sub-tile

__device__ __forceinline__ uint32_t swz(int row, int ch) {
    return (uint32_t)(row * 64 + ((ch ^ ((row >> 1) & 3)) * 16));
}

template<int BN>
__global__ __launch_bounds__(512, 1) void mma_gemm(
    const hlf* __restrict__ Ah, const hlf* __restrict__ Al, int lda, long long aO, long long aI,
    const hlf* __restrict__ B, int ldb, long long bO, long long bI,
    float* __restrict__ C, hlf* __restrict__ Chi, hlf* __restrict__ Clo,
    int ldc, long long cO, long long cI,
    const float* __restrict__ bias, float alpha, int K, int zInner)
{
    constexpr int JG = BN / 64;
    constexpr int BSZ = BN * GBK * 2;
    constexpr int STAGE_B = 2 * ASZ + BSZ;

    extern __shared__ char smem_raw[];
    uint32_t sbase = smem_u32(smem_raw);

    int tid = threadIdx.x, wid = tid >> 5, lane = tid & 31;
    int z = blockIdx.z, zo = z / zInner, zi = z - zo * zInner;
    Ah += zo * aO + zi * aI;  Al += zo * aO + zi * aI;
    B  += zo * bO + zi * bI;
    if (C)   C   += zo * cO + zi * cI;
    if (Chi) Chi += zo * cO + zi * cI;
    if (Clo) Clo += zo * cO + zi * cI;

    int bm = blockIdx.y * 128, bn = blockIdx.x * BN;
    int wm = (wid & 3) * 32;
    int wn = (wid >> 2) * (BN / 4);

    const hlf* pAh = Ah + (long long)bm * lda;
    const hlf* pAl = Al + (long long)bm * lda;
    const hlf* pB  = B  + (long long)bn * ldb;

    float acc[2][2 * JG][4];
#pragma unroll
    for (int t = 0; t < 2; t++)
#pragma unroll
        for (int j = 0; j < 2 * JG; j++)
#pragma unroll
            for (int q = 0; q < 4; q++) acc[t][j][q] = 0.f;

    int nk = K / GBK;

#define ISSUE(stage_) do { \
    int st_ = (stage_) % STAGES; \
    uint32_t sb_ = sbase + st_ * STAGE_B; \
    long long k0_ = (long long)(stage_) * GBK; \
    { int r = tid >> 2, ch = tid & 3; \
      uint32_t so = swz(r, ch); \
      CP_ASYNC16(sb_ + so,       pAh + (long long)r * lda + k0_ + ch * 8); \
      CP_ASYNC16(sb_ + ASZ + so, pAl + (long long)r * lda + k0_ + ch * 8); } \
    _Pragma("unroll") \
    for (int u = 0; u < BN / 128; u++) { \
        int idx = u * 512 + tid; int r = idx >> 2, ch = idx & 3; \
        uint32_t so = swz(r, ch); \
        CP_ASYNC16(sb_ + 2 * ASZ + so, pB + (long long)r * ldb + k0_ + ch * 8); \
    } \
} while (0)

    for (int s = 0; s < STAGES - 1; s++) {
        if (s < nk) ISSUE(s);
        CP_COMMIT();
    }

    int a_row = (lane & 15);
    int a_sel = lane >> 4;
    int b_row = (lane & 7) + ((lane >> 4) * 8);
    int b_sel = (lane >> 3) & 1;

    for (int i = 0; i < nk; i++) {
        CP_WAIT(STAGES - 2);
        __syncthreads();
        if (i + STAGES - 1 < nk) ISSUE(i + STAGES - 1);
        CP_COMMIT();

        uint32_t sb = sbase + (i % STAGES) * STAGE_B;

#pragma unroll
        for (int kh = 0; kh < 2; kh++) {
            uint32_t Afh[2][4], Afl[2][4];
#pragma unroll
            for (int t = 0; t < 2; t++) {
                int row = wm + t * 16 + a_row;
                uint32_t off = swz(row, 2 * kh + a_sel);
                LDSM4(Afh[t], sb + off);
                LDSM4(Afl[t], sb + ASZ + off);
            }
#pragma unroll
            for (int jg = 0; jg < JG; jg++) {
                int row = wn + jg * 16 + b_row;
                uint32_t off = swz(row, 2 * kh + b_sel);
                uint32_t B4[4];
                LDSM4(B4, sb + 2 * ASZ + off);
#pragma unroll
                for (int t = 0; t < 2; t++) {
                    MMA16816(acc[t][2*jg],   Afh[t], B4[0], B4[1]);
                    MMA16816(acc[t][2*jg],   Afl[t], B4[0], B4[1]);
                    MMA16816(acc[t][2*jg+1], Afh[t], B4[2], B4[3]);
                    MMA16816(acc[t][2*jg+1], Afl[t], B4[2], B4[3]);
                }
            }
        }
    }
#undef ISSUE

#pragma unroll
    for (int t = 0; t < 2; t++) {
        int r0 = bm + wm + t * 16 + (lane >> 2);
#pragma unroll
        for (int j = 0; j < 2 * JG; j++) {
            int col = bn + wn + j * 8 + (lane & 3) * 2;
            float v0 = acc[t][j][0] * alpha;
            float v1 = acc[t][j][1] * alpha;
            float v2 = acc[t][j][2] * alpha;
            float v3 = acc[t][j][3] * alpha;
            if (bias) { v0 += bias[col]; v1 += bias[col + 1]; v2 += bias[col]; v3 += bias[col + 1]; }
            long long o0 = (long long)r0 * ldc + col;
            long long o1 = (long long)(r0 + 8) * ldc + col;
            if (Chi) {
                if (Clo) {
                    split2x2(v0, v1, Chi + o0, Clo + o0);
                    split2x2(v2, v3, Chi + o1, Clo + o1);
                } else {
                    store_h2(v0, v1, Chi + o0);
                    store_h2(v2, v3, Chi + o1);
                }
            } else {
                C[o0] = v0; C[o0 + 1] = v1;
                C[o1] = v2; C[o1 + 1] = v3;
            }
        }
    }
}

// ---------------- fused flash attention (512 threads, pure fp16) ----------------
// CTA: 64 q rows, one (b,h). K' tile (64 keys x 640 fp16) resident;
// V = K'[:, :512] via ldmatrix.trans. Q/P single fp16. Max-free softmax.
// smem: K chunks 10 x 8KB = 80KB @0; Q ring 4 x 8KB @81920 (P overlays slot 0).
static constexpr int FQOFF = 81920;
static constexpr int FSMEM = 81920 + 4 * 8192;   // 112 KB

__device__ __forceinline__ uint32_t psw(int row, int ch) {
    return (uint32_t)(row * 128 + ((ch ^ (row & 7)) << 4));
}

__device__ __forceinline__ void fissue(uint32_t sbase, int kc,
    const hlf* pQ, const hlf* pKj, uint32_t soff, long long goff)
{
    uint32_t kb = sbase + kc * 8192;
    uint32_t qb = sbase + FQOFF + (kc & 3) * 8192;
    long long co = (long long)kc * 64;
    CP_ASYNC16(kb + soff, pKj + goff + co);
    CP_ASYNC16(qb + soff, pQ + goff + co);
}

__global__ __launch_bounds__(512, 1) void flash_kernel(
    const hlf* __restrict__ Q,
    const hlf* __restrict__ Kf,
    const float* __restrict__ mask,
    hlf* __restrict__ Oh, hlf* __restrict__ Ol,
    float scale)
{
    extern __shared__ char smem[];
    uint32_t sbase = smem_u32(smem);
    int tid = threadIdx.x, wid = tid >> 5, lane = tid & 31;
    int mg = wid & 3, cg = wid >> 2;
    int bh = blockIdx.y, b = bh >> 4;
    int q0 = blockIdx.x * 64;

    const hlf* pQ = Q + (long long)bh * CS * CCAT + (long long)q0 * CCAT;
    const hlf* pK = Kf + (long long)b * CS * CCAT;

    int lrow = tid >> 3, lch = tid & 7;
    uint32_t soff = psw(lrow, lch);
    long long goff = (long long)lrow * CCAT + lch * 8;

    int arow = mg * 16 + (lane & 15);
    int asel = lane >> 4;
    int brow = cg * 16 + (lane & 7) + ((lane >> 4) * 8);
    int bsel = (lane >> 3) & 1;
    int trow_b = (lane & 7) + (((lane >> 3) & 1) * 8);
    int tsel = lane >> 4;

    float oacc[16][4];
#pragma unroll
    for (int i = 0; i < 16; i++)
#pragma unroll
        for (int q = 0; q < 4; q++) oacc[i][q] = 0.f;
    float lsum0 = 0.f, lsum1 = 0.f;

    int prow0 = mg * 16 + (lane >> 2), prow1 = prow0 + 8;

    for (int j = 0; j < 32; j++) {
        const hlf* pKj = pK + (long long)j * 64 * CCAT;

        fissue(sbase, 0, pQ, pKj, soff, goff); CP_COMMIT();
        fissue(sbase, 1, pQ, pKj, soff, goff); CP_COMMIT();
        fissue(sbase, 2, pQ, pKj, soff, goff); CP_COMMIT();

        float sacc[2][4];
#pragma unroll
        for (int n = 0; n < 2; n++)
#pragma unroll
            for (int q = 0; q < 4; q++) sacc[n][q] = 0.f;

        for (int kc = 0; kc < 10; kc++) {
            CP_WAIT(2);
            __syncthreads();
            if (kc + 3 < 10) fissue(sbase, kc + 3, pQ, pKj, soff, goff);
            CP_COMMIT();
            uint32_t kb = sbase + kc * 8192;
            uint32_t qb = sbase + FQOFF + (kc & 3) * 8192;
#pragma unroll
            for (int kk = 0; kk < 4; kk++) {
                uint32_t A4[4];
                LDSM4(A4, qb + psw(arow, kk * 2 + asel));
                uint32_t B4[4];
                LDSM4(B4, kb + psw(brow, kk * 2 + bsel));
                MMA16816(sacc[0], A4, B4[0], B4[1]);
                MMA16816(sacc[1], A4, B4[2], B4[3]);
            }
        }
        // no sync needed: P overlays Q slot 0; last slot-0 reader (kc=8) is
        // fenced by kc=9's top-of-loop __syncthreads.

        // softmax (max-free) + P fp16 write
        {
            const float* mrow = mask + (long long)b * CS * CS
                              + (long long)(q0 + prow0) * CS + j * 64 + cg * 16 + (lane & 3) * 2;
            float ladd0 = 0.f, ladd1 = 0.f;
#pragma unroll
            for (int nn = 0; nn < 2; nn++) {
                float2 m0 = *reinterpret_cast<const float2*>(mrow + nn * 8);
                float2 m1 = *reinterpret_cast<const float2*>(mrow + nn * 8 + 8 * CS);
                float p0 = __expf(sacc[nn][0] * scale + m0.x);
                float p1 = __expf(sacc[nn][1] * scale + m0.y);
                float p2 = __expf(sacc[nn][2] * scale + m1.x);
                float p3 = __expf(sacc[nn][3] * scale + m1.y);
                ladd0 += p0 + p1; ladd1 += p2 + p3;
                int col = cg * 16 + nn * 8 + (lane & 3) * 2;
                uint32_t o0 = (uint32_t)(prow0 * 128 + ((((col >> 3)) ^ (prow0 & 7)) << 4) + (col & 7) * 2);
                uint32_t o1 = (uint32_t)(prow1 * 128 + ((((col >> 3)) ^ (prow1 & 7)) << 4) + (col & 7) * 2);
                store_h2(p0, p1, (hlf*)(smem + FQOFF + o0));
                store_h2(p2, p3, (hlf*)(smem + FQOFF + o1));
            }
            ladd0 += __shfl_xor_sync(~0u, ladd0, 1); ladd0 += __shfl_xor_sync(~0u, ladd0, 2);
            ladd1 += __shfl_xor_sync(~0u, ladd1, 1); ladd1 += __shfl_xor_sync(~0u, ladd1, 2);
            lsum0 += ladd0; lsum1 += ladd1;
        }
        __syncthreads();   // P visible to all warps

        // AV: O += P*V; warp covers 16 rows x 128 cols
#pragma unroll
        for (int kt = 0; kt < 4; kt++) {
            uint32_t P4[4];
            LDSM4(P4, sbase + FQOFF + psw(arow, kt * 2 + asel));
            int trow = kt * 16 + trow_b;
#pragma unroll
            for (int ng = 0; ng < 8; ng++) {
                int c0 = cg * 128 + ng * 16;
                uint32_t kcb = sbase + (c0 >> 6) * 8192;
                uint32_t bo = psw(trow, ((c0 & 63) >> 3) + tsel);
                uint32_t V4[4];
                LDSM4T(V4, kcb + bo);
                MMA16816(oacc[ng*2],   P4, V4[0], V4[1]);
                MMA16816(oacc[ng*2+1], P4, V4[2], V4[3]);
            }
        }
        __syncthreads();   // AV reads done before next j overwrites K/Q/P
    }

    // finalize
    float* Larr = reinterpret_cast<float*>(smem);
    if ((lane & 3) == 0) {
        Larr[cg * 64 + prow0] = lsum0;
        Larr[cg * 64 + prow1] = lsum1;
    }
    __syncthreads();
    float inv0 = 1.f / (Larr[prow0] + Larr[64 + prow0] + Larr[128 + prow0] + Larr[192 + prow0]);
    float inv1 = 1.f / (Larr[prow1] + Larr[64 + prow1] + Larr[128 + prow1] + Larr[192 + prow1]);

    hlf* poh = Oh + (long long)bh * CS * CKVLR + (long long)q0 * CKVLR;
    hlf* pol = Ol + (long long)bh * CS * CKVLR + (long long)q0 * CKVLR;
#pragma unroll
    for (int ng = 0; ng < 8; ng++) {
#pragma unroll
        for (int h8 = 0; h8 < 2; h8++) {
            int c = cg * 128 + ng * 16 + h8 * 8 + (lane & 3) * 2;
            float* a = oacc[ng * 2 + h8];
            long long o0 = (long long)prow0 * CKVLR + c;
            long long o1 = (long long)prow1 * CKVLR + c;
            split2x2(a[0] * inv0, a[1] * inv0, poh + o0, pol + o0);
            split2x2(a[2] * inv1, a[3] * inv1, poh + o1, pol + o1);
        }
    }
}

// ---------------- conversions ----------------
__global__ void cvt_split_kernel(const float* __restrict__ s, hlf* __restrict__ hi, hlf* __restrict__ lo, long long n)
{
    long long n4 = n >> 2;
    long long i = (long long)blockIdx.x * blockDim.x + threadIdx.x;
    long long st = (long long)gridDim.x * blockDim.x;
    for (; i < n4; i += st) {
        float4 v = reinterpret_cast<const float4*>(s)[i];
        hlf h[4], l[4];
        h[0] = __float2half_rn(v.x); l[0] = __float2half_rn(v.x - __half2float(h[0]));
        h[1] = __float2half_rn(v.y); l[1] = __float2half_rn(v.y - __half2float(h[1]));
        h[2] = __float2half_rn(v.z); l[2] = __float2half_rn(v.z - __half2float(h[2]));
        h[3] = __float2half_rn(v.w); l[3] = __float2half_rn(v.w - __half2float(h[3]));
        *reinterpret_cast<uint2*>(hi + i * 4) = *reinterpret_cast<uint2*>(h);
        *reinterpret_cast<uint2*>(lo + i * 4) = *reinterpret_cast<uint2*>(l);
    }
}

__global__ void cvt_half_kernel(const float* __restrict__ s, hlf* __restrict__ d, long long n)
{
    long long n4 = n >> 2;
    long long i = (long long)blockIdx.x * blockDim.x + threadIdx.x;
    long long st = (long long)gridDim.x * blockDim.x;
    for (; i < n4; i += st) {
        float4 v = reinterpret_cast<const float4*>(s)[i];
        hlf h[4];
        h[0] = __float2half_rn(v.x); h[1] = __float2half_rn(v.y);
        h[2] = __float2half_rn(v.z); h[3] = __float2half_rn(v.w);
        *reinterpret_cast<uint2*>(d + i * 4) = *reinterpret_cast<uint2*>(h);
    }
}

// qab [h][c][d], oabT [h][d][c] from kv_b_W [c, h, 2, d] (single fp16)
__global__ void extract_kernel(const float* __restrict__ kvb,
                               hlf* __restrict__ qab, hlf* __restrict__ oabt)
{
    long long n = (long long)CNH * CKVLR * CHD;
    long long i = (long long)blockIdx.x * blockDim.x + threadIdx.x;
    long long st = (long long)gridDim.x * blockDim.x;
    for (; i < n; i += st) {
        {
            int c = (int)(i & 511);
            int d = (int)((i >> 9) & 127);
            int h = (int)(i >> 16);
            oabt[i] = __float2half_rn(kvb[(((long long)c * CNH + h) * 2 + 1) * CHD + d]);
        }
        {
            int d = (int)(i & 127);
            int c = (int)((i >> 7) & 511);
            int h = (int)(i >> 16);
            qab[i] = __float2half_rn(kvb[(((long long)c * CNH + h) * 2) * CHD + d]);
        }
    }
}

// ---------------- RMSNorm ----------------
__global__ __launch_bounds__(256) void rms_kernel(const float* __restrict__ x, const float* __restrict__ w,
                                                  hlf* __restrict__ hi, hlf* __restrict__ lo)
{
    __shared__ float red[8];
    size_t row = blockIdx.x;
    const float* p = x + row * CQLR;
    int tid = threadIdx.x;
    float s = 0.f;
    for (int i = tid; i < CQLR; i += 256) { float v = p[i]; s += v * v; }
#pragma unroll
    for (int o = 16; o; o >>= 1) s += __shfl_xor_sync(~0u, s, o);
    if ((tid & 31) == 0) red[tid >> 5] = s;
    __syncthreads();
    float tot = 0.f;
#pragma unroll
    for (int i = 0; i < 8; i++) tot += red[i];
    float r = rsqrtf(tot + 1e-6f);
    hlf* ph = hi + row * CQLR;
    hlf* pl = lo + row * CQLR;
    for (int i = tid; i < CQLR; i += 256) split2(p[i] * r * w[i], ph + i, pl + i);
}

// ---------------- RoPE ----------------
__device__ __forceinline__ void rope_cs(int s, int i, float& c, float& sn)
{
    double invf = pow(10000.0, -(double)(2 * i) / 128.0);
    double ang = (double)s * invf;
    c = (float)cos(ang);
    sn = (float)sin(ang);
}

__global__ void rope_k_kernel(float* __restrict__ ckv)
{
    int idx = blockIdx.x * blockDim.x + threadIdx.x;
    if (idx >= CB * CS * 64) return;
    int i = idx & 63;
    int row = idx >> 6;
    int s = row & (CS - 1);
    float c, sn; rope_cs(s, i, c, sn);
    float* p = ckv + (size_t)row * CCAT + CKVLR;
    float x1 = p[i], x2 = p[i + 64];
    p[i]      = x1 * c - x2 * sn;
    p[i + 64] = x2 * c + x1 * sn;
}

// q_pe: read split q, rope, write SINGLE fp16 into qc cols 512..639
__global__ void rope_q_kernel(const hlf* __restrict__ qh, const hlf* __restrict__ ql,
                              hlf* __restrict__ qc)
{
    int idx = blockIdx.x * blockDim.x + threadIdx.x;
    if (idx >= CB * CS * CNH * 64) return;
    int i = idx & 63;
    int h = (idx >> 6) & 15;
    int row = idx >> 10;
    int s = row & (CS - 1);
    int b = row >> 11;
    float c, sn; rope_cs(s, i, c, sn);
    long long so = (long long)row * (CNH * CQHD) + h * CQHD + CHD;
    float x1 = __half2float(qh[so + i])      + __half2float(ql[so + i]);
    float x2 = __half2float(qh[so + i + 64]) + __half2float(ql[so + i + 64]);
    long long dofs = ((long long)(b * CNH + h) * CS + s) * CCAT + CKVLR;
    qc[dofs + i]      = __float2half_rn(x1 * c - x2 * sn);
    qc[dofs + i + 64] = __float2half_rn(x2 * c + x1 * sn);
}

// ---------------- launch ----------------
extern "C" void kernel_launch(void* const* d_in, const int* in_sizes, int n_in,
                              void* d_out, int out_size)
{
    const float* hidden = (const float*)d_in[0];
    const float* mask   = (const float*)d_in[1];
    const float* q_a_W  = (const float*)d_in[2];
    const float* q_a_b  = (const float*)d_in[3];
    const float* q_a_nw = (const float*)d_in[4];
    const float* q_b_W  = (const float*)d_in[5];
    const float* kv_a_W = (const float*)d_in[6];
    const float* kv_b_W = (const float*)d_in[7];
    const float* o_W    = (const float*)d_in[8];
    float* out = (float*)d_out;

    void* p;
#define SYM(v, g) cudaGetSymbolAddress(&p, g); auto* v = (decltype(&g[0]))p
    SYM(qa, g_qa);     SYM(ckv, g_ckv);
    SYM(hidh, g_hid_h); SYM(hidl, g_hid_l);
    SYM(qaw, g_qaw);   SYM(qbw, g_qbw);
    SYM(kvaw, g_kvaw); SYM(ow, g_ow);
    SYM(qanh, g_qan_h); SYM(qanl, g_qan_l);
    SYM(qsh, g_qs_h);   SYM(qsl, g_qs_l);
    SYM(qab, g_qab);   SYM(oabt, g_oabt);
    SYM(qc, g_qc);
    SYM(ckvf, g_ckvf);
    SYM(olh, g_ol_h);   SYM(oll, g_ol_l);
    SYM(ohh, g_oh_h);   SYM(ohl, g_oh_l);
#undef SYM

    constexpr int SMEM128 = STAGES * (2 * ASZ + 128 * GBK * 2);  //  96 KB
    constexpr int SMEM256 = STAGES * (2 * ASZ + 256 * GBK * 2);  // 128 KB
    cudaFuncSetAttribute(mma_gemm<128>, cudaFuncAttributeMaxDynamicSharedMemorySize, SMEM128);
    cudaFuncSetAttribute(mma_gemm<256>, cudaFuncAttributeMaxDynamicSharedMemorySize, SMEM256);
    cudaFuncSetAttribute(flash_kernel, cudaFuncAttributeMaxDynamicSharedMemorySize, FSMEM);

    const long long LS = CS;
    const int CVG = 2048;

    cvt_split_kernel<<<CVG, 256>>>(hidden, hidh, hidl, (long long)CBS * CHID);
    cvt_half_kernel<<<CVG, 256>>>(q_a_W, qaw, (long long)CQLR * CHID);
    cvt_half_kernel<<<CVG, 256>>>(kv_a_W, kvaw, (long long)CCAT * CHID);

    // q_a = hidden @ q_a_W^T + bias   [4096,1536] K=2048, fp32 out
    mma_gemm<256><<<dim3(CQLR / 256, CBS / 128, 1), 512, SMEM256>>>(
        hidh, hidl, CHID, 0, 0, qaw, CHID, 0, 0,
        qa, nullptr, nullptr, CQLR, 0, 0, q_a_b, 1.f, CHID, 1);

    // ckv = hidden @ kv_a_W^T  [4096,640] K=2048, fp32 out
    mma_gemm<128><<<dim3(CCAT / 128, CBS / 128, 1), 512, SMEM128>>>(
        hidh, hidl, CHID, 0, 0, kvaw, CHID, 0, 0,
        ckv, nullptr, nullptr, CCAT, 0, 0, nullptr, 1.f, CHID, 1);

    rms_kernel<<<CBS, 256>>>(qa, q_a_nw, qanh, qanl);
    cvt_half_kernel<<<CVG, 256>>>(q_b_W, qbw, (long long)CNH * CQHD * CQLR);

    // q = qa_norm @ q_b_W^T  [4096,4096] K=1536, split out
    mma_gemm<256><<<dim3((CNH * CQHD) / 256, CBS / 128, 1), 512, SMEM256>>>(
        qanh, qanl, CQLR, 0, 0, qbw, CQLR, 0, 0,
        nullptr, qsh, qsl, CNH * CQHD, 0, 0, nullptr, 1.f, CQLR, 1);

    extract_kernel<<<CVG, 256>>>(kv_b_W, qab, oabt);
    rope_k_kernel<<<(CB * CS * 64) / 256, 256>>>(ckv);
    rope_q_kernel<<<(CB * CS * CNH * 64) / 256, 256>>>(qsh, qsl, qc);

    // q_lat -> qc cols [0,512)  K=128, Z=32, single fp16 out
    mma_gemm<256><<<dim3(CKVLR / 256, CS / 128, CB * CNH), 512, SMEM256>>>(
        qsh, qsl, CNH * CQHD, LS * CNH * CQHD, CQHD,
        qab, CHD, 0, (long long)CKVLR * CHD,
        nullptr, qc, nullptr, CCAT, LS * CNH * CCAT, LS * CCAT,
        nullptr, 1.f, CHD, CNH);

    // keys/V single fp16 (K-major)
    cvt_half_kernel<<<CVG, 256>>>(ckv, ckvf, (long long)CBS * CCAT);

    // fused attention: scores + softmax + AV -> olat split
    float scale = 1.f / sqrtf((float)CCAT);
    flash_kernel<<<dim3(CS / 64, CB * CNH), 512, FSMEM>>>(
        qc, ckvf, mask, olh, oll, scale);

    cvt_half_kernel<<<CVG, 256>>>(o_W, ow, (long long)CHID * CNH * CHD);

    // out_head = olat . o_absorb^T -> [b,s,h*128+d]  K=512, N=128, Z=32, split out
    mma_gemm<128><<<dim3(1, CS / 128, CB * CNH), 512, SMEM128>>>(
        olh, oll, CKVLR, LS * CNH * CKVLR, LS * CKVLR,
        oabt, CKVLR, 0, (long long)CHD * CKVLR,
        nullptr, ohh, ohl, CNH * CHD, LS * (long long)CNH * CHD, CHD,
        nullptr, 1.f, CKVLR, CNH);

    // final = ohead @ o_W^T  [4096,2048] K=2048, fp32 out
    mma_gemm<256><<<dim3(CHID / 256, CBS / 128, 1), 512, SMEM256>>>(
        ohh, ohl, CNH * CHD, 0, 0, ow, CNH * CHD, 0, 0,
        out, nullptr, nullptr, CHID, 0, 0, nullptr, 1.f, CNH * CHD, 1);
}

// round 11
// speedup vs baseline: 1.7502x; 1.1477x over previous
#include <cuda_runtime.h>
#include <cuda_fp16.h>
#include <math.h>
#include <stdint.h>

// ---------------- problem constants ----------------
#define CB   2
#define CS   2048
#define CHID 2048
#define CNH  16
#define CHD  128
#define CQLR 1536
#define CKVLR 512
#define CBS  (CB*CS)          // 4096
#define CCAT (CKVLR+CHD)      // 640
#define CQHD (2*CHD)          // 256

typedef __half hlf;

// ---------------- device scratch (all single fp16 now) ----------------
static __device__ __align__(256) float g_qa[(size_t)CBS*CQLR];
static __device__ __align__(256) float g_ckv[(size_t)CBS*CCAT];

static __device__ __align__(256) hlf g_hid[(size_t)CBS*CHID];
static __device__ __align__(256) hlf g_qan[(size_t)CBS*CQLR];
static __device__ __align__(256) hlf g_qs[(size_t)CBS*CNH*CQHD];
static __device__ __align__(256) hlf g_ol[(size_t)CB*CNH*CS*CKVLR];
static __device__ __align__(256) hlf g_oh[(size_t)CBS*CNH*CHD];
static __device__ __align__(256) hlf g_qc[(size_t)CB*CNH*CS*CCAT];
static __device__ __align__(256) hlf g_qaw[(size_t)CQLR*CHID];
static __device__ __align__(256) hlf g_qbw[(size_t)CNH*CQHD*CQLR];
static __device__ __align__(256) hlf g_kvaw[(size_t)CCAT*CHID];
static __device__ __align__(256) hlf g_ow[(size_t)CHID*CNH*CHD];
static __device__ __align__(256) hlf g_qab[(size_t)CNH*CKVLR*CHD];     // [h][c][d]
static __device__ __align__(256) hlf g_oabt[(size_t)CNH*CHD*CKVLR];    // [h][d][c]
static __device__ __align__(256) hlf g_ckvf[(size_t)CBS*CCAT];         // keys/V, K-major

// ---------------- asm helpers (sm_80-portable) ----------------
__device__ __forceinline__ uint32_t smem_u32(const void* p) {
    uint32_t a;
    asm("{ .reg .u64 t; cvta.to.shared.u64 t, %1; cvt.u32.u64 %0, t; }" : "=r"(a) : "l"(p));
    return a;
}
#define CP_ASYNC16(dst, src) \
    asm volatile("cp.async.cg.shared.global [%0], [%1], 16;" :: "r"(dst), "l"(src) : "memory")
#define CP_COMMIT() asm volatile("cp.async.commit_group;" ::: "memory")
#define CP_WAIT(n)  asm volatile("cp.async.wait_group %0;" :: "n"(n) : "memory")

#define LDSM4(r, addr) \
    asm volatile("ldmatrix.sync.aligned.m8n8.x4.shared.b16 {%0,%1,%2,%3}, [%4];" \
        : "=r"((r)[0]),"=r"((r)[1]),"=r"((r)[2]),"=r"((r)[3]) : "r"(addr))
#define LDSM4T(r, addr) \
    asm volatile("ldmatrix.sync.aligned.m8n8.x4.trans.shared.b16 {%0,%1,%2,%3}, [%4];" \
        : "=r"((r)[0]),"=r"((r)[1]),"=r"((r)[2]),"=r"((r)[3]) : "r"(addr))

#define MMA16816(d, a, b0, b1) \
    asm volatile("mma.sync.aligned.m16n8k16.row.col.f32.f16.f16.f32 " \
        "{%0,%1,%2,%3},{%4,%5,%6,%7},{%8,%9},{%0,%1,%2,%3};" \
        : "+f"((d)[0]),"+f"((d)[1]),"+f"((d)[2]),"+f"((d)[3]) \
        : "r"((a)[0]),"r"((a)[1]),"r"((a)[2]),"r"((a)[3]), "r"(b0),"r"(b1))

__device__ __forceinline__ void store_h2(float v0, float v1, hlf* hp) {
    __half2 hh; hh.x = __float2half_rn(v0); hh.y = __float2half_rn(v1);
    *reinterpret_cast<__half2*>(hp) = hh;
}

// ---------------- fp16 MMA GEMM (512 threads, 16 warps) ----------------
// C = alpha*A@B^T (+bias). Out: fp32 (C) or single fp16 (Chi).
static constexpr int GBK = 32, STAGES = 4;
static constexpr int ASZ = 128 * GBK * 2;   // 8192 B

__device__ __forceinline__ uint32_t swz(int row, int ch) {
    return (uint32_t)(row * 64 + ((ch ^ ((row >> 1) & 3)) * 16));
}

template<int BN>
__global__ __launch_bounds__(512, 1) void mma_gemm(
    const hlf* __restrict__ A, int lda, long long aO, long long aI,
    const hlf* __restrict__ B, int ldb, long long bO, long long bI,
    float* __restrict__ C, hlf* __restrict__ Chi,
    int ldc, long long cO, long long cI,
    const float* __restrict__ bias, float alpha, int K, int zInner)
{
    constexpr int JG = BN / 64;
    constexpr int BSZ = BN * GBK * 2;
    constexpr int STAGE_B = ASZ + BSZ;

    extern __shared__ char smem_raw[];
    uint32_t sbase = smem_u32(smem_raw);

    int tid = threadIdx.x, wid = tid >> 5, lane = tid & 31;
    int z = blockIdx.z, zo = z / zInner, zi = z - zo * zInner;
    A += zo * aO + zi * aI;
    B += zo * bO + zi * bI;
    if (C)   C   += zo * cO + zi * cI;
    if (Chi) Chi += zo * cO + zi * cI;

    int bm = blockIdx.y * 128, bn = blockIdx.x * BN;
    int wm = (wid & 3) * 32;
    int wn = (wid >> 2) * (BN / 4);

    const hlf* pA = A + (long long)bm * lda;
    const hlf* pB = B + (long long)bn * ldb;

    float acc[2][2 * JG][4];
#pragma unroll
    for (int t = 0; t < 2; t++)
#pragma unroll
        for (int j = 0; j < 2 * JG; j++)
#pragma unroll
            for (int q = 0; q < 4; q++) acc[t][j][q] = 0.f;

    int nk = K / GBK;

#define ISSUE(stage_) do { \
    int st_ = (stage_) % STAGES; \
    uint32_t sb_ = sbase + st_ * STAGE_B; \
    long long k0_ = (long long)(stage_) * GBK; \
    { int r = tid >> 2, ch = tid & 3; \
      uint32_t so = swz(r, ch); \
      CP_ASYNC16(sb_ + so, pA + (long long)r * lda + k0_ + ch * 8); } \
    _Pragma("unroll") \
    for (int u = 0; u < BN / 128; u++) { \
        int idx = u * 512 + tid; int r = idx >> 2, ch = idx & 3; \
        uint32_t so = swz(r, ch); \
        CP_ASYNC16(sb_ + ASZ + so, pB + (long long)r * ldb + k0_ + ch * 8); \
    } \
} while (0)

    for (int s = 0; s < STAGES - 1; s++) {
        if (s < nk) ISSUE(s);
        CP_COMMIT();
    }

    int a_row = (lane & 15);
    int a_sel = lane >> 4;
    int b_row = (lane & 7) + ((lane >> 4) * 8);
    int b_sel = (lane >> 3) & 1;

    for (int i = 0; i < nk; i++) {
        CP_WAIT(STAGES - 2);
        __syncthreads();
        if (i + STAGES - 1 < nk) ISSUE(i + STAGES - 1);
        CP_COMMIT();

        uint32_t sb = sbase + (i % STAGES) * STAGE_B;

#pragma unroll
        for (int kh = 0; kh < 2; kh++) {
            uint32_t Af[2][4];
#pragma unroll
            for (int t = 0; t < 2; t++) {
                int row = wm + t * 16 + a_row;
                LDSM4(Af[t], sb + swz(row, 2 * kh + a_sel));
            }
#pragma unroll
            for (int jg = 0; jg < JG; jg++) {
                int row = wn + jg * 16 + b_row;
                uint32_t B4[4];
                LDSM4(B4, sb + ASZ + swz(row, 2 * kh + b_sel));
#pragma unroll
                for (int t = 0; t < 2; t++) {
                    MMA16816(acc[t][2*jg],   Af[t], B4[0], B4[1]);
                    MMA16816(acc[t][2*jg+1], Af[t], B4[2], B4[3]);
                }
            }
        }
    }
#undef ISSUE

#pragma unroll
    for (int t = 0; t < 2; t++) {
        int r0 = bm + wm + t * 16 + (lane >> 2);
#pragma unroll
        for (int j = 0; j < 2 * JG; j++) {
            int col = bn + wn + j * 8 + (lane & 3) * 2;
            float v0 = acc[t][j][0] * alpha;
            float v1 = acc[t][j][1] * alpha;
            float v2 = acc[t][j][2] * alpha;
            float v3 = acc[t][j][3] * alpha;
            if (bias) { v0 += bias[col]; v1 += bias[col + 1]; v2 += bias[col]; v3 += bias[col + 1]; }
            long long o0 = (long long)r0 * ldc + col;
            long long o1 = (long long)(r0 + 8) * ldc + col;
            if (Chi) {
                store_h2(v0, v1, Chi + o0);
                store_h2(v2, v3, Chi + o1);
            } else {
                C[o0] = v0; C[o0 + 1] = v1;
                C[o1] = v2; C[o1 + 1] = v3;
            }
        }
    }
}

// ---------------- fused flash attention (512 threads, pure fp16) ----------------
// CTA: 64 q rows, one (b,h). K' tile (64 keys x 640 fp16) resident;
// V = K'[:, :512] via ldmatrix.trans. Q/P single fp16. Max-free softmax.
// smem: K chunks 10 x 8KB = 80KB @0; Q ring 4 x 8KB @81920 (P overlays slot 0).
static constexpr int FQOFF = 81920;
static constexpr int FSMEM = 81920 + 4 * 8192;   // 112 KB

__device__ __forceinline__ uint32_t psw(int row, int ch) {
    return (uint32_t)(row * 128 + ((ch ^ (row & 7)) << 4));
}

__device__ __forceinline__ void fissue(uint32_t sbase, int kc,
    const hlf* pQ, const hlf* pKj, uint32_t soff, long long goff)
{
    uint32_t kb = sbase + kc * 8192;
    uint32_t qb = sbase + FQOFF + (kc & 3) * 8192;
    long long co = (long long)kc * 64;
    CP_ASYNC16(kb + soff, pKj + goff + co);
    CP_ASYNC16(qb + soff, pQ + goff + co);
}

__global__ __launch_bounds__(512, 1) void flash_kernel(
    const hlf* __restrict__ Q,
    const hlf* __restrict__ Kf,
    const float* __restrict__ mask,
    hlf* __restrict__ O,
    float scale)
{
    extern __shared__ char smem[];
    uint32_t sbase = smem_u32(smem);
    int tid = threadIdx.x, wid = tid >> 5, lane = tid & 31;
    int mg = wid & 3, cg = wid >> 2;
    int bh = blockIdx.y, b = bh >> 4;
    int q0 = blockIdx.x * 64;

    const hlf* pQ = Q + (long long)bh * CS * CCAT + (long long)q0 * CCAT;
    const hlf* pK = Kf + (long long)b * CS * CCAT;

    int lrow = tid >> 3, lch = tid & 7;
    uint32_t soff = psw(lrow, lch);
    long long goff = (long long)lrow * CCAT + lch * 8;

    int arow = mg * 16 + (lane & 15);
    int asel = lane >> 4;
    int brow = cg * 16 + (lane & 7) + ((lane >> 4) * 8);
    int bsel = (lane >> 3) & 1;
    int trow_b = (lane & 7) + (((lane >> 3) & 1) * 8);
    int tsel = lane >> 4;

    float oacc[16][4];
#pragma unroll
    for (int i = 0; i < 16; i++)
#pragma unroll
        for (int q = 0; q < 4; q++) oacc[i][q] = 0.f;
    float lsum0 = 0.f, lsum1 = 0.f;

    int prow0 = mg * 16 + (lane >> 2), prow1 = prow0 + 8;

    for (int j = 0; j < 32; j++) {
        const hlf* pKj = pK + (long long)j * 64 * CCAT;

        fissue(sbase, 0, pQ, pKj, soff, goff); CP_COMMIT();
        fissue(sbase, 1, pQ, pKj, soff, goff); CP_COMMIT();
        fissue(sbase, 2, pQ, pKj, soff, goff); CP_COMMIT();

        float sacc[2][4];
#pragma unroll
        for (int n = 0; n < 2; n++)
#pragma unroll
            for (int q = 0; q < 4; q++) sacc[n][q] = 0.f;

        for (int kc = 0; kc < 10; kc++) {
            CP_WAIT(2);
            __syncthreads();
            if (kc + 3 < 10) fissue(sbase, kc + 3, pQ, pKj, soff, goff);
            CP_COMMIT();
            uint32_t kb = sbase + kc * 8192;
            uint32_t qb = sbase + FQOFF + (kc & 3) * 8192;
#pragma unroll
            for (int kk = 0; kk < 4; kk++) {
                uint32_t A4[4];
                LDSM4(A4, qb + psw(arow, kk * 2 + asel));
                uint32_t B4[4];
                LDSM4(B4, kb + psw(brow, kk * 2 + bsel));
                MMA16816(sacc[0], A4, B4[0], B4[1]);
                MMA16816(sacc[1], A4, B4[2], B4[3]);
            }
        }
        // no sync needed: P overlays Q slot 0; last slot-0 reader (kc=8) is
        // fenced by kc=9's top-of-loop __syncthreads.

        // softmax (max-free) + P fp16 write
        {
            const float* mrow = mask + (long long)b * CS * CS
                              + (long long)(q0 + prow0) * CS + j * 64 + cg * 16 + (lane & 3) * 2;
            float ladd0 = 0.f, ladd1 = 0.f;
#pragma unroll
            for (int nn = 0; nn < 2; nn++) {
                float2 m0 = *reinterpret_cast<const float2*>(mrow + nn * 8);
                float2 m1 = *reinterpret_cast<const float2*>(mrow + nn * 8 + 8 * CS);
                float p0 = __expf(sacc[nn][0] * scale + m0.x);
                float p1 = __expf(sacc[nn][1] * scale + m0.y);
                float p2 = __expf(sacc[nn][2] * scale + m1.x);
                float p3 = __expf(sacc[nn][3] * scale + m1.y);
                ladd0 += p0 + p1; ladd1 += p2 + p3;
                int col = cg * 16 + nn * 8 + (lane & 3) * 2;
                uint32_t o0 = (uint32_t)(prow0 * 128 + ((((col >> 3)) ^ (prow0 & 7)) << 4) + (col & 7) * 2);
                uint32_t o1 = (uint32_t)(prow1 * 128 + ((((col >> 3)) ^ (prow1 & 7)) << 4) + (col & 7) * 2);
                store_h2(p0, p1, (hlf*)(smem + FQOFF + o0));
                store_h2(p2, p3, (hlf*)(smem + FQOFF + o1));
            }
            ladd0 += __shfl_xor_sync(~0u, ladd0, 1); ladd0 += __shfl_xor_sync(~0u, ladd0, 2);
            ladd1 += __shfl_xor_sync(~0u, ladd1, 1); ladd1 += __shfl_xor_sync(~0u, ladd1, 2);
            lsum0 += ladd0; lsum1 += ladd1;
        }
        __syncthreads();   // P visible to all warps

        // AV: O += P*V; warp covers 16 rows x 128 cols
#pragma unroll
        for (int kt = 0; kt < 4; kt++) {
            uint32_t P4[4];
            LDSM4(P4, sbase + FQOFF + psw(arow, kt * 2 + asel));
            int trow = kt * 16 + trow_b;
#pragma unroll
            for (int ng = 0; ng < 8; ng++) {
                int c0 = cg * 128 + ng * 16;
                uint32_t kcb = sbase + (c0 >> 6) * 8192;
                uint32_t bo = psw(trow, ((c0 & 63) >> 3) + tsel);
                uint32_t V4[4];
                LDSM4T(V4, kcb + bo);
                MMA16816(oacc[ng*2],   P4, V4[0], V4[1]);
                MMA16816(oacc[ng*2+1], P4, V4[2], V4[3]);
            }
        }
        __syncthreads();   // AV reads done before next j overwrites K/Q/P
    }

    // finalize
    float* Larr = reinterpret_cast<float*>(smem);
    if ((lane & 3) == 0) {
        Larr[cg * 64 + prow0] = lsum0;
        Larr[cg * 64 + prow1] = lsum1;
    }
    __syncthreads();
    float inv0 = 1.f / (Larr[prow0] + Larr[64 + prow0] + Larr[128 + prow0] + Larr[192 + prow0]);
    float inv1 = 1.f / (Larr[prow1] + Larr[64 + prow1] + Larr[128 + prow1] + Larr[192 + prow1]);

    hlf* po = O + (long long)bh * CS * CKVLR + (long long)q0 * CKVLR;
#pragma unroll
    for (int ng = 0; ng < 8; ng++) {
#pragma unroll
        for (int h8 = 0; h8 < 2; h8++) {
            int c = cg * 128 + ng * 16 + h8 * 8 + (lane & 3) * 2;
            float* a = oacc[ng * 2 + h8];
            store_h2(a[0] * inv0, a[1] * inv0, po + (long long)prow0 * CKVLR + c);
            store_h2(a[2] * inv1, a[3] * inv1, po + (long long)prow1 * CKVLR + c);
        }
    }
}

// ---------------- conversions ----------------
__global__ void cvt_half_kernel(const float* __restrict__ s, hlf* __restrict__ d, long long n)
{
    long long n4 = n >> 2;
    long long i = (long long)blockIdx.x * blockDim.x + threadIdx.x;
    long long st = (long long)gridDim.x * blockDim.x;
    for (; i < n4; i += st) {
        float4 v = reinterpret_cast<const float4*>(s)[i];
        hlf h[4];
        h[0] = __float2half_rn(v.x); h[1] = __float2half_rn(v.y);
        h[2] = __float2half_rn(v.z); h[3] = __float2half_rn(v.w);
        *reinterpret_cast<uint2*>(d + i * 4) = *reinterpret_cast<uint2*>(h);
    }
}

// qab [h][c][d], oabT [h][d][c] from kv_b_W [c, h, 2, d] (single fp16)
__global__ void extract_kernel(const float* __restrict__ kvb,
                               hlf* __restrict__ qab, hlf* __restrict__ oabt)
{
    long long n = (long long)CNH * CKVLR * CHD;
    long long i = (long long)blockIdx.x * blockDim.x + threadIdx.x;
    long long st = (long long)gridDim.x * blockDim.x;
    for (; i < n; i += st) {
        {
            int c = (int)(i & 511);
            int d = (int)((i >> 9) & 127);
            int h = (int)(i >> 16);
            oabt[i] = __float2half_rn(kvb[(((long long)c * CNH + h) * 2 + 1) * CHD + d]);
        }
        {
            int d = (int)(i & 127);
            int c = (int)((i >> 7) & 511);
            int h = (int)(i >> 16);
            qab[i] = __float2half_rn(kvb[(((long long)c * CNH + h) * 2) * CHD + d]);
        }
    }
}

// ---------------- RMSNorm (fp32 in, fp16 out) ----------------
__global__ __launch_bounds__(256) void rms_kernel(const float* __restrict__ x, const float* __restrict__ w,
                                                  hlf* __restrict__ o)
{
    __shared__ float red[8];
    size_t row = blockIdx.x;
    const float* p = x + row * CQLR;
    int tid = threadIdx.x;
    float s = 0.f;
    for (int i = tid; i < CQLR; i += 256) { float v = p[i]; s += v * v; }
#pragma unroll
    for (int off = 16; off; off >>= 1) s += __shfl_xor_sync(~0u, s, off);
    if ((tid & 31) == 0) red[tid >> 5] = s;
    __syncthreads();
    float tot = 0.f;
#pragma unroll
    for (int i = 0; i < 8; i++) tot += red[i];
    float r = rsqrtf(tot + 1e-6f);
    hlf* po = o + row * CQLR;
    for (int i = tid; i < CQLR; i += 256) po[i] = __float2half_rn(p[i] * r * w[i]);
}

// ---------------- RoPE ----------------
__device__ __forceinline__ void rope_cs(int s, int i, float& c, float& sn)
{
    double invf = pow(10000.0, -(double)(2 * i) / 128.0);
    double ang = (double)s * invf;
    c = (float)cos(ang);
    sn = (float)sin(ang);
}

__global__ void rope_k_kernel(float* __restrict__ ckv)
{
    int idx = blockIdx.x * blockDim.x + threadIdx.x;
    if (idx >= CB * CS * 64) return;
    int i = idx & 63;
    int row = idx >> 6;
    int s = row & (CS - 1);
    float c, sn; rope_cs(s, i, c, sn);
    float* p = ckv + (size_t)row * CCAT + CKVLR;
    float x1 = p[i], x2 = p[i + 64];
    p[i]      = x1 * c - x2 * sn;
    p[i + 64] = x2 * c + x1 * sn;
}

// q_pe: read single-fp16 q, rope, write single fp16 into qc cols 512..639
__global__ void rope_q_kernel(const hlf* __restrict__ q, hlf* __restrict__ qc)
{
    int idx = blockIdx.x * blockDim.x + threadIdx.x;
    if (idx >= CB * CS * CNH * 64) return;
    int i = idx & 63;
    int h = (idx >> 6) & 15;
    int row = idx >> 10;
    int s = row & (CS - 1);
    int b = row >> 11;
    float c, sn; rope_cs(s, i, c, sn);
    long long so = (long long)row * (CNH * CQHD) + h * CQHD + CHD;
    float x1 = __half2float(q[so + i]);
    float x2 = __half2float(q[so + i + 64]);
    long long dofs = ((long long)(b * CNH + h) * CS + s) * CCAT + CKVLR;
    qc[dofs + i]      = __float2half_rn(x1 * c - x2 * sn);
    qc[dofs + i + 64] = __float2half_rn(x2 * c + x1 * sn);
}

// ---------------- launch ----------------
extern "C" void kernel_launch(void* const* d_in, const int* in_sizes, int n_in,
                              void* d_out, int out_size)
{
    const float* hidden = (const float*)d_in[0];
    const float* mask   = (const float*)d_in[1];
    const float* q_a_W  = (const float*)d_in[2];
    const float* q_a_b  = (const float*)d_in[3];
    const float* q_a_nw = (const float*)d_in[4];
    const float* q_b_W  = (const float*)d_in[5];
    const float* kv_a_W = (const float*)d_in[6];
    const float* kv_b_W = (const float*)d_in[7];
    const float* o_W    = (const float*)d_in[8];
    float* out = (float*)d_out;

    void* p;
#define SYM(v, g) cudaGetSymbolAddress(&p, g); auto* v = (decltype(&g[0]))p
    SYM(qa, g_qa);     SYM(ckv, g_ckv);
    SYM(hid, g_hid);
    SYM(qaw, g_qaw);   SYM(qbw, g_qbw);
    SYM(kvaw, g_kvaw); SYM(ow, g_ow);
    SYM(qan, g_qan);   SYM(qs, g_qs);
    SYM(qab, g_qab);   SYM(oabt, g_oabt);
    SYM(qc, g_qc);     SYM(ckvf, g_ckvf);
    SYM(ol, g_ol);     SYM(oh, g_oh);
#undef SYM

    constexpr int SMEM128 = STAGES * (ASZ + 128 * GBK * 2);  // 64 KB
    constexpr int SMEM256 = STAGES * (ASZ + 256 * GBK * 2);  // 96 KB
    cudaFuncSetAttribute(mma_gemm<128>, cudaFuncAttributeMaxDynamicSharedMemorySize, SMEM128);
    cudaFuncSetAttribute(mma_gemm<256>, cudaFuncAttributeMaxDynamicSharedMemorySize, SMEM256);
    cudaFuncSetAttribute(flash_kernel, cudaFuncAttributeMaxDynamicSharedMemorySize, FSMEM);

    const long long LS = CS;
    const int CVG = 2048;

    cvt_half_kernel<<<CVG, 256>>>(hidden, hid, (long long)CBS * CHID);
    cvt_half_kernel<<<CVG, 256>>>(q_a_W, qaw, (long long)CQLR * CHID);
    cvt_half_kernel<<<CVG, 256>>>(kv_a_W, kvaw, (long long)CCAT * CHID);

    // q_a = hidden @ q_a_W^T + bias   [4096,1536] K=2048, fp32 out
    mma_gemm<256><<<dim3(CQLR / 256, CBS / 128, 1), 512, SMEM256>>>(
        hid, CHID, 0, 0, qaw, CHID, 0, 0,
        qa, nullptr, CQLR, 0, 0, q_a_b, 1.f, CHID, 1);

    // ckv = hidden @ kv_a_W^T  [4096,640] K=2048, fp32 out
    mma_gemm<128><<<dim3(CCAT / 128, CBS / 128, 1), 512, SMEM128>>>(
        hid, CHID, 0, 0, kvaw, CHID, 0, 0,
        ckv, nullptr, CCAT, 0, 0, nullptr, 1.f, CHID, 1);

    rms_kernel<<<CBS, 256>>>(qa, q_a_nw, qan);
    cvt_half_kernel<<<CVG, 256>>>(q_b_W, qbw, (long long)CNH * CQHD * CQLR);

    // q = qa_norm @ q_b_W^T  [4096,4096] K=1536, fp16 out
    mma_gemm<256><<<dim3((CNH * CQHD) / 256, CBS / 128, 1), 512, SMEM256>>>(
        qan, CQLR, 0, 0, qbw, CQLR, 0, 0,
        nullptr, qs, CNH * CQHD, 0, 0, nullptr, 1.f, CQLR, 1);

    extract_kernel<<<CVG, 256>>>(kv_b_W, qab, oabt);
    rope_k_kernel<<<(CB * CS * 64) / 256, 256>>>(ckv);
    rope_q_kernel<<<(CB * CS * CNH * 64) / 256, 256>>>(qs, qc);

    // q_lat -> qc cols [0,512)  K=128, Z=32, fp16 out
    mma_gemm<256><<<dim3(CKVLR / 256, CS / 128, CB * CNH), 512, SMEM256>>>(
        qs, CNH * CQHD, LS * CNH * CQHD, CQHD,
        qab, CHD, 0, (long long)CKVLR * CHD,
        nullptr, qc, CCAT, LS * CNH * CCAT, LS * CCAT,
        nullptr, 1.f, CHD, CNH);

    // keys/V single fp16 (K-major)
    cvt_half_kernel<<<CVG, 256>>>(ckv, ckvf, (long long)CBS * CCAT);

    // fused attention: scores + softmax + AV -> ol (fp16)
    float scale = 1.f / sqrtf((float)CCAT);
    flash_kernel<<<dim3(CS / 64, CB * CNH), 512, FSMEM>>>(
        qc, ckvf, mask, ol, scale);

    cvt_half_kernel<<<CVG, 256>>>(o_W, ow, (long long)CHID * CNH * CHD);

    // out_head = ol . o_absorb^T -> [b,s,h*128+d]  K=512, N=128, Z=32, fp16 out
    mma_gemm<128><<<dim3(1, CS / 128, CB * CNH), 512, SMEM128>>>(
        ol, CKVLR, LS * CNH * CKVLR, LS * CKVLR,
        oabt, CKVLR, 0, (long long)CHD * CKVLR,
        nullptr, oh, CNH * CHD, LS * (long long)CNH * CHD, CHD,
        nullptr, 1.f, CKVLR, CNH);

    // final = oh @ o_W^T  [4096,2048] K=2048, fp32 out
    mma_gemm<256><<<dim3(CHID / 256, CBS / 128, 1), 512, SMEM256>>>(
        oh, CNH * CHD, 0, 0, ow, CNH * CHD, 0, 0,
        out, nullptr, CHID, 0, 0, nullptr, 1.f, CNH * CHD, 1);
}

// round 12
// speedup vs baseline: 1.7630x; 1.0073x over previous
#include <cuda_runtime.h>
#include <cuda_fp16.h>
#include <math.h>
#include <stdint.h>

// ---------------- problem constants ----------------
#define CB   2
#define CS   2048
#define CHID 2048
#define CNH  16
#define CHD  128
#define CQLR 1536
#define CKVLR 512
#define CBS  (CB*CS)          // 4096
#define CCAT (CKVLR+CHD)      // 640
#define CQHD (2*CHD)          // 256

typedef __half hlf;

// ---------------- device scratch ----------------
static __device__ __align__(256) float g_qa[(size_t)CBS*CQLR];
static __device__ __align__(256) float g_ckv[(size_t)CBS*CCAT];

static __device__ __align__(256) hlf g_hid[(size_t)CBS*CHID];
static __device__ __align__(256) hlf g_qan[(size_t)CBS*CQLR];
static __device__ __align__(256) hlf g_qs[(size_t)CBS*CNH*CQHD];
static __device__ __align__(256) hlf g_ol[(size_t)CB*CNH*CS*CKVLR];
static __device__ __align__(256) hlf g_oh[(size_t)CBS*CNH*CHD];
static __device__ __align__(256) hlf g_qc[(size_t)CB*CNH*CS*CCAT];
static __device__ __align__(256) hlf g_qaw[(size_t)CQLR*CHID];
static __device__ __align__(256) hlf g_qbw[(size_t)CNH*CQHD*CQLR];
static __device__ __align__(256) hlf g_kvaw[(size_t)CCAT*CHID];
static __device__ __align__(256) hlf g_ow[(size_t)CHID*CNH*CHD];
static __device__ __align__(256) hlf g_qab[(size_t)CNH*CKVLR*CHD];     // [h][c][d]
static __device__ __align__(256) hlf g_oabt[(size_t)CNH*CHD*CKVLR];    // [h][d][c]
static __device__ __align__(256) hlf g_ckvf[(size_t)CBS*CCAT];         // keys/V, K-major

// ---------------- asm helpers (sm_80-portable) ----------------
__device__ __forceinline__ uint32_t smem_u32(const void* p) {
    uint32_t a;
    asm("{ .reg .u64 t; cvta.to.shared.u64 t, %1; cvt.u32.u64 %0, t; }" : "=r"(a) : "l"(p));
    return a;
}
#define CP_ASYNC16(dst, src) \
    asm volatile("cp.async.cg.shared.global [%0], [%1], 16;" :: "r"(dst), "l"(src) : "memory")
#define CP_COMMIT() asm volatile("cp.async.commit_group;" ::: "memory")
#define CP_WAIT(n)  asm volatile("cp.async.wait_group %0;" :: "n"(n) : "memory")

#define LDSM4(r, addr) \
    asm volatile("ldmatrix.sync.aligned.m8n8.x4.shared.b16 {%0,%1,%2,%3}, [%4];" \
        : "=r"((r)[0]),"=r"((r)[1]),"=r"((r)[2]),"=r"((r)[3]) : "r"(addr))
#define LDSM4T(r, addr) \
    asm volatile("ldmatrix.sync.aligned.m8n8.x4.trans.shared.b16 {%0,%1,%2,%3}, [%4];" \
        : "=r"((r)[0]),"=r"((r)[1]),"=r"((r)[2]),"=r"((r)[3]) : "r"(addr))

#define MMA16816(d, a, b0, b1) \
    asm volatile("mma.sync.aligned.m16n8k16.row.col.f32.f16.f16.f32 " \
        "{%0,%1,%2,%3},{%4,%5,%6,%7},{%8,%9},{%0,%1,%2,%3};" \
        : "+f"((d)[0]),"+f"((d)[1]),"+f"((d)[2]),"+f"((d)[3]) \
        : "r"((a)[0]),"r"((a)[1]),"r"((a)[2]),"r"((a)[3]), "r"(b0),"r"(b1))

__device__ __forceinline__ void store_h2(float v0, float v1, hlf* hp) {
    __half2 hh; hh.x = __float2half_rn(v0); hh.y = __float2half_rn(v1);
    *reinterpret_cast<__half2*>(hp) = hh;
}

// ---------------- fp16 MMA GEMM (512 threads, 16 warps) ----------------
static constexpr int GBK = 32, STAGES = 4;
static constexpr int ASZ = 128 * GBK * 2;   // 8192 B

__device__ __forceinline__ uint32_t swz(int row, int ch) {
    return (uint32_t)(row * 64 + ((ch ^ ((row >> 1) & 3)) * 16));
}

template<int BN>
__global__ __launch_bounds__(512, 1) void mma_gemm(
    const hlf* __restrict__ A, int lda, long long aO, long long aI,
    const hlf* __restrict__ B, int ldb, long long bO, long long bI,
    float* __restrict__ C, hlf* __restrict__ Chi,
    int ldc, long long cO, long long cI,
    const float* __restrict__ bias, float alpha, int K, int zInner)
{
    constexpr int JG = BN / 64;
    constexpr int BSZ = BN * GBK * 2;
    constexpr int STAGE_B = ASZ + BSZ;

    extern __shared__ char smem_raw[];
    uint32_t sbase = smem_u32(smem_raw);

    int tid = threadIdx.x, wid = tid >> 5, lane = tid & 31;
    int z = blockIdx.z, zo = z / zInner, zi = z - zo * zInner;
    A += zo * aO + zi * aI;
    B += zo * bO + zi * bI;
    if (C)   C   += zo * cO + zi * cI;
    if (Chi) Chi += zo * cO + zi * cI;

    int bm = blockIdx.y * 128, bn = blockIdx.x * BN;
    int wm = (wid & 3) * 32;
    int wn = (wid >> 2) * (BN / 4);

    const hlf* pA = A + (long long)bm * lda;
    const hlf* pB = B + (long long)bn * ldb;

    float acc[2][2 * JG][4];
#pragma unroll
    for (int t = 0; t < 2; t++)
#pragma unroll
        for (int j = 0; j < 2 * JG; j++)
#pragma unroll
            for (int q = 0; q < 4; q++) acc[t][j][q] = 0.f;

    int nk = K / GBK;

#define ISSUE(stage_) do { \
    int st_ = (stage_) % STAGES; \
    uint32_t sb_ = sbase + st_ * STAGE_B; \
    long long k0_ = (long long)(stage_) * GBK; \
    { int r = tid >> 2, ch = tid & 3; \
      uint32_t so = swz(r, ch); \
      CP_ASYNC16(sb_ + so, pA + (long long)r * lda + k0_ + ch * 8); } \
    _Pragma("unroll") \
    for (int u = 0; u < BN / 128; u++) { \
        int idx = u * 512 + tid; int r = idx >> 2, ch = idx & 3; \
        uint32_t so = swz(r, ch); \
        CP_ASYNC16(sb_ + ASZ + so, pB + (long long)r * ldb + k0_ + ch * 8); \
    } \
} while (0)

    for (int s = 0; s < STAGES - 1; s++) {
        if (s < nk) ISSUE(s);
        CP_COMMIT();
    }

    int a_row = (lane & 15);
    int a_sel = lane >> 4;
    int b_row = (lane & 7) + ((lane >> 4) * 8);
    int b_sel = (lane >> 3) & 1;

    for (int i = 0; i < nk; i++) {
        CP_WAIT(STAGES - 2);
        __syncthreads();
        if (i + STAGES - 1 < nk) ISSUE(i + STAGES - 1);
        CP_COMMIT();

        uint32_t sb = sbase + (i % STAGES) * STAGE_B;

#pragma unroll
        for (int kh = 0; kh < 2; kh++) {
            uint32_t Af[2][4];
#pragma unroll
            for (int t = 0; t < 2; t++) {
                int row = wm + t * 16 + a_row;
                LDSM4(Af[t], sb + swz(row, 2 * kh + a_sel));
            }
#pragma unroll
            for (int jg = 0; jg < JG; jg++) {
                int row = wn + jg * 16 + b_row;
                uint32_t B4[4];
                LDSM4(B4, sb + ASZ + swz(row, 2 * kh + b_sel));
#pragma unroll
                for (int t = 0; t < 2; t++) {
                    MMA16816(acc[t][2*jg],   Af[t], B4[0], B4[1]);
                    MMA16816(acc[t][2*jg+1], Af[t], B4[2], B4[3]);
                }
            }
        }
    }
#undef ISSUE

#pragma unroll
    for (int t = 0; t < 2; t++) {
        int r0 = bm + wm + t * 16 + (lane >> 2);
#pragma unroll
        for (int j = 0; j < 2 * JG; j++) {
            int col = bn + wn + j * 8 + (lane & 3) * 2;
            float v0 = acc[t][j][0] * alpha;
            float v1 = acc[t][j][1] * alpha;
            float v2 = acc[t][j][2] * alpha;
            float v3 = acc[t][j][3] * alpha;
            if (bias) { v0 += bias[col]; v1 += bias[col + 1]; v2 += bias[col]; v3 += bias[col + 1]; }
            long long o0 = (long long)r0 * ldc + col;
            long long o1 = (long long)(r0 + 8) * ldc + col;
            if (Chi) {
                store_h2(v0, v1, Chi + o0);
                store_h2(v2, v3, Chi + o1);
            } else {
                C[o0] = v0; C[o0 + 1] = v1;
                C[o1] = v2; C[o1 + 1] = v3;
            }
        }
    }
}

// ---------------- fused flash attention (512 threads, Q resident) ----------------
// CTA: 64 q rows, one (b,h). Q (64x640 fp16, 80KB) loaded ONCE and resident.
// K' tile (64 keys x 640 fp16, 80KB) streamed per j; V = K'[:, :512] via
// ldmatrix.trans. P in separate 8KB buffer. Max-free softmax.
// smem: K 10x8KB @0; Q 10x8KB @81920; P 8KB @163840.  Total 168KB.
static constexpr int FQOFF = 81920;
static constexpr int FPOFF = 163840;
static constexpr int FSMEM = 163840 + 8192;   // 168 KB

__device__ __forceinline__ uint32_t psw(int row, int ch) {
    return (uint32_t)(row * 128 + ((ch ^ (row & 7)) << 4));
}

__global__ __launch_bounds__(512, 1) void flash_kernel(
    const hlf* __restrict__ Q,
    const hlf* __restrict__ Kf,
    const float* __restrict__ mask,
    hlf* __restrict__ O,
    float scale)
{
    extern __shared__ char smem[];
    uint32_t sbase = smem_u32(smem);
    int tid = threadIdx.x, wid = tid >> 5, lane = tid & 31;
    int mg = wid & 3, cg = wid >> 2;
    int bh = blockIdx.y, b = bh >> 4;
    int q0 = blockIdx.x * 64;

    const hlf* pQ = Q + (long long)bh * CS * CCAT + (long long)q0 * CCAT;
    const hlf* pK = Kf + (long long)b * CS * CCAT;

    int lrow = tid >> 3, lch = tid & 7;
    uint32_t soff = psw(lrow, lch);
    long long goff = (long long)lrow * CCAT + lch * 8;

    int arow = mg * 16 + (lane & 15);
    int asel = lane >> 4;
    int brow = cg * 16 + (lane & 7) + ((lane >> 4) * 8);
    int bsel = (lane >> 3) & 1;
    int trow_b = (lane & 7) + (((lane >> 3) & 1) * 8);
    int tsel = lane >> 4;

    // load Q once (resident)
#pragma unroll
    for (int kc = 0; kc < 10; kc++)
        CP_ASYNC16(sbase + FQOFF + kc * 8192 + soff, pQ + goff + (long long)kc * 64);
    CP_COMMIT();
    CP_WAIT(0);
    __syncthreads();

    float oacc[16][4];
#pragma unroll
    for (int i = 0; i < 16; i++)
#pragma unroll
        for (int q = 0; q < 4; q++) oacc[i][q] = 0.f;
    float lsum0 = 0.f, lsum1 = 0.f;

    int prow0 = mg * 16 + (lane >> 2), prow1 = prow0 + 8;

    for (int j = 0; j < 32; j++) {
        const hlf* pKj = pK + (long long)j * 64 * CCAT;

#define KISSUE(kc_) do { \
    CP_ASYNC16(sbase + (kc_) * 8192 + soff, pKj + goff + (long long)(kc_) * 64); \
    CP_COMMIT(); \
} while (0)
        KISSUE(0); KISSUE(1); KISSUE(2);

        float sacc[2][4];
#pragma unroll
        for (int n = 0; n < 2; n++)
#pragma unroll
            for (int q = 0; q < 4; q++) sacc[n][q] = 0.f;

        for (int kc = 0; kc < 10; kc++) {
            CP_WAIT(2);
            __syncthreads();
            if (kc + 3 < 10) KISSUE(kc + 3);
            else CP_COMMIT();
            uint32_t kb = sbase + kc * 8192;
            uint32_t qb = sbase + FQOFF + kc * 8192;
#pragma unroll
            for (int kk = 0; kk < 4; kk++) {
                uint32_t A4[4];
                LDSM4(A4, qb + psw(arow, kk * 2 + asel));
                uint32_t B4[4];
                LDSM4(B4, kb + psw(brow, kk * 2 + bsel));
                MMA16816(sacc[0], A4, B4[0], B4[1]);
                MMA16816(sacc[1], A4, B4[2], B4[3]);
            }
        }
#undef KISSUE

        // softmax (max-free) + P fp16 write (own buffer)
        {
            const float* mrow = mask + (long long)b * CS * CS
                              + (long long)(q0 + prow0) * CS + j * 64 + cg * 16 + (lane & 3) * 2;
            float ladd0 = 0.f, ladd1 = 0.f;
#pragma unroll
            for (int nn = 0; nn < 2; nn++) {
                float2 m0 = *reinterpret_cast<const float2*>(mrow + nn * 8);
                float2 m1 = *reinterpret_cast<const float2*>(mrow + nn * 8 + 8 * CS);
                float p0 = __expf(sacc[nn][0] * scale + m0.x);
                float p1 = __expf(sacc[nn][1] * scale + m0.y);
                float p2 = __expf(sacc[nn][2] * scale + m1.x);
                float p3 = __expf(sacc[nn][3] * scale + m1.y);
                ladd0 += p0 + p1; ladd1 += p2 + p3;
                int col = cg * 16 + nn * 8 + (lane & 3) * 2;
                uint32_t o0 = (uint32_t)(prow0 * 128 + ((((col >> 3)) ^ (prow0 & 7)) << 4) + (col & 7) * 2);
                uint32_t o1 = (uint32_t)(prow1 * 128 + ((((col >> 3)) ^ (prow1 & 7)) << 4) + (col & 7) * 2);
                store_h2(p0, p1, (hlf*)(smem + FPOFF + o0));
                store_h2(p2, p3, (hlf*)(smem + FPOFF + o1));
            }
            ladd0 += __shfl_xor_sync(~0u, ladd0, 1); ladd0 += __shfl_xor_sync(~0u, ladd0, 2);
            ladd1 += __shfl_xor_sync(~0u, ladd1, 1); ladd1 += __shfl_xor_sync(~0u, ladd1, 2);
            lsum0 += ladd0; lsum1 += ladd1;
        }
        __syncthreads();   // P visible to all warps

        // AV: O += P*V; warp covers 16 rows x 128 cols
#pragma unroll
        for (int kt = 0; kt < 4; kt++) {
            uint32_t P4[4];
            LDSM4(P4, sbase + FPOFF + psw(arow, kt * 2 + asel));
            int trow = kt * 16 + trow_b;
#pragma unroll
            for (int ng = 0; ng < 8; ng++) {
                int c0 = cg * 128 + ng * 16;
                uint32_t kcb = sbase + (c0 >> 6) * 8192;
                uint32_t bo = psw(trow, ((c0 & 63) >> 3) + tsel);
                uint32_t V4[4];
                LDSM4T(V4, kcb + bo);
                MMA16816(oacc[ng*2],   P4, V4[0], V4[1]);
                MMA16816(oacc[ng*2+1], P4, V4[2], V4[3]);
            }
        }
        __syncthreads();   // AV (K/P) reads done before next j overwrites K / P
    }

    // finalize
    float* Larr = reinterpret_cast<float*>(smem);
    if ((lane & 3) == 0) {
        Larr[cg * 64 + prow0] = lsum0;
        Larr[cg * 64 + prow1] = lsum1;
    }
    __syncthreads();
    float inv0 = 1.f / (Larr[prow0] + Larr[64 + prow0] + Larr[128 + prow0] + Larr[192 + prow0]);
    float inv1 = 1.f / (Larr[prow1] + Larr[64 + prow1] + Larr[128 + prow1] + Larr[192 + prow1]);

    hlf* po = O + (long long)bh * CS * CKVLR + (long long)q0 * CKVLR;
#pragma unroll
    for (int ng = 0; ng < 8; ng++) {
#pragma unroll
        for (int h8 = 0; h8 < 2; h8++) {
            int c = cg * 128 + ng * 16 + h8 * 8 + (lane & 3) * 2;
            float* a = oacc[ng * 2 + h8];
            store_h2(a[0] * inv0, a[1] * inv0, po + (long long)prow0 * CKVLR + c);
            store_h2(a[2] * inv1, a[3] * inv1, po + (long long)prow1 * CKVLR + c);
        }
    }
}

// ---------------- conversions ----------------
__global__ void cvt_half_kernel(const float* __restrict__ s, hlf* __restrict__ d, long long n)
{
    long long n4 = n >> 2;
    long long i = (long long)blockIdx.x * blockDim.x + threadIdx.x;
    long long st = (long long)gridDim.x * blockDim.x;
    for (; i < n4; i += st) {
        float4 v = reinterpret_cast<const float4*>(s)[i];
        hlf h[4];
        h[0] = __float2half_rn(v.x); h[1] = __float2half_rn(v.y);
        h[2] = __float2half_rn(v.z); h[3] = __float2half_rn(v.w);
        *reinterpret_cast<uint2*>(d + i * 4) = *reinterpret_cast<uint2*>(h);
    }
}

// qab [h][c][d], oabT [h][d][c] from kv_b_W [c, h, 2, d] (single fp16)
__global__ void extract_kernel(const float* __restrict__ kvb,
                               hlf* __restrict__ qab, hlf* __restrict__ oabt)
{
    long long n = (long long)CNH * CKVLR * CHD;
    long long i = (long long)blockIdx.x * blockDim.x + threadIdx.x;
    long long st = (long long)gridDim.x * blockDim.x;
    for (; i < n; i += st) {
        {
            int c = (int)(i & 511);
            int d = (int)((i >> 9) & 127);
            int h = (int)(i >> 16);
            oabt[i] = __float2half_rn(kvb[(((long long)c * CNH + h) * 2 + 1) * CHD + d]);
        }
        {
            int d = (int)(i & 127);
            int c = (int)((i >> 7) & 511);
            int h = (int)(i >> 16);
            qab[i] = __float2half_rn(kvb[(((long long)c * CNH + h) * 2) * CHD + d]);
        }
    }
}

// ---------------- RMSNorm (fp32 in, fp16 out) ----------------
__global__ __launch_bounds__(256) void rms_kernel(const float* __restrict__ x, const float* __restrict__ w,
                                                  hlf* __restrict__ o)
{
    __shared__ float red[8];
    size_t row = blockIdx.x;
    const float* p = x + row * CQLR;
    int tid = threadIdx.x;
    float s = 0.f;
    for (int i = tid; i < CQLR; i += 256) { float v = p[i]; s += v * v; }
#pragma unroll
    for (int off = 16; off; off >>= 1) s += __shfl_xor_sync(~0u, s, off);
    if ((tid & 31) == 0) red[tid >> 5] = s;
    __syncthreads();
    float tot = 0.f;
#pragma unroll
    for (int i = 0; i < 8; i++) tot += red[i];
    float r = rsqrtf(tot + 1e-6f);
    hlf* po = o + row * CQLR;
    for (int i = tid; i < CQLR; i += 256) po[i] = __float2half_rn(p[i] * r * w[i]);
}

// ---------------- RoPE ----------------
__device__ __forceinline__ void rope_cs(int s, int i, float& c, float& sn)
{
    double invf = pow(10000.0, -(double)(2 * i) / 128.0);
    double ang = (double)s * invf;
    c = (float)cos(ang);
    sn = (float)sin(ang);
}

__global__ void rope_k_kernel(float* __restrict__ ckv)
{
    int idx = blockIdx.x * blockDim.x + threadIdx.x;
    if (idx >= CB * CS * 64) return;
    int i = idx & 63;
    int row = idx >> 6;
    int s = row & (CS - 1);
    float c, sn; rope_cs(s, i, c, sn);
    float* p = ckv + (size_t)row * CCAT + CKVLR;
    float x1 = p[i], x2 = p[i + 64];
    p[i]      = x1 * c - x2 * sn;
    p[i + 64] = x2 * c + x1 * sn;
}

// q_pe: read single-fp16 q, rope, write single fp16 into qc cols 512..639
__global__ void rope_q_kernel(const hlf* __restrict__ q, hlf* __restrict__ qc)
{
    int idx = blockIdx.x * blockDim.x + threadIdx.x;
    if (idx >= CB * CS * CNH * 64) return;
    int i = idx & 63;
    int h = (idx >> 6) & 15;
    int row = idx >> 10;
    int s = row & (CS - 1);
    int b = row >> 11;
    float c, sn; rope_cs(s, i, c, sn);
    long long so = (long long)row * (CNH * CQHD) + h * CQHD + CHD;
    float x1 = __half2float(q[so + i]);
    float x2 = __half2float(q[so + i + 64]);
    long long dofs = ((long long)(b * CNH + h) * CS + s) * CCAT + CKVLR;
    qc[dofs + i]      = __float2half_rn(x1 * c - x2 * sn);
    qc[dofs + i + 64] = __float2half_rn(x2 * c + x1 * sn);
}

// ---------------- launch ----------------
extern "C" void kernel_launch(void* const* d_in, const int* in_sizes, int n_in,
                              void* d_out, int out_size)
{
    const float* hidden = (const float*)d_in[0];
    const float* mask   = (const float*)d_in[1];
    const float* q_a_W  = (const float*)d_in[2];
    const float* q_a_b  = (const float*)d_in[3];
    const float* q_a_nw = (const float*)d_in[4];
    const float* q_b_W  = (const float*)d_in[5];
    const float* kv_a_W = (const float*)d_in[6];
    const float* kv_b_W = (const float*)d_in[7];
    const float* o_W    = (const float*)d_in[8];
    float* out = (float*)d_out;

    void* p;
#define SYM(v, g) cudaGetSymbolAddress(&p, g); auto* v = (decltype(&g[0]))p
    SYM(qa, g_qa);     SYM(ckv, g_ckv);
    SYM(hid, g_hid);
    SYM(qaw, g_qaw);   SYM(qbw, g_qbw);
    SYM(kvaw, g_kvaw); SYM(ow, g_ow);
    SYM(qan, g_qan);   SYM(qs, g_qs);
    SYM(qab, g_qab);   SYM(oabt, g_oabt);
    SYM(qc, g_qc);     SYM(ckvf, g_ckvf);
    SYM(ol, g_ol);     SYM(oh, g_oh);
#undef SYM

    constexpr int SMEM128 = STAGES * (ASZ + 128 * GBK * 2);  // 64 KB
    constexpr int SMEM256 = STAGES * (ASZ + 256 * GBK * 2);  // 96 KB
    cudaFuncSetAttribute(mma_gemm<128>, cudaFuncAttributeMaxDynamicSharedMemorySize, SMEM128);
    cudaFuncSetAttribute(mma_gemm<256>, cudaFuncAttributeMaxDynamicSharedMemorySize, SMEM256);
    cudaFuncSetAttribute(flash_kernel, cudaFuncAttributeMaxDynamicSharedMemorySize, FSMEM);

    const long long LS = CS;
    const int CVG = 2048;

    cvt_half_kernel<<<CVG, 256>>>(hidden, hid, (long long)CBS * CHID);
    cvt_half_kernel<<<CVG, 256>>>(q_a_W, qaw, (long long)CQLR * CHID);
    cvt_half_kernel<<<CVG, 256>>>(kv_a_W, kvaw, (long long)CCAT * CHID);

    // q_a = hidden @ q_a_W^T + bias   [4096,1536] K=2048, fp32 out
    mma_gemm<256><<<dim3(CQLR / 256, CBS / 128, 1), 512, SMEM256>>>(
        hid, CHID, 0, 0, qaw, CHID, 0, 0,
        qa, nullptr, CQLR, 0, 0, q_a_b, 1.f, CHID, 1);

    // ckv = hidden @ kv_a_W^T  [4096,640] K=2048, fp32 out
    mma_gemm<128><<<dim3(CCAT / 128, CBS / 128, 1), 512, SMEM128>>>(
        hid, CHID, 0, 0, kvaw, CHID, 0, 0,
        ckv, nullptr, CCAT, 0, 0, nullptr, 1.f, CHID, 1);

    rms_kernel<<<CBS, 256>>>(qa, q_a_nw, qan);
    cvt_half_kernel<<<CVG, 256>>>(q_b_W, qbw, (long long)CNH * CQHD * CQLR);

    // q = qa_norm @ q_b_W^T  [4096,4096] K=1536, fp16 out
    mma_gemm<256><<<dim3((CNH * CQHD) / 256, CBS / 128, 1), 512, SMEM256>>>(
        qan, CQLR, 0, 0, qbw, CQLR, 0, 0,
        nullptr, qs, CNH * CQHD, 0, 0, nullptr, 1.f, CQLR, 1);

    extract_kernel<<<CVG, 256>>>(kv_b_W, qab, oabt);
    rope_k_kernel<<<(CB * CS * 64) / 256, 256>>>(ckv);
    rope_q_kernel<<<(CB * CS * CNH * 64) / 256, 256>>>(qs, qc);

    // q_lat -> qc cols [0,512)  K=128, Z=32, fp16 out
    mma_gemm<256><<<dim3(CKVLR / 256, CS / 128, CB * CNH), 512, SMEM256>>>(
        qs, CNH * CQHD, LS * CNH * CQHD, CQHD,
        qab, CHD, 0, (long long)CKVLR * CHD,
        nullptr, qc, CCAT, LS * CNH * CCAT, LS * CCAT,
        nullptr, 1.f, CHD, CNH);

    // keys/V single fp16 (K-major)
    cvt_half_kernel<<<CVG, 256>>>(ckv, ckvf, (long long)CBS * CCAT);

    // fused attention: scores + softmax + AV -> ol (fp16)
    float scale = 1.f / sqrtf((float)CCAT);
    flash_kernel<<<dim3(CS / 64, CB * CNH), 512, FSMEM>>>(
        qc, ckvf, mask, ol, scale);

    cvt_half_kernel<<<CVG, 256>>>(o_W, ow, (long long)CHID * CNH * CHD);

    // out_head = ol . o_absorb^T -> [b,s,h*128+d]  K=512, N=128, Z=32, fp16 out
    mma_gemm<128><<<dim3(1, CS / 128, CB * CNH), 512, SMEM128>>>(
        ol, CKVLR, LS * CNH * CKVLR, LS * CKVLR,
        oabt, CKVLR, 0, (long long)CHD * CKVLR,
        nullptr, oh, CNH * CHD, LS * (long long)CNH * CHD, CHD,
        nullptr, 1.f, CKVLR, CNH);

    // final = oh @ o_W^T  [4096,2048] K=2048, fp32 out
    mma_gemm<256><<<dim3(CHID / 256, CBS / 128, 1), 512, SMEM256>>>(
        oh, CNH * CHD, 0, 0, ow, CNH * CHD, 0, 0,
        out, nullptr, CHID, 0, 0, nullptr, 1.f, CNH * CHD, 1);
}

// round 13
// speedup vs baseline: 1.7767x; 1.0078x over previous
#include <cuda_runtime.h>
#include <cuda_fp16.h>
#include <math.h>
#include <stdint.h>

// ---------------- problem constants ----------------
#define CB   2
#define CS   2048
#define CHID 2048
#define CNH  16
#define CHD  128
#define CQLR 1536
#define CKVLR 512
#define CBS  (CB*CS)          // 4096
#define CCAT (CKVLR+CHD)      // 640
#define CQHD (2*CHD)          // 256

typedef __half hlf;

// ---------------- device scratch ----------------
static __device__ __align__(256) float g_qa[(size_t)CBS*CQLR];

static __device__ __align__(256) hlf g_hid[(size_t)CBS*CHID];
static __device__ __align__(256) hlf g_qan[(size_t)CBS*CQLR];
static __device__ __align__(256) hlf g_qs[(size_t)CBS*CNH*CQHD];
static __device__ __align__(256) hlf g_ol[(size_t)CB*CNH*CS*CKVLR];
static __device__ __align__(256) hlf g_oh[(size_t)CBS*CNH*CHD];
static __device__ __align__(256) hlf g_qc[(size_t)CB*CNH*CS*CCAT];
static __device__ __align__(256) hlf g_qaw[(size_t)CQLR*CHID];
static __device__ __align__(256) hlf g_qbw[(size_t)CNH*CQHD*CQLR];
static __device__ __align__(256) hlf g_kvaw[(size_t)CCAT*CHID];
static __device__ __align__(256) hlf g_ow[(size_t)CHID*CNH*CHD];
static __device__ __align__(256) hlf g_qab[(size_t)CNH*CKVLR*CHD];     // [h][c][d]
static __device__ __align__(256) hlf g_oabt[(size_t)CNH*CHD*CKVLR];    // [h][d][c]
static __device__ __align__(256) hlf g_ckvf[(size_t)CBS*CCAT];         // keys/V, K-major fp16

// ---------------- asm helpers (sm_80-portable) ----------------
__device__ __forceinline__ uint32_t smem_u32(const void* p) {
    uint32_t a;
    asm("{ .reg .u64 t; cvta.to.shared.u64 t, %1; cvt.u32.u64 %0, t; }" : "=r"(a) : "l"(p));
    return a;
}
#define CP_ASYNC16(dst, src) \
    asm volatile("cp.async.cg.shared.global [%0], [%1], 16;" :: "r"(dst), "l"(src) : "memory")
#define CP_COMMIT() asm volatile("cp.async.commit_group;" ::: "memory")
#define CP_WAIT(n)  asm volatile("cp.async.wait_group %0;" :: "n"(n) : "memory")

#define LDSM4(r, addr) \
    asm volatile("ldmatrix.sync.aligned.m8n8.x4.shared.b16 {%0,%1,%2,%3}, [%4];" \
        : "=r"((r)[0]),"=r"((r)[1]),"=r"((r)[2]),"=r"((r)[3]) : "r"(addr))
#define LDSM4T(r, addr) \
    asm volatile("ldmatrix.sync.aligned.m8n8.x4.trans.shared.b16 {%0,%1,%2,%3}, [%4];" \
        : "=r"((r)[0]),"=r"((r)[1]),"=r"((r)[2]),"=r"((r)[3]) : "r"(addr))

#define MMA16816(d, a, b0, b1) \
    asm volatile("mma.sync.aligned.m16n8k16.row.col.f32.f16.f16.f32 " \
        "{%0,%1,%2,%3},{%4,%5,%6,%7},{%8,%9},{%0,%1,%2,%3};" \
        : "+f"((d)[0]),"+f"((d)[1]),"+f"((d)[2]),"+f"((d)[3]) \
        : "r"((a)[0]),"r"((a)[1]),"r"((a)[2]),"r"((a)[3]), "r"(b0),"r"(b1))

__device__ __forceinline__ void store_h2(float v0, float v1, hlf* hp) {
    __half2 hh; hh.x = __float2half_rn(v0); hh.y = __float2half_rn(v1);
    *reinterpret_cast<__half2*>(hp) = hh;
}

// ---------------- fp16 MMA GEMM (512 threads, 16 warps) ----------------
static constexpr int GBK = 32, STAGES = 4;
static constexpr int ASZ = 128 * GBK * 2;   // 8192 B

__device__ __forceinline__ uint32_t swz(int row, int ch) {
    return (uint32_t)(row * 64 + ((ch ^ ((row >> 1) & 3)) * 16));
}

template<int BN>
__global__ __launch_bounds__(512, 1) void mma_gemm(
    const hlf* __restrict__ A, int lda, long long aO, long long aI,
    const hlf* __restrict__ B, int ldb, long long bO, long long bI,
    float* __restrict__ C, hlf* __restrict__ Chi,
    int ldc, long long cO, long long cI,
    const float* __restrict__ bias, float alpha, int K, int zInner)
{
    constexpr int JG = BN / 64;
    constexpr int BSZ = BN * GBK * 2;
    constexpr int STAGE_B = ASZ + BSZ;

    extern __shared__ char smem_raw[];
    uint32_t sbase = smem_u32(smem_raw);

    int tid = threadIdx.x, wid = tid >> 5, lane = tid & 31;
    int z = blockIdx.z, zo = z / zInner, zi = z - zo * zInner;
    A += zo * aO + zi * aI;
    B += zo * bO + zi * bI;
    if (C)   C   += zo * cO + zi * cI;
    if (Chi) Chi += zo * cO + zi * cI;

    int bm = blockIdx.y * 128, bn = blockIdx.x * BN;
    int wm = (wid & 3) * 32;
    int wn = (wid >> 2) * (BN / 4);

    const hlf* pA = A + (long long)bm * lda;
    const hlf* pB = B + (long long)bn * ldb;

    float acc[2][2 * JG][4];
#pragma unroll
    for (int t = 0; t < 2; t++)
#pragma unroll
        for (int j = 0; j < 2 * JG; j++)
#pragma unroll
            for (int q = 0; q < 4; q++) acc[t][j][q] = 0.f;

    int nk = K / GBK;

#define ISSUE(stage_) do { \
    int st_ = (stage_) % STAGES; \
    uint32_t sb_ = sbase + st_ * STAGE_B; \
    long long k0_ = (long long)(stage_) * GBK; \
    { int r = tid >> 2, ch = tid & 3; \
      uint32_t so = swz(r, ch); \
      CP_ASYNC16(sb_ + so, pA + (long long)r * lda + k0_ + ch * 8); } \
    _Pragma("unroll") \
    for (int u = 0; u < BN / 128; u++) { \
        int idx = u * 512 + tid; int r = idx >> 2, ch = idx & 3; \
        uint32_t so = swz(r, ch); \
        CP_ASYNC16(sb_ + ASZ + so, pB + (long long)r * ldb + k0_ + ch * 8); \
    } \
} while (0)

    for (int s = 0; s < STAGES - 1; s++) {
        if (s < nk) ISSUE(s);
        CP_COMMIT();
    }

    int a_row = (lane & 15);
    int a_sel = lane >> 4;
    int b_row = (lane & 7) + ((lane >> 4) * 8);
    int b_sel = (lane >> 3) & 1;

    for (int i = 0; i < nk; i++) {
        CP_WAIT(STAGES - 2);
        __syncthreads();
        if (i + STAGES - 1 < nk) ISSUE(i + STAGES - 1);
        CP_COMMIT();

        uint32_t sb = sbase + (i % STAGES) * STAGE_B;

#pragma unroll
        for (int kh = 0; kh < 2; kh++) {
            uint32_t Af[2][4];
#pragma unroll
            for (int t = 0; t < 2; t++) {
                int row = wm + t * 16 + a_row;
                LDSM4(Af[t], sb + swz(row, 2 * kh + a_sel));
            }
#pragma unroll
            for (int jg = 0; jg < JG; jg++) {
                int row = wn + jg * 16 + b_row;
                uint32_t B4[4];
                LDSM4(B4, sb + ASZ + swz(row, 2 * kh + b_sel));
#pragma unroll
                for (int t = 0; t < 2; t++) {
                    MMA16816(acc[t][2*jg],   Af[t], B4[0], B4[1]);
                    MMA16816(acc[t][2*jg+1], Af[t], B4[2], B4[3]);
                }
            }
        }
    }
#undef ISSUE

#pragma unroll
    for (int t = 0; t < 2; t++) {
        int r0 = bm + wm + t * 16 + (lane >> 2);
#pragma unroll
        for (int j = 0; j < 2 * JG; j++) {
            int col = bn + wn + j * 8 + (lane & 3) * 2;
            float v0 = acc[t][j][0] * alpha;
            float v1 = acc[t][j][1] * alpha;
            float v2 = acc[t][j][2] * alpha;
            float v3 = acc[t][j][3] * alpha;
            if (bias) { v0 += bias[col]; v1 += bias[col + 1]; v2 += bias[col]; v3 += bias[col + 1]; }
            long long o0 = (long long)r0 * ldc + col;
            long long o1 = (long long)(r0 + 8) * ldc + col;
            if (Chi) {
                store_h2(v0, v1, Chi + o0);
                store_h2(v2, v3, Chi + o1);
            } else {
                C[o0] = v0; C[o0 + 1] = v1;
                C[o1] = v2; C[o1 + 1] = v3;
            }
        }
    }
}

// ---------------- fused flash attention (512 threads, Q resident, paired chunks) ----------------
// CTA: 64 q rows, one (b,h). Q (64x640 fp16, 80KB) loaded once.
// K' tile (64 keys x 640) streamed per j in 5 PAIRS of 8KB chunks (one barrier
// per pair -> 16 MMAs/warp between barriers). V = K'[:, :512] via ldmatrix.trans.
// smem: K 10x8KB @0; Q 10x8KB @81920; P 8KB @163840.  Total 168KB.
static constexpr int FQOFF = 81920;
static constexpr int FPOFF = 163840;
static constexpr int FSMEM = 163840 + 8192;   // 168 KB

__device__ __forceinline__ uint32_t psw(int row, int ch) {
    return (uint32_t)(row * 128 + ((ch ^ (row & 7)) << 4));
}

__global__ __launch_bounds__(512, 1) void flash_kernel(
    const hlf* __restrict__ Q,
    const hlf* __restrict__ Kf,
    const float* __restrict__ mask,
    hlf* __restrict__ O,
    float scale)
{
    extern __shared__ char smem[];
    uint32_t sbase = smem_u32(smem);
    int tid = threadIdx.x, wid = tid >> 5, lane = tid & 31;
    int mg = wid & 3, cg = wid >> 2;
    int bh = blockIdx.y, b = bh >> 4;
    int q0 = blockIdx.x * 64;

    const hlf* pQ = Q + (long long)bh * CS * CCAT + (long long)q0 * CCAT;
    const hlf* pK = Kf + (long long)b * CS * CCAT;

    int lrow = tid >> 3, lch = tid & 7;
    uint32_t soff = psw(lrow, lch);
    long long goff = (long long)lrow * CCAT + lch * 8;

    int arow = mg * 16 + (lane & 15);
    int asel = lane >> 4;
    int brow = cg * 16 + (lane & 7) + ((lane >> 4) * 8);
    int bsel = (lane >> 3) & 1;
    int trow_b = (lane & 7) + (((lane >> 3) & 1) * 8);
    int tsel = lane >> 4;

    // load Q once (resident)
#pragma unroll
    for (int kc = 0; kc < 10; kc++)
        CP_ASYNC16(sbase + FQOFF + kc * 8192 + soff, pQ + goff + (long long)kc * 64);
    CP_COMMIT();
    CP_WAIT(0);
    __syncthreads();

    float oacc[16][4];
#pragma unroll
    for (int i = 0; i < 16; i++)
#pragma unroll
        for (int q = 0; q < 4; q++) oacc[i][q] = 0.f;
    float lsum0 = 0.f, lsum1 = 0.f;

    int prow0 = mg * 16 + (lane >> 2), prow1 = prow0 + 8;

    for (int j = 0; j < 32; j++) {
        const hlf* pKj = pK + (long long)j * 64 * CCAT;

#define KPAIR(p_) do { \
    CP_ASYNC16(sbase + (2*(p_)) * 8192 + soff,     pKj + goff + (long long)(2*(p_)) * 64); \
    CP_ASYNC16(sbase + (2*(p_)+1) * 8192 + soff,   pKj + goff + (long long)(2*(p_)+1) * 64); \
    CP_COMMIT(); \
} while (0)
        KPAIR(0); KPAIR(1); KPAIR(2);

        float sacc[2][4];
#pragma unroll
        for (int n = 0; n < 2; n++)
#pragma unroll
            for (int q = 0; q < 4; q++) sacc[n][q] = 0.f;

        for (int pp = 0; pp < 5; pp++) {
            CP_WAIT(2);
            __syncthreads();
            if (pp + 3 < 5) KPAIR(pp + 3);
            else CP_COMMIT();
#pragma unroll
            for (int half = 0; half < 2; half++) {
                int kc = 2 * pp + half;
                uint32_t kb = sbase + kc * 8192;
                uint32_t qb = sbase + FQOFF + kc * 8192;
#pragma unroll
                for (int kk = 0; kk < 4; kk++) {
                    uint32_t A4[4];
                    LDSM4(A4, qb + psw(arow, kk * 2 + asel));
                    uint32_t B4[4];
                    LDSM4(B4, kb + psw(brow, kk * 2 + bsel));
                    MMA16816(sacc[0], A4, B4[0], B4[1]);
                    MMA16816(sacc[1], A4, B4[2], B4[3]);
                }
            }
        }
#undef KPAIR

        // softmax (max-free) + P fp16 write (own buffer)
        {
            const float* mrow = mask + (long long)b * CS * CS
                              + (long long)(q0 + prow0) * CS + j * 64 + cg * 16 + (lane & 3) * 2;
            float ladd0 = 0.f, ladd1 = 0.f;
#pragma unroll
            for (int nn = 0; nn < 2; nn++) {
                float2 m0 = *reinterpret_cast<const float2*>(mrow + nn * 8);
                float2 m1 = *reinterpret_cast<const float2*>(mrow + nn * 8 + 8 * CS);
                float p0 = __expf(sacc[nn][0] * scale + m0.x);
                float p1 = __expf(sacc[nn][1] * scale + m0.y);
                float p2 = __expf(sacc[nn][2] * scale + m1.x);
                float p3 = __expf(sacc[nn][3] * scale + m1.y);
                ladd0 += p0 + p1; ladd1 += p2 + p3;
                int col = cg * 16 + nn * 8 + (lane & 3) * 2;
                uint32_t o0 = (uint32_t)(prow0 * 128 + ((((col >> 3)) ^ (prow0 & 7)) << 4) + (col & 7) * 2);
                uint32_t o1 = (uint32_t)(prow1 * 128 + ((((col >> 3)) ^ (prow1 & 7)) << 4) + (col & 7) * 2);
                store_h2(p0, p1, (hlf*)(smem + FPOFF + o0));
                store_h2(p2, p3, (hlf*)(smem + FPOFF + o1));
            }
            ladd0 += __shfl_xor_sync(~0u, ladd0, 1); ladd0 += __shfl_xor_sync(~0u, ladd0, 2);
            ladd1 += __shfl_xor_sync(~0u, ladd1, 1); ladd1 += __shfl_xor_sync(~0u, ladd1, 2);
            lsum0 += ladd0; lsum1 += ladd1;
        }
        __syncthreads();   // P visible to all warps

        // AV: O += P*V; warp covers 16 rows x 128 cols
#pragma unroll
        for (int kt = 0; kt < 4; kt++) {
            uint32_t P4[4];
            LDSM4(P4, sbase + FPOFF + psw(arow, kt * 2 + asel));
            int trow = kt * 16 + trow_b;
#pragma unroll
            for (int ng = 0; ng < 8; ng++) {
                int c0 = cg * 128 + ng * 16;
                uint32_t kcb = sbase + (c0 >> 6) * 8192;
                uint32_t bo = psw(trow, ((c0 & 63) >> 3) + tsel);
                uint32_t V4[4];
                LDSM4T(V4, kcb + bo);
                MMA16816(oacc[ng*2],   P4, V4[0], V4[1]);
                MMA16816(oacc[ng*2+1], P4, V4[2], V4[3]);
            }
        }
        __syncthreads();   // AV (K/P) reads done before next j overwrites K / P
    }

    // finalize
    float* Larr = reinterpret_cast<float*>(smem);
    if ((lane & 3) == 0) {
        Larr[cg * 64 + prow0] = lsum0;
        Larr[cg * 64 + prow1] = lsum1;
    }
    __syncthreads();
    float inv0 = 1.f / (Larr[prow0] + Larr[64 + prow0] + Larr[128 + prow0] + Larr[192 + prow0]);
    float inv1 = 1.f / (Larr[prow1] + Larr[64 + prow1] + Larr[128 + prow1] + Larr[192 + prow1]);

    hlf* po = O + (long long)bh * CS * CKVLR + (long long)q0 * CKVLR;
#pragma unroll
    for (int ng = 0; ng < 8; ng++) {
#pragma unroll
        for (int h8 = 0; h8 < 2; h8++) {
            int c = cg * 128 + ng * 16 + h8 * 8 + (lane & 3) * 2;
            float* a = oacc[ng * 2 + h8];
            store_h2(a[0] * inv0, a[1] * inv0, po + (long long)prow0 * CKVLR + c);
            store_h2(a[2] * inv1, a[3] * inv1, po + (long long)prow1 * CKVLR + c);
        }
    }
}

// ---------------- conversions ----------------
__global__ void cvt_half_kernel(const float* __restrict__ s, hlf* __restrict__ d, long long n)
{
    long long n4 = n >> 2;
    long long i = (long long)blockIdx.x * blockDim.x + threadIdx.x;
    long long st = (long long)gridDim.x * blockDim.x;
    for (; i < n4; i += st) {
        float4 v = reinterpret_cast<const float4*>(s)[i];
        hlf h[4];
        h[0] = __float2half_rn(v.x); h[1] = __float2half_rn(v.y);
        h[2] = __float2half_rn(v.z); h[3] = __float2half_rn(v.w);
        *reinterpret_cast<uint2*>(d + i * 4) = *reinterpret_cast<uint2*>(h);
    }
}

// qab [h][c][d], oabT [h][d][c] from kv_b_W [c, h, 2, d] (single fp16)
__global__ void extract_kernel(const float* __restrict__ kvb,
                               hlf* __restrict__ qab, hlf* __restrict__ oabt)
{
    long long n = (long long)CNH * CKVLR * CHD;
    long long i = (long long)blockIdx.x * blockDim.x + threadIdx.x;
    long long st = (long long)gridDim.x * blockDim.x;
    for (; i < n; i += st) {
        {
            int c = (int)(i & 511);
            int d = (int)((i >> 9) & 127);
            int h = (int)(i >> 16);
            oabt[i] = __float2half_rn(kvb[(((long long)c * CNH + h) * 2 + 1) * CHD + d]);
        }
        {
            int d = (int)(i & 127);
            int c = (int)((i >> 7) & 511);
            int h = (int)(i >> 16);
            qab[i] = __float2half_rn(kvb[(((long long)c * CNH + h) * 2) * CHD + d]);
        }
    }
}

// ---------------- RMSNorm (fp32 in, fp16 out) ----------------
__global__ __launch_bounds__(256) void rms_kernel(const float* __restrict__ x, const float* __restrict__ w,
                                                  hlf* __restrict__ o)
{
    __shared__ float red[8];
    size_t row = blockIdx.x;
    const float* p = x + row * CQLR;
    int tid = threadIdx.x;
    float s = 0.f;
    for (int i = tid; i < CQLR; i += 256) { float v = p[i]; s += v * v; }
#pragma unroll
    for (int off = 16; off; off >>= 1) s += __shfl_xor_sync(~0u, s, off);
    if ((tid & 31) == 0) red[tid >> 5] = s;
    __syncthreads();
    float tot = 0.f;
#pragma unroll
    for (int i = 0; i < 8; i++) tot += red[i];
    float r = rsqrtf(tot + 1e-6f);
    hlf* po = o + row * CQLR;
    for (int i = tid; i < CQLR; i += 256) po[i] = __float2half_rn(p[i] * r * w[i]);
}

// ---------------- RoPE ----------------
__device__ __forceinline__ void rope_cs(int s, int i, float& c, float& sn)
{
    double invf = pow(10000.0, -(double)(2 * i) / 128.0);
    double ang = (double)s * invf;
    c = (float)cos(ang);
    sn = (float)sin(ang);
}

// k_pe: in-place on fp16 ckvf cols [512,640)
__global__ void rope_k_kernel(hlf* __restrict__ ckv)
{
    int idx = blockIdx.x * blockDim.x + threadIdx.x;
    if (idx >= CB * CS * 64) return;
    int i = idx & 63;
    int row = idx >> 6;
    int s = row & (CS - 1);
    float c, sn; rope_cs(s, i, c, sn);
    hlf* p = ckv + (size_t)row * CCAT + CKVLR;
    float x1 = __half2float(p[i]), x2 = __half2float(p[i + 64]);
    p[i]      = __float2half_rn(x1 * c - x2 * sn);
    p[i + 64] = __float2half_rn(x2 * c + x1 * sn);
}

// q_pe: read single-fp16 q, rope, write single fp16 into qc cols 512..639
__global__ void rope_q_kernel(const hlf* __restrict__ q, hlf* __restrict__ qc)
{
    int idx = blockIdx.x * blockDim.x + threadIdx.x;
    if (idx >= CB * CS * CNH * 64) return;
    int i = idx & 63;
    int h = (idx >> 6) & 15;
    int row = idx >> 10;
    int s = row & (CS - 1);
    int b = row >> 11;
    float c, sn; rope_cs(s, i, c, sn);
    long long so = (long long)row * (CNH * CQHD) + h * CQHD + CHD;
    float x1 = __half2float(q[so + i]);
    float x2 = __half2float(q[so + i + 64]);
    long long dofs = ((long long)(b * CNH + h) * CS + s) * CCAT + CKVLR;
    qc[dofs + i]      = __float2half_rn(x1 * c - x2 * sn);
    qc[dofs + i + 64] = __float2half_rn(x2 * c + x1 * sn);
}

// ---------------- launch ----------------
extern "C" void kernel_launch(void* const* d_in, const int* in_sizes, int n_in,
                              void* d_out, int out_size)
{
    const float* hidden = (const float*)d_in[0];
    const float* mask   = (const float*)d_in[1];
    const float* q_a_W  = (const float*)d_in[2];
    const float* q_a_b  = (const float*)d_in[3];
    const float* q_a_nw = (const float*)d_in[4];
    const float* q_b_W  = (const float*)d_in[5];
    const float* kv_a_W = (const float*)d_in[6];
    const float* kv_b_W = (const float*)d_in[7];
    const float* o_W    = (const float*)d_in[8];
    float* out = (float*)d_out;

    void* p;
#define SYM(v, g) cudaGetSymbolAddress(&p, g); auto* v = (decltype(&g[0]))p
    SYM(qa, g_qa);
    SYM(hid, g_hid);
    SYM(qaw, g_qaw);   SYM(qbw, g_qbw);
    SYM(kvaw, g_kvaw); SYM(ow, g_ow);
    SYM(qan, g_qan);   SYM(qs, g_qs);
    SYM(qab, g_qab);   SYM(oabt, g_oabt);
    SYM(qc, g_qc);     SYM(ckvf, g_ckvf);
    SYM(ol, g_ol);     SYM(oh, g_oh);
#undef SYM

    constexpr int SMEM128 = STAGES * (ASZ + 128 * GBK * 2);  // 64 KB
    constexpr int SMEM256 = STAGES * (ASZ + 256 * GBK * 2);  // 96 KB
    cudaFuncSetAttribute(mma_gemm<128>, cudaFuncAttributeMaxDynamicSharedMemorySize, SMEM128);
    cudaFuncSetAttribute(mma_gemm<256>, cudaFuncAttributeMaxDynamicSharedMemorySize, SMEM256);
    cudaFuncSetAttribute(flash_kernel, cudaFuncAttributeMaxDynamicSharedMemorySize, FSMEM);

    const long long LS = CS;
    const int CVG = 2048;

    cvt_half_kernel<<<CVG, 256>>>(hidden, hid, (long long)CBS * CHID);
    cvt_half_kernel<<<CVG, 256>>>(q_a_W, qaw, (long long)CQLR * CHID);
    cvt_half_kernel<<<CVG, 256>>>(kv_a_W, kvaw, (long long)CCAT * CHID);

    // q_a = hidden @ q_a_W^T + bias   [4096,1536] K=2048, fp32 out
    mma_gemm<256><<<dim3(CQLR / 256, CBS / 128, 1), 512, SMEM256>>>(
        hid, CHID, 0, 0, qaw, CHID, 0, 0,
        qa, nullptr, CQLR, 0, 0, q_a_b, 1.f, CHID, 1);

    // ckv = hidden @ kv_a_W^T  [4096,640] K=2048, fp16 out directly
    mma_gemm<128><<<dim3(CCAT / 128, CBS / 128, 1), 512, SMEM128>>>(
        hid, CHID, 0, 0, kvaw, CHID, 0, 0,
        nullptr, ckvf, CCAT, 0, 0, nullptr, 1.f, CHID, 1);

    rms_kernel<<<CBS, 256>>>(qa, q_a_nw, qan);
    cvt_half_kernel<<<CVG, 256>>>(q_b_W, qbw, (long long)CNH * CQHD * CQLR);

    // q = qa_norm @ q_b_W^T  [4096,4096] K=1536, fp16 out
    mma_gemm<256><<<dim3((CNH * CQHD) / 256, CBS / 128, 1), 512, SMEM256>>>(
        qan, CQLR, 0, 0, qbw, CQLR, 0, 0,
        nullptr, qs, CNH * CQHD, 0, 0, nullptr, 1.f, CQLR, 1);

    extract_kernel<<<CVG, 256>>>(kv_b_W, qab, oabt);
    rope_k_kernel<<<(CB * CS * 64) / 256, 256>>>(ckvf);
    rope_q_kernel<<<(CB * CS * CNH * 64) / 256, 256>>>(qs, qc);

    // q_lat -> qc cols [0,512)  K=128, Z=32, fp16 out
    mma_gemm<256><<<dim3(CKVLR / 256, CS / 128, CB * CNH), 512, SMEM256>>>(
        qs, CNH * CQHD, LS * CNH * CQHD, CQHD,
        qab, CHD, 0, (long long)CKVLR * CHD,
        nullptr, qc, CCAT, LS * CNH * CCAT, LS * CCAT,
        nullptr, 1.f, CHD, CNH);

    // fused attention: scores + softmax + AV -> ol (fp16)
    float scale = 1.f / sqrtf((float)CCAT);
    flash_kernel<<<dim3(CS / 64, CB * CNH), 512, FSMEM>>>(
        qc, ckvf, mask, ol, scale);

    cvt_half_kernel<<<CVG, 256>>>(o_W, ow, (long long)CHID * CNH * CHD);

    // out_head = ol . o_absorb^T -> [b,s,h*128+d]  K=512, N=128, Z=32, fp16 out
    mma_gemm<128><<<dim3(1, CS / 128, CB * CNH), 512, SMEM128>>>(
        ol, CKVLR, LS * CNH * CKVLR, LS * CKVLR,
        oabt, CKVLR, 0, (long long)CHD * CKVLR,
        nullptr, oh, CNH * CHD, LS * (long long)CNH * CHD, CHD,
        nullptr, 1.f, CKVLR, CNH);

    // final = oh @ o_W^T  [4096,2048] K=2048, fp32 out
    mma_gemm<256><<<dim3(CHID / 256, CBS / 128, 1), 512, SMEM256>>>(
        oh, CNH * CHD, 0, 0, ow, CNH * CHD, 0, 0,
        out, nullptr, CHID, 0, 0, nullptr, 1.f, CNH * CHD, 1);
}

// round 14
// speedup vs baseline: 1.9103x; 1.0752x over previous
#include <cuda_runtime.h>
#include <cuda_fp16.h>
#include <math.h>
#include <stdint.h>

// ---------------- problem constants ----------------
#define CB   2
#define CS   2048
#define CHID 2048
#define CNH  16
#define CHD  128
#define CQLR 1536
#define CKVLR 512
#define CBS  (CB*CS)          // 4096
#define CCAT (CKVLR+CHD)      // 640
#define CQHD (2*CHD)          // 256

typedef __half hlf;

// ---------------- device scratch ----------------
static __device__ __align__(256) float g_qa[(size_t)CBS*CQLR];

static __device__ __align__(256) hlf g_hid[(size_t)CBS*CHID];
static __device__ __align__(256) hlf g_qan[(size_t)CBS*CQLR];
static __device__ __align__(256) hlf g_qs[(size_t)CBS*CNH*CQHD];
static __device__ __align__(256) hlf g_ol[(size_t)CB*CNH*CS*CKVLR];
static __device__ __align__(256) hlf g_oh[(size_t)CBS*CNH*CHD];
static __device__ __align__(256) hlf g_qc[(size_t)CB*CNH*CS*CCAT];
static __device__ __align__(256) hlf g_qaw[(size_t)CQLR*CHID];
static __device__ __align__(256) hlf g_qbw[(size_t)CNH*CQHD*CQLR];
static __device__ __align__(256) hlf g_kvaw[(size_t)CCAT*CHID];
static __device__ __align__(256) hlf g_ow[(size_t)CHID*CNH*CHD];
static __device__ __align__(256) hlf g_qab[(size_t)CNH*CKVLR*CHD];     // [h][c][d]
static __device__ __align__(256) hlf g_oabt[(size_t)CNH*CHD*CKVLR];    // [h][d][c]
static __device__ __align__(256) hlf g_ckvf[(size_t)CBS*CCAT];         // keys/V, K-major fp16

// ---------------- asm helpers (sm_80-portable) ----------------
__device__ __forceinline__ uint32_t smem_u32(const void* p) {
    uint32_t a;
    asm("{ .reg .u64 t; cvta.to.shared.u64 t, %1; cvt.u32.u64 %0, t; }" : "=r"(a) : "l"(p));
    return a;
}
#define CP_ASYNC16(dst, src) \
    asm volatile("cp.async.cg.shared.global [%0], [%1], 16;" :: "r"(dst), "l"(src) : "memory")
#define CP_COMMIT() asm volatile("cp.async.commit_group;" ::: "memory")
#define CP_WAIT(n)  asm volatile("cp.async.wait_group %0;" :: "n"(n) : "memory")

#define LDSM4(r, addr) \
    asm volatile("ldmatrix.sync.aligned.m8n8.x4.shared.b16 {%0,%1,%2,%3}, [%4];" \
        : "=r"((r)[0]),"=r"((r)[1]),"=r"((r)[2]),"=r"((r)[3]) : "r"(addr))
#define LDSM4T(r, addr) \
    asm volatile("ldmatrix.sync.aligned.m8n8.x4.trans.shared.b16 {%0,%1,%2,%3}, [%4];" \
        : "=r"((r)[0]),"=r"((r)[1]),"=r"((r)[2]),"=r"((r)[3]) : "r"(addr))

#define MMA16816(d, a, b0, b1) \
    asm volatile("mma.sync.aligned.m16n8k16.row.col.f32.f16.f16.f32 " \
        "{%0,%1,%2,%3},{%4,%5,%6,%7},{%8,%9},{%0,%1,%2,%3};" \
        : "+f"((d)[0]),"+f"((d)[1]),"+f"((d)[2]),"+f"((d)[3]) \
        : "r"((a)[0]),"r"((a)[1]),"r"((a)[2]),"r"((a)[3]), "r"(b0),"r"(b1))

__device__ __forceinline__ void store_h2(float v0, float v1, hlf* hp) {
    __half2 hh; hh.x = __float2half_rn(v0); hh.y = __float2half_rn(v1);
    *reinterpret_cast<__half2*>(hp) = hh;
}

// ---------------- fp16 MMA GEMM (512 threads, 16 warps) ----------------
static constexpr int GBK = 32, STAGES = 4;
static constexpr int ASZ = 128 * GBK * 2;   // 8192 B

__device__ __forceinline__ uint32_t swz(int row, int ch) {
    return (uint32_t)(row * 64 + ((ch ^ ((row >> 1) & 3)) * 16));
}

template<int BN>
__global__ __launch_bounds__(512, 1) void mma_gemm(
    const hlf* __restrict__ A, int lda, long long aO, long long aI,
    const hlf* __restrict__ B, int ldb, long long bO, long long bI,
    float* __restrict__ C, hlf* __restrict__ Chi,
    int ldc, long long cO, long long cI,
    const float* __restrict__ bias, float alpha, int K, int zInner)
{
    constexpr int JG = BN / 64;
    constexpr int BSZ = BN * GBK * 2;
    constexpr int STAGE_B = ASZ + BSZ;

    extern __shared__ char smem_raw[];
    uint32_t sbase = smem_u32(smem_raw);

    int tid = threadIdx.x, wid = tid >> 5, lane = tid & 31;
    int z = blockIdx.z, zo = z / zInner, zi = z - zo * zInner;
    A += zo * aO + zi * aI;
    B += zo * bO + zi * bI;
    if (C)   C   += zo * cO + zi * cI;
    if (Chi) Chi += zo * cO + zi * cI;

    int bm = blockIdx.y * 128, bn = blockIdx.x * BN;
    int wm = (wid & 3) * 32;
    int wn = (wid >> 2) * (BN / 4);

    const hlf* pA = A + (long long)bm * lda;
    const hlf* pB = B + (long long)bn * ldb;

    float acc[2][2 * JG][4];
#pragma unroll
    for (int t = 0; t < 2; t++)
#pragma unroll
        for (int j = 0; j < 2 * JG; j++)
#pragma unroll
            for (int q = 0; q < 4; q++) acc[t][j][q] = 0.f;

    int nk = K / GBK;

#define ISSUE(stage_) do { \
    int st_ = (stage_) % STAGES; \
    uint32_t sb_ = sbase + st_ * STAGE_B; \
    long long k0_ = (long long)(stage_) * GBK; \
    { int r = tid >> 2, ch = tid & 3; \
      uint32_t so = swz(r, ch); \
      CP_ASYNC16(sb_ + so, pA + (long long)r * lda + k0_ + ch * 8); } \
    _Pragma("unroll") \
    for (int u = 0; u < BN / 128; u++) { \
        int idx = u * 512 + tid; int r = idx >> 2, ch = idx & 3; \
        uint32_t so = swz(r, ch); \
        CP_ASYNC16(sb_ + ASZ + so, pB + (long long)r * ldb + k0_ + ch * 8); \
    } \
} while (0)

    for (int s = 0; s < STAGES - 1; s++) {
        if (s < nk) ISSUE(s);
        CP_COMMIT();
    }

    int a_row = (lane & 15);
    int a_sel = lane >> 4;
    int b_row = (lane & 7) + ((lane >> 4) * 8);
    int b_sel = (lane >> 3) & 1;

    for (int i = 0; i < nk; i++) {
        CP_WAIT(STAGES - 2);
        __syncthreads();
        if (i + STAGES - 1 < nk) ISSUE(i + STAGES - 1);
        CP_COMMIT();

        uint32_t sb = sbase + (i % STAGES) * STAGE_B;

#pragma unroll
        for (int kh = 0; kh < 2; kh++) {
            uint32_t Af[2][4];
#pragma unroll
            for (int t = 0; t < 2; t++) {
                int row = wm + t * 16 + a_row;
                LDSM4(Af[t], sb + swz(row, 2 * kh + a_sel));
            }
#pragma unroll
            for (int jg = 0; jg < JG; jg++) {
                int row = wn + jg * 16 + b_row;
                uint32_t B4[4];
                LDSM4(B4, sb + ASZ + swz(row, 2 * kh + b_sel));
#pragma unroll
                for (int t = 0; t < 2; t++) {
                    MMA16816(acc[t][2*jg],   Af[t], B4[0], B4[1]);
                    MMA16816(acc[t][2*jg+1], Af[t], B4[2], B4[3]);
                }
            }
        }
    }
#undef ISSUE

#pragma unroll
    for (int t = 0; t < 2; t++) {
        int r0 = bm + wm + t * 16 + (lane >> 2);
#pragma unroll
        for (int j = 0; j < 2 * JG; j++) {
            int col = bn + wn + j * 8 + (lane & 3) * 2;
            float v0 = acc[t][j][0] * alpha;
            float v1 = acc[t][j][1] * alpha;
            float v2 = acc[t][j][2] * alpha;
            float v3 = acc[t][j][3] * alpha;
            if (bias) { v0 += bias[col]; v1 += bias[col + 1]; v2 += bias[col]; v3 += bias[col + 1]; }
            long long o0 = (long long)r0 * ldc + col;
            long long o1 = (long long)(r0 + 8) * ldc + col;
            if (Chi) {
                store_h2(v0, v1, Chi + o0);
                store_h2(v2, v3, Chi + o1);
            } else {
                C[o0] = v0; C[o0 + 1] = v1;
                C[o1] = v2; C[o1 + 1] = v3;
            }
        }
    }
}

// ---------------- fused flash attention v2 ----------------
// CTA: 64 q rows, one (b,h). Per j-iter: 128-key K' tile fully resident
// (10 chunks x 16KB = 160KB; chunk c = K cols [64c, 64c+64) for 128 keys).
// Q streamed via 4x8KB ring. P (64x128, two 8KB halves) overlays K chunk 8
// (k_pe cols, dead after S-phase). V = chunks 0..7 re-read in AV.
// Warp tiles: S-phase 16q x 32keys (4mg x 4cg); AV 64q x 32cols (col stripe).
static constexpr int FPOFF = 131072;     // P overlays chunk 8 slot
static constexpr int FQOFF = 163840;     // Q ring 4 x 8KB
static constexpr int FSMEM = 196608;     // 192 KB

__device__ __forceinline__ uint32_t psw(int row, int ch) {
    return (uint32_t)(row * 128 + ((ch ^ (row & 7)) << 4));
}

__global__ __launch_bounds__(512, 1) void flash_kernel(
    const hlf* __restrict__ Q,
    const hlf* __restrict__ Kf,
    const float* __restrict__ mask,
    hlf* __restrict__ O,
    float scale)
{
    extern __shared__ char smem[];
    uint32_t sbase = smem_u32(smem);
    int tid = threadIdx.x, wid = tid >> 5, lane = tid & 31;
    int mg = wid & 3, cg = wid >> 2;
    int bh = blockIdx.y, b = bh >> 4;
    int q0 = blockIdx.x * 64;

    const hlf* pQ = Q + (long long)bh * CS * CCAT + (long long)q0 * CCAT;
    const hlf* pK = Kf + (long long)b * CS * CCAT;

    // loader geometry: Q chunk 8KB (1 granule/thread), K chunk 16KB (2/thread)
    int grow = tid >> 3, gch = tid & 7;
    uint32_t qsoff  = psw(grow, gch);
    long long qgoff = (long long)grow * CCAT + gch * 8;
    uint32_t ksoff0 = psw(grow, gch);
    uint32_t ksoff1 = psw(grow + 64, gch);
    long long kgoff0 = qgoff;
    long long kgoff1 = (long long)(grow + 64) * CCAT + gch * 8;

    // S-phase ldmatrix geometry
    int arow = mg * 16 + (lane & 15);
    int asel = lane >> 4;
    int brow0 = cg * 32 + (lane & 7) + ((lane >> 4) * 8);
    int brow1 = brow0 + 16;
    int bsel = (lane >> 3) & 1;
    // AV geometry
    int trow_b = (lane & 7) + (((lane >> 3) & 1) * 8);
    int tsel = lane >> 4;

    float oacc[4][4][4];
#pragma unroll
    for (int rg = 0; rg < 4; rg++)
#pragma unroll
        for (int j = 0; j < 4; j++)
#pragma unroll
            for (int q = 0; q < 4; q++) oacc[rg][j][q] = 0.f;
    float lsum0 = 0.f, lsum1 = 0.f;

    int prow0 = mg * 16 + (lane >> 2), prow1 = prow0 + 8;

    for (int j = 0; j < 16; j++) {
        const hlf* pKj = pK + (long long)j * 128 * CCAT;

#define KISSUE(kc_) do { \
    uint32_t kb_ = sbase + (kc_) * 16384; \
    uint32_t qb_ = sbase + FQOFF + ((kc_) & 3) * 8192; \
    long long co_ = (long long)(kc_) * 64; \
    CP_ASYNC16(kb_ + ksoff0, pKj + kgoff0 + co_); \
    CP_ASYNC16(kb_ + ksoff1, pKj + kgoff1 + co_); \
    CP_ASYNC16(qb_ + qsoff,  pQ + qgoff + co_); \
    CP_COMMIT(); \
} while (0)
        KISSUE(0); KISSUE(1); KISSUE(2);

        float sacc[4][4];
#pragma unroll
        for (int n = 0; n < 4; n++)
#pragma unroll
            for (int q = 0; q < 4; q++) sacc[n][q] = 0.f;

        for (int kc = 0; kc < 10; kc++) {
            CP_WAIT(2);
            __syncthreads();
            if (kc + 3 < 10) KISSUE(kc + 3);
            else CP_COMMIT();
            uint32_t kb = sbase + kc * 16384;
            uint32_t qb = sbase + FQOFF + (kc & 3) * 8192;
#pragma unroll
            for (int kk = 0; kk < 4; kk++) {
                uint32_t A4[4];
                LDSM4(A4, qb + psw(arow, kk * 2 + asel));
                uint32_t B0[4], B1[4];
                LDSM4(B0, kb + psw(brow0, kk * 2 + bsel));
                LDSM4(B1, kb + psw(brow1, kk * 2 + bsel));
                MMA16816(sacc[0], A4, B0[0], B0[1]);
                MMA16816(sacc[1], A4, B0[2], B0[3]);
                MMA16816(sacc[2], A4, B1[0], B1[1]);
                MMA16816(sacc[3], A4, B1[2], B1[3]);
            }
        }
#undef KISSUE

        // softmax (max-free) + P fp16 write (P overlays chunk-8 slot; all
        // chunk-8 S reads completed before the kc=9 top-of-loop barrier).
        {
            const float* mrow = mask + (long long)b * CS * CS
                              + (long long)(q0 + prow0) * CS + j * 128 + cg * 32 + (lane & 3) * 2;
            uint32_t pb = sbase + FPOFF + (cg >> 1) * 8192;
            float ladd0 = 0.f, ladd1 = 0.f;
#pragma unroll
            for (int nn = 0; nn < 4; nn++) {
                float2 m0 = *reinterpret_cast<const float2*>(mrow + nn * 8);
                float2 m1 = *reinterpret_cast<const float2*>(mrow + nn * 8 + 8 * CS);
                float p0 = __expf(sacc[nn][0] * scale + m0.x);
                float p1 = __expf(sacc[nn][1] * scale + m0.y);
                float p2 = __expf(sacc[nn][2] * scale + m1.x);
                float p3 = __expf(sacc[nn][3] * scale + m1.y);
                ladd0 += p0 + p1; ladd1 += p2 + p3;
                int c64 = (cg & 1) * 32 + nn * 8 + (lane & 3) * 2;
                uint32_t o0 = (uint32_t)(prow0 * 128 + (((c64 >> 3) ^ (prow0 & 7)) << 4) + (c64 & 7) * 2);
                uint32_t o1 = (uint32_t)(prow1 * 128 + (((c64 >> 3) ^ (prow1 & 7)) << 4) + (c64 & 7) * 2);
                store_h2(p0, p1, (hlf*)((char*)smem + (pb - sbase) + o0));
                store_h2(p2, p3, (hlf*)((char*)smem + (pb - sbase) + o1));
            }
            ladd0 += __shfl_xor_sync(~0u, ladd0, 1); ladd0 += __shfl_xor_sync(~0u, ladd0, 2);
            ladd1 += __shfl_xor_sync(~0u, ladd1, 1); ladd1 += __shfl_xor_sync(~0u, ladd1, 2);
            lsum0 += ladd0; lsum1 += ladd1;
        }
        __syncthreads();   // P visible to all warps

        // AV: O += P*V; warp owns col stripe [wid*32, wid*32+32), all 64 rows
        int wc = wid * 32;
#pragma unroll
        for (int kt = 0; kt < 8; kt++) {
            uint32_t pb = sbase + FPOFF + (kt >> 2) * 8192;
            int kt4 = kt & 3;
            uint32_t P4[4][4];
#pragma unroll
            for (int rg = 0; rg < 4; rg++)
                LDSM4(P4[rg], pb + psw(rg * 16 + (lane & 15), kt4 * 2 + (lane >> 4)));
            int trow = kt * 16 + trow_b;
#pragma unroll
            for (int vf = 0; vf < 2; vf++) {
                int c0 = wc + vf * 16;
                uint32_t kcb = sbase + (c0 >> 6) * 16384;
                uint32_t V4[4];
                LDSM4T(V4, kcb + psw(trow, ((c0 & 63) >> 3) + tsel));
#pragma unroll
                for (int rg = 0; rg < 4; rg++) {
                    MMA16816(oacc[rg][vf*2],   P4[rg], V4[0], V4[1]);
                    MMA16816(oacc[rg][vf*2+1], P4[rg], V4[2], V4[3]);
                }
            }
        }
        __syncthreads();   // AV (K/P) reads done before next j overwrites them
    }

    // finalize: row sums across 4 cg groups (Larr reuses chunk-0 region)
    float* Larr = reinterpret_cast<float*>(smem);
    if ((lane & 3) == 0) {
        Larr[cg * 64 + prow0] = lsum0;
        Larr[cg * 64 + prow1] = lsum1;
    }
    __syncthreads();

    hlf* po = O + (long long)bh * CS * CKVLR + (long long)q0 * CKVLR;
    int wc = wid * 32;
#pragma unroll
    for (int rg = 0; rg < 4; rg++) {
        int row0 = rg * 16 + (lane >> 2), row1 = row0 + 8;
        float inv0 = 1.f / (Larr[row0] + Larr[64 + row0] + Larr[128 + row0] + Larr[192 + row0]);
        float inv1 = 1.f / (Larr[row1] + Larr[64 + row1] + Larr[128 + row1] + Larr[192 + row1]);
#pragma unroll
        for (int jj = 0; jj < 4; jj++) {
            int col = wc + jj * 8 + (lane & 3) * 2;
            float* a = oacc[rg][jj];
            store_h2(a[0] * inv0, a[1] * inv0, po + (long long)row0 * CKVLR + col);
            store_h2(a[2] * inv1, a[3] * inv1, po + (long long)row1 * CKVLR + col);
        }
    }
}

// ---------------- conversions ----------------
__global__ void cvt_half_kernel(const float* __restrict__ s, hlf* __restrict__ d, long long n)
{
    long long n4 = n >> 2;
    long long i = (long long)blockIdx.x * blockDim.x + threadIdx.x;
    long long st = (long long)gridDim.x * blockDim.x;
    for (; i < n4; i += st) {
        float4 v = reinterpret_cast<const float4*>(s)[i];
        hlf h[4];
        h[0] = __float2half_rn(v.x); h[1] = __float2half_rn(v.y);
        h[2] = __float2half_rn(v.z); h[3] = __float2half_rn(v.w);
        *reinterpret_cast<uint2*>(d + i * 4) = *reinterpret_cast<uint2*>(h);
    }
}

// qab [h][c][d], oabT [h][d][c] from kv_b_W [c, h, 2, d] (single fp16)
__global__ void extract_kernel(const float* __restrict__ kvb,
                               hlf* __restrict__ qab, hlf* __restrict__ oabt)
{
    long long n = (long long)CNH * CKVLR * CHD;
    long long i = (long long)blockIdx.x * blockDim.x + threadIdx.x;
    long long st = (long long)gridDim.x * blockDim.x;
    for (; i < n; i += st) {
        {
            int c = (int)(i & 511);
            int d = (int)((i >> 9) & 127);
            int h = (int)(i >> 16);
            oabt[i] = __float2half_rn(kvb[(((long long)c * CNH + h) * 2 + 1) * CHD + d]);
        }
        {
            int d = (int)(i & 127);
            int c = (int)((i >> 7) & 511);
            int h = (int)(i >> 16);
            qab[i] = __float2half_rn(kvb[(((long long)c * CNH + h) * 2) * CHD + d]);
        }
    }
}

// ---------------- RMSNorm (fp32 in, fp16 out) ----------------
__global__ __launch_bounds__(256) void rms_kernel(const float* __restrict__ x, const float* __restrict__ w,
                                                  hlf* __restrict__ o)
{
    __shared__ float red[8];
    size_t row = blockIdx.x;
    const float* p = x + row * CQLR;
    int tid = threadIdx.x;
    float s = 0.f;
    for (int i = tid; i < CQLR; i += 256) { float v = p[i]; s += v * v; }
#pragma unroll
    for (int off = 16; off; off >>= 1) s += __shfl_xor_sync(~0u, s, off);
    if ((tid & 31) == 0) red[tid >> 5] = s;
    __syncthreads();
    float tot = 0.f;
#pragma unroll
    for (int i = 0; i < 8; i++) tot += red[i];
    float r = rsqrtf(tot + 1e-6f);
    hlf* po = o + row * CQLR;
    for (int i = tid; i < CQLR; i += 256) po[i] = __float2half_rn(p[i] * r * w[i]);
}

// ---------------- RoPE ----------------
__device__ __forceinline__ void rope_cs(int s, int i, float& c, float& sn)
{
    double invf = pow(10000.0, -(double)(2 * i) / 128.0);
    double ang = (double)s * invf;
    c = (float)cos(ang);
    sn = (float)sin(ang);
}

// k_pe: in-place on fp16 ckvf cols [512,640)
__global__ void rope_k_kernel(hlf* __restrict__ ckv)
{
    int idx = blockIdx.x * blockDim.x + threadIdx.x;
    if (idx >= CB * CS * 64) return;
    int i = idx & 63;
    int row = idx >> 6;
    int s = row & (CS - 1);
    float c, sn; rope_cs(s, i, c, sn);
    hlf* p = ckv + (size_t)row * CCAT + CKVLR;
    float x1 = __half2float(p[i]), x2 = __half2float(p[i + 64]);
    p[i]      = __float2half_rn(x1 * c - x2 * sn);
    p[i + 64] = __float2half_rn(x2 * c + x1 * sn);
}

// q_pe: read single-fp16 q, rope, write single fp16 into qc cols 512..639
__global__ void rope_q_kernel(const hlf* __restrict__ q, hlf* __restrict__ qc)
{
    int idx = blockIdx.x * blockDim.x + threadIdx.x;
    if (idx >= CB * CS * CNH * 64) return;
    int i = idx & 63;
    int h = (idx >> 6) & 15;
    int row = idx >> 10;
    int s = row & (CS - 1);
    int b = row >> 11;
    float c, sn; rope_cs(s, i, c, sn);
    long long so = (long long)row * (CNH * CQHD) + h * CQHD + CHD;
    float x1 = __half2float(q[so + i]);
    float x2 = __half2float(q[so + i + 64]);
    long long dofs = ((long long)(b * CNH + h) * CS + s) * CCAT + CKVLR;
    qc[dofs + i]      = __float2half_rn(x1 * c - x2 * sn);
    qc[dofs + i + 64] = __float2half_rn(x2 * c + x1 * sn);
}

// ---------------- launch ----------------
extern "C" void kernel_launch(void* const* d_in, const int* in_sizes, int n_in,
                              void* d_out, int out_size)
{
    const float* hidden = (const float*)d_in[0];
    const float* mask   = (const float*)d_in[1];
    const float* q_a_W  = (const float*)d_in[2];
    const float* q_a_b  = (const float*)d_in[3];
    const float* q_a_nw = (const float*)d_in[4];
    const float* q_b_W  = (const float*)d_in[5];
    const float* kv_a_W = (const float*)d_in[6];
    const float* kv_b_W = (const float*)d_in[7];
    const float* o_W    = (const float*)d_in[8];
    float* out = (float*)d_out;

    void* p;
#define SYM(v, g) cudaGetSymbolAddress(&p, g); auto* v = (decltype(&g[0]))p
    SYM(qa, g_qa);
    SYM(hid, g_hid);
    SYM(qaw, g_qaw);   SYM(qbw, g_qbw);
    SYM(kvaw, g_kvaw); SYM(ow, g_ow);
    SYM(qan, g_qan);   SYM(qs, g_qs);
    SYM(qab, g_qab);   SYM(oabt, g_oabt);
    SYM(qc, g_qc);     SYM(ckvf, g_ckvf);
    SYM(ol, g_ol);     SYM(oh, g_oh);
#undef SYM

    constexpr int SMEM128 = STAGES * (ASZ + 128 * GBK * 2);  // 64 KB
    constexpr int SMEM256 = STAGES * (ASZ + 256 * GBK * 2);  // 96 KB
    cudaFuncSetAttribute(mma_gemm<128>, cudaFuncAttributeMaxDynamicSharedMemorySize, SMEM128);
    cudaFuncSetAttribute(mma_gemm<256>, cudaFuncAttributeMaxDynamicSharedMemorySize, SMEM256);
    cudaFuncSetAttribute(flash_kernel, cudaFuncAttributeMaxDynamicSharedMemorySize, FSMEM);

    const long long LS = CS;
    const int CVG = 2048;

    cvt_half_kernel<<<CVG, 256>>>(hidden, hid, (long long)CBS * CHID);
    cvt_half_kernel<<<CVG, 256>>>(q_a_W, qaw, (long long)CQLR * CHID);
    cvt_half_kernel<<<CVG, 256>>>(kv_a_W, kvaw, (long long)CCAT * CHID);

    // q_a = hidden @ q_a_W^T + bias   [4096,1536] K=2048, fp32 out
    mma_gemm<256><<<dim3(CQLR / 256, CBS / 128, 1), 512, SMEM256>>>(
        hid, CHID, 0, 0, qaw, CHID, 0, 0,
        qa, nullptr, CQLR, 0, 0, q_a_b, 1.f, CHID, 1);

    // ckv = hidden @ kv_a_W^T  [4096,640] K=2048, fp16 out directly
    mma_gemm<128><<<dim3(CCAT / 128, CBS / 128, 1), 512, SMEM128>>>(
        hid, CHID, 0, 0, kvaw, CHID, 0, 0,
        nullptr, ckvf, CCAT, 0, 0, nullptr, 1.f, CHID, 1);

    rms_kernel<<<CBS, 256>>>(qa, q_a_nw, qan);
    cvt_half_kernel<<<CVG, 256>>>(q_b_W, qbw, (long long)CNH * CQHD * CQLR);

    // q = qa_norm @ q_b_W^T  [4096,4096] K=1536, fp16 out
    mma_gemm<256><<<dim3((CNH * CQHD) / 256, CBS / 128, 1), 512, SMEM256>>>(
        qan, CQLR, 0, 0, qbw, CQLR, 0, 0,
        nullptr, qs, CNH * CQHD, 0, 0, nullptr, 1.f, CQLR, 1);

    extract_kernel<<<CVG, 256>>>(kv_b_W, qab, oabt);
    rope_k_kernel<<<(CB * CS * 64) / 256, 256>>>(ckvf);
    rope_q_kernel<<<(CB * CS * CNH * 64) / 256, 256>>>(qs, qc);

    // q_lat -> qc cols [0,512)  K=128, Z=32, fp16 out
    mma_gemm<256><<<dim3(CKVLR / 256, CS / 128, CB * CNH), 512, SMEM256>>>(
        qs, CNH * CQHD, LS * CNH * CQHD, CQHD,
        qab, CHD, 0, (long long)CKVLR * CHD,
        nullptr, qc, CCAT, LS * CNH * CCAT, LS * CCAT,
        nullptr, 1.f, CHD, CNH);

    // fused attention: scores + softmax + AV -> ol (fp16)
    float scale = 1.f / sqrtf((float)CCAT);
    flash_kernel<<<dim3(CS / 64, CB * CNH), 512, FSMEM>>>(
        qc, ckvf, mask, ol, scale);

    cvt_half_kernel<<<CVG, 256>>>(o_W, ow, (long long)CHID * CNH * CHD);

    // out_head = ol . o_absorb^T -> [b,s,h*128+d]  K=512, N=128, Z=32, fp16 out
    mma_gemm<128><<<dim3(1, CS / 128, CB * CNH), 512, SMEM128>>>(
        ol, CKVLR, LS * CNH * CKVLR, LS * CKVLR,
        oabt, CKVLR, 0, (long long)CHD * CKVLR,
        nullptr, oh, CNH * CHD, LS * (long long)CNH * CHD, CHD,
        nullptr, 1.f, CKVLR, CNH);

    // final = oh @ o_W^T  [4096,2048] K=2048, fp32 out
    mma_gemm<256><<<dim3(CHID / 256, CBS / 128, 1), 512, SMEM256>>>(
        oh, CNH * CHD, 0, 0, ow, CNH * CHD, 0, 0,
        out, nullptr, CHID, 0, 0, nullptr, 1.f, CNH * CHD, 1);
}